// round 1
// baseline (speedup 1.0000x reference)
#include <cuda_runtime.h>

#define MAXN 50000
#define MAXE 800000

struct __align__(16) EdgeRec { int row; float c1; float c2; float pad; };

// ---------------- scratch (static device globals; no allocation) -------------
__device__ float g_xcat[MAXN * 256];   // [N,256]  padded concat(x, d2an)
__device__ float g_xpe [MAXN * 256];   // [N,256]  (xpe1 | xpe2)
__device__ float g_agg0[MAXN * 256];   // [N,256]  (c1-agg | c2-agg) graph 0
__device__ float g_agg1[MAXN * 256];   // graph 1
__device__ float g_xm  [MAXN * 128];   // mid features
__device__ float g_wcat[256 * 256];    // padded (nodeLin1 | nodeLin2)
__device__ float g_ws1 [256 * 128];    // [lin1_1 ; lin2_1]
__device__ float g_ws2 [256 * 128];
__device__ float g_ws3 [256 * 128];
__device__ float g_ws4 [256 * 128];
__device__ int   g_cnt0[MAXN];
__device__ int   g_cnt1[MAXN];
__device__ int   g_off0[MAXN + 1];
__device__ int   g_off1[MAXN + 1];
__device__ int   g_cur0[MAXN];
__device__ int   g_cur1[MAXN];
__device__ float g_dis0[MAXN];
__device__ float g_dis1[MAXN];
__device__ EdgeRec g_ent0[MAXE];
__device__ EdgeRec g_ent1[MAXE];

// ---------------- graph preprocessing ---------------------------------------
__global__ void k_count(const int* __restrict__ col, int* __restrict__ cnt, int e) {
    int i = blockIdx.x * blockDim.x + threadIdx.x;
    if (i < e) atomicAdd(&cnt[col[i]], 1);
}

__global__ void k_dis(const int* __restrict__ cnt, float* __restrict__ dis, int n) {
    int i = blockIdx.x * blockDim.x + threadIdx.x;
    if (i < n) dis[i] = rsqrtf((float)(cnt[i] + 1));  // +1 self loop; deg >= 1
}

__global__ void k_scan(const int* __restrict__ cnt, int* __restrict__ off,
                       int* __restrict__ cur, int n) {
    __shared__ int s[1024];
    int t = threadIdx.x;
    int chunk = (n + 1023) >> 10;
    int b = t * chunk;
    int e = min(b + chunk, n);
    int sum = 0;
    for (int i = b; i < e; i++) sum += cnt[i];
    s[t] = sum;
    __syncthreads();
    for (int o = 1; o < 1024; o <<= 1) {
        int v = (t >= o) ? s[t - o] : 0;
        __syncthreads();
        s[t] += v;
        __syncthreads();
    }
    int base = s[t] - sum;  // exclusive prefix
    for (int i = b; i < e; i++) { off[i] = base; cur[i] = base; base += cnt[i]; }
    if (t == 1023) off[n] = s[1023];
}

__global__ void k_fill(const int* __restrict__ row, const int* __restrict__ col,
                       const float* __restrict__ attr, const float* __restrict__ dis,
                       int* __restrict__ cur, EdgeRec* __restrict__ ent, int e) {
    int i = blockIdx.x * blockDim.x + threadIdx.x;
    if (i >= e) return;
    int r = row[i], c = col[i];
    float a = attr[i];
    EdgeRec rec;
    rec.row = r;
    rec.c1  = dis[r] * dis[c];
    rec.c2  = (a > 0.f) ? fminf(rsqrtf(a), 1.f) : 0.f;
    rec.pad = 0.f;
    int p = atomicAdd(&cur[c], 1);
    ent[p] = rec;
}

// ---------------- feature / weight prep --------------------------------------
__global__ void k_xcat(const float* __restrict__ x, const float* __restrict__ pe,
                       float* __restrict__ xcat, int n) {
    int stride = gridDim.x * blockDim.x;
    for (int idx = blockIdx.x * blockDim.x + threadIdx.x; idx < n * 256; idx += stride) {
        int i = idx >> 8, k = idx & 255;
        float v;
        if (k < 128)       v = x[(size_t)i * 128 + k];
        else if (k < 226)  v = pe[(size_t)i * 98 + (k - 128)];
        else               v = 0.f;
        xcat[idx] = v;
    }
}

__global__ void k_wcat(const float* __restrict__ w1, const float* __restrict__ w2,
                       float* __restrict__ wc) {
    int idx = blockIdx.x * blockDim.x + threadIdx.x;
    if (idx >= 256 * 256) return;
    int k = idx >> 8, j = idx & 255;
    float v = 0.f;
    if (k < 226) v = (j < 128) ? w1[k * 128 + j] : w2[k * 128 + (j - 128)];
    wc[idx] = v;
}

__global__ void k_wstk(const float* __restrict__ w1, const float* __restrict__ w2,
                       float* __restrict__ ws) {
    int idx = blockIdx.x * blockDim.x + threadIdx.x;
    if (idx >= 256 * 128) return;
    int k = idx >> 7, j = idx & 127;
    ws[idx] = (k < 128) ? w1[k * 128 + j] : w2[(k - 128) * 128 + j];
}

// ---------------- CSR gather: agg[c] = (sum c1*x[r] | sum c2*x[r]) -----------
__global__ void k_gather(const float* __restrict__ src, int ld, int off,
                         const int* __restrict__ offs, const EdgeRec* __restrict__ ent,
                         const float* __restrict__ dis, float* __restrict__ agg, int n) {
    int warp = (blockIdx.x * blockDim.x + threadIdx.x) >> 5;
    int lane = threadIdx.x & 31;
    if (warp >= n) return;
    int b = offs[warp], e = offs[warp + 1];
    float4 a1 = make_float4(0.f, 0.f, 0.f, 0.f);
    float4 a2 = make_float4(0.f, 0.f, 0.f, 0.f);
    for (int i = b; i < e; i++) {
        EdgeRec rec = ent[i];  // uniform across warp -> broadcast
        const float4 v = *reinterpret_cast<const float4*>(
            src + (size_t)rec.row * ld + off + lane * 4);
        a1.x += rec.c1 * v.x; a1.y += rec.c1 * v.y; a1.z += rec.c1 * v.z; a1.w += rec.c1 * v.w;
        a2.x += rec.c2 * v.x; a2.y += rec.c2 * v.y; a2.z += rec.c2 * v.z; a2.w += rec.c2 * v.w;
    }
    // self loop: deg_norm = dis^2, edge_norm = 1
    float d = dis[warp];
    float sc = d * d;
    const float4 v = *reinterpret_cast<const float4*>(
        src + (size_t)warp * ld + off + lane * 4);
    a1.x += sc * v.x; a1.y += sc * v.y; a1.z += sc * v.z; a1.w += sc * v.w;
    a2.x += v.x;      a2.y += v.y;      a2.z += v.z;      a2.w += v.w;
    float* o = agg + (size_t)warp * 256 + lane * 4;
    *reinterpret_cast<float4*>(o)       = a1;
    *reinterpret_cast<float4*>(o + 128) = a2;
}

// ---------------- fp32 tiled GEMM: C[M,NC] = A[M,256] @ B[256,NC] ------------
// epi: 0 -> store;  1 -> C = 0.5*relu(acc);  2 -> C += 0.5*relu(acc)
__global__ void __launch_bounds__(256) k_gemm(const float* __restrict__ A,
                                              const float* __restrict__ B,
                                              float* __restrict__ C,
                                              int M, int NC, int epi) {
    __shared__ float As[32][68];
    __shared__ float Bs[32][68];
    int tid = threadIdx.x;
    int tx = tid & 15, ty = tid >> 4;
    int r0 = blockIdx.y * 64, n0 = blockIdx.x * 64;

    float acc[4][4] = {};

    int arow = tid >> 3;         // 0..31
    int acg  = (tid & 7) * 4;    // 0,4,..,28
    int bk   = tid >> 4;         // 0..15
    int bng  = (tid & 15) * 4;   // 0,4,..,60

    const float4 z4 = make_float4(0.f, 0.f, 0.f, 0.f);

    for (int k0 = 0; k0 < 256; k0 += 32) {
        int ra = r0 + arow;
        float4 av0 = (ra < M)
            ? *reinterpret_cast<const float4*>(A + (size_t)ra * 256 + k0 + acg) : z4;
        int ra2 = ra + 32;
        float4 av1 = (ra2 < M)
            ? *reinterpret_cast<const float4*>(A + (size_t)ra2 * 256 + k0 + acg) : z4;
        As[acg + 0][arow] = av0.x; As[acg + 1][arow] = av0.y;
        As[acg + 2][arow] = av0.z; As[acg + 3][arow] = av0.w;
        As[acg + 0][arow + 32] = av1.x; As[acg + 1][arow + 32] = av1.y;
        As[acg + 2][arow + 32] = av1.z; As[acg + 3][arow + 32] = av1.w;

        float4 bv0 = *reinterpret_cast<const float4*>(B + (size_t)(k0 + bk) * NC + n0 + bng);
        float4 bv1 = *reinterpret_cast<const float4*>(B + (size_t)(k0 + bk + 16) * NC + n0 + bng);
        *reinterpret_cast<float4*>(&Bs[bk][bng])      = bv0;
        *reinterpret_cast<float4*>(&Bs[bk + 16][bng]) = bv1;
        __syncthreads();

#pragma unroll
        for (int k = 0; k < 32; k++) {
            float4 a = *reinterpret_cast<float4*>(&As[k][ty * 4]);
            float4 b = *reinterpret_cast<float4*>(&Bs[k][tx * 4]);
            acc[0][0] += a.x * b.x; acc[0][1] += a.x * b.y; acc[0][2] += a.x * b.z; acc[0][3] += a.x * b.w;
            acc[1][0] += a.y * b.x; acc[1][1] += a.y * b.y; acc[1][2] += a.y * b.z; acc[1][3] += a.y * b.w;
            acc[2][0] += a.z * b.x; acc[2][1] += a.z * b.y; acc[2][2] += a.z * b.z; acc[2][3] += a.z * b.w;
            acc[3][0] += a.w * b.x; acc[3][1] += a.w * b.y; acc[3][2] += a.w * b.z; acc[3][3] += a.w * b.w;
        }
        __syncthreads();
    }

#pragma unroll
    for (int i = 0; i < 4; i++) {
        int r = r0 + ty * 4 + i;
        if (r >= M) continue;
        float* c = C + (size_t)r * NC + n0 + tx * 4;
#pragma unroll
        for (int j = 0; j < 4; j++) {
            float v = acc[i][j];
            if (epi == 0)      c[j] = v;
            else if (epi == 1) c[j] = 0.5f * fmaxf(v, 0.f);
            else               c[j] += 0.5f * fmaxf(v, 0.f);
        }
    }
}

// ---------------- host orchestration -----------------------------------------
extern "C" void kernel_launch(void* const* d_in, const int* in_sizes, int n_in,
                              void* d_out, int out_size) {
    const float* x   = (const float*)d_in[0];
    const float* pe  = (const float*)d_in[1];
    const int*   ei0 = (const int*)d_in[2];
    const float* ea0 = (const float*)d_in[3];
    const int*   ei1 = (const int*)d_in[4];
    const float* ea1 = (const float*)d_in[5];
    const float* nl1 = (const float*)d_in[6];
    const float* nl2 = (const float*)d_in[7];
    const float* l11 = (const float*)d_in[8];
    const float* l21 = (const float*)d_in[9];
    const float* l12 = (const float*)d_in[10];
    const float* l22 = (const float*)d_in[11];
    const float* l13 = (const float*)d_in[12];
    const float* l23 = (const float*)d_in[13];
    const float* l14 = (const float*)d_in[14];
    const float* l24 = (const float*)d_in[15];
    float* out = (float*)d_out;

    int N = in_sizes[0] / 128;
    int E = in_sizes[3];

    float *xcat, *xpe, *agg0, *agg1, *xm, *wcat, *ws1, *ws2, *ws3, *ws4, *dis0, *dis1;
    int *cnt0, *cnt1, *off0, *off1, *cur0, *cur1;
    EdgeRec *ent0, *ent1;
    cudaGetSymbolAddress((void**)&xcat, g_xcat);
    cudaGetSymbolAddress((void**)&xpe,  g_xpe);
    cudaGetSymbolAddress((void**)&agg0, g_agg0);
    cudaGetSymbolAddress((void**)&agg1, g_agg1);
    cudaGetSymbolAddress((void**)&xm,   g_xm);
    cudaGetSymbolAddress((void**)&wcat, g_wcat);
    cudaGetSymbolAddress((void**)&ws1,  g_ws1);
    cudaGetSymbolAddress((void**)&ws2,  g_ws2);
    cudaGetSymbolAddress((void**)&ws3,  g_ws3);
    cudaGetSymbolAddress((void**)&ws4,  g_ws4);
    cudaGetSymbolAddress((void**)&cnt0, g_cnt0);
    cudaGetSymbolAddress((void**)&cnt1, g_cnt1);
    cudaGetSymbolAddress((void**)&off0, g_off0);
    cudaGetSymbolAddress((void**)&off1, g_off1);
    cudaGetSymbolAddress((void**)&cur0, g_cur0);
    cudaGetSymbolAddress((void**)&cur1, g_cur1);
    cudaGetSymbolAddress((void**)&dis0, g_dis0);
    cudaGetSymbolAddress((void**)&dis1, g_dis1);
    cudaGetSymbolAddress((void**)&ent0, g_ent0);
    cudaGetSymbolAddress((void**)&ent1, g_ent1);

    // ---- graph preprocessing (both graphs) ----
    cudaMemsetAsync(cnt0, 0, N * sizeof(int));
    cudaMemsetAsync(cnt1, 0, N * sizeof(int));
    int eb = (E + 255) / 256;
    k_count<<<eb, 256>>>(ei0 + E, cnt0, E);
    k_count<<<eb, 256>>>(ei1 + E, cnt1, E);
    int nb = (N + 255) / 256;
    k_dis<<<nb, 256>>>(cnt0, dis0, N);
    k_dis<<<nb, 256>>>(cnt1, dis1, N);
    k_scan<<<1, 1024>>>(cnt0, off0, cur0, N);
    k_scan<<<1, 1024>>>(cnt1, off1, cur1, N);
    k_fill<<<eb, 256>>>(ei0, ei0 + E, ea0, dis0, cur0, ent0, E);
    k_fill<<<eb, 256>>>(ei1, ei1 + E, ea1, dis1, cur1, ent1, E);

    // ---- feature / weight prep ----
    k_xcat<<<2048, 256>>>(x, pe, xcat, N);
    k_wcat<<<256, 256>>>(nl1, nl2, wcat);
    k_wstk<<<128, 256>>>(l11, l21, ws1);
    k_wstk<<<128, 256>>>(l12, l22, ws2);
    k_wstk<<<128, 256>>>(l13, l23, ws3);
    k_wstk<<<128, 256>>>(l14, l24, ws4);

    // ---- stage B: xpe = xcat @ Wcat  ([N,256]) ----
    dim3 gB(4, (N + 63) / 64);
    k_gemm<<<gB, 256>>>(xcat, wcat, xpe, N, 256, 0);

    // ---- stage C: gather per graph ----
    int gw = (N + 7) / 8;  // 8 warps/block, warp per node
    k_gather<<<gw, 256>>>(xpe, 256, 0,   off0, ent0, dis0, agg0, N);
    k_gather<<<gw, 256>>>(xpe, 256, 128, off1, ent1, dis1, agg1, N);

    // ---- stage D: xm = 0.5*relu(agg0@Ws1) + 0.5*relu(agg1@Ws2) ----
    dim3 gD(2, (N + 63) / 64);
    k_gemm<<<gD, 256>>>(agg0, ws1, xm, N, 128, 1);
    k_gemm<<<gD, 256>>>(agg1, ws2, xm, N, 128, 2);

    // ---- stage E: gather xm per graph ----
    k_gather<<<gw, 256>>>(xm, 128, 0, off0, ent0, dis0, agg0, N);
    k_gather<<<gw, 256>>>(xm, 128, 0, off1, ent1, dis1, agg1, N);

    // ---- stage F: out = 0.5*relu(agg0@Ws3) + 0.5*relu(agg1@Ws4) ----
    k_gemm<<<gD, 256>>>(agg0, ws3, out, N, 128, 1);
    k_gemm<<<gD, 256>>>(agg1, ws4, out, N, 128, 2);
}

// round 3
// speedup vs baseline: 1.4679x; 1.4679x over previous
#include <cuda_runtime.h>
#include <cuda_bf16.h>
#include <cstdint>

#define MAXN 50000
#define MAXE 800000

// ================= device scratch =================
struct __align__(16) EdgeRec { int row; float c1; float c2; float pad; };

__device__ __nv_bfloat16 g_xcat_h[MAXN * 256];
__device__ __nv_bfloat16 g_xcat_l[MAXN * 256];
__device__ float         g_xpe  [MAXN * 256];
__device__ __nv_bfloat16 g_a0h[MAXN * 256];
__device__ __nv_bfloat16 g_a0l[MAXN * 256];
__device__ __nv_bfloat16 g_a1h[MAXN * 256];
__device__ __nv_bfloat16 g_a1l[MAXN * 256];
__device__ float         g_xm [MAXN * 128];
__device__ __nv_bfloat16 g_wbh[256 * 256];
__device__ __nv_bfloat16 g_wbl[256 * 256];
__device__ __nv_bfloat16 g_wsh[4][128 * 256];
__device__ __nv_bfloat16 g_wsl[4][128 * 256];
__device__ int   g_cnt0[MAXN];
__device__ int   g_cnt1[MAXN];
__device__ int   g_off0[MAXN + 1];
__device__ int   g_off1[MAXN + 1];
__device__ int   g_cur0[MAXN];
__device__ int   g_cur1[MAXN];
__device__ float g_dis0[MAXN];
__device__ float g_dis1[MAXN];
__device__ EdgeRec g_ent0[MAXE];
__device__ EdgeRec g_ent1[MAXE];

// ================= graph preprocessing =================
__global__ void k_count(const int* __restrict__ col, int* __restrict__ cnt, int e) {
    int i = blockIdx.x * blockDim.x + threadIdx.x;
    if (i < e) atomicAdd(&cnt[col[i]], 1);
}
__global__ void k_dis(const int* __restrict__ cnt, float* __restrict__ dis, int n) {
    int i = blockIdx.x * blockDim.x + threadIdx.x;
    if (i < n) dis[i] = rsqrtf((float)(cnt[i] + 1));
}
__global__ void k_scan(const int* __restrict__ cnt, int* __restrict__ off,
                       int* __restrict__ cur, int n) {
    __shared__ int s[1024];
    int t = threadIdx.x;
    int chunk = (n + 1023) >> 10;
    int b = t * chunk;
    int e = min(b + chunk, n);
    int sum = 0;
    for (int i = b; i < e; i++) sum += cnt[i];
    s[t] = sum;
    __syncthreads();
    for (int o = 1; o < 1024; o <<= 1) {
        int v = (t >= o) ? s[t - o] : 0;
        __syncthreads();
        s[t] += v;
        __syncthreads();
    }
    int base = s[t] - sum;
    for (int i = b; i < e; i++) { off[i] = base; cur[i] = base; base += cnt[i]; }
    if (t == 1023) off[n] = s[1023];
}
__global__ void k_fill(const int* __restrict__ row, const int* __restrict__ col,
                       const float* __restrict__ attr, const float* __restrict__ dis,
                       int* __restrict__ cur, EdgeRec* __restrict__ ent, int e) {
    int i = blockIdx.x * blockDim.x + threadIdx.x;
    if (i >= e) return;
    int r = row[i], c = col[i];
    float a = attr[i];
    EdgeRec rec;
    rec.row = r;
    rec.c1  = dis[r] * dis[c];
    rec.c2  = (a > 0.f) ? fminf(rsqrtf(a), 1.f) : 0.f;
    rec.pad = 0.f;
    int p = atomicAdd(&cur[c], 1);
    ent[p] = rec;
}

// ================= feature / weight prep =================
__device__ __forceinline__ void bsplit(float v, __nv_bfloat16& h, __nv_bfloat16& l) {
    h = __float2bfloat16(v);
    l = __float2bfloat16(v - __bfloat162float(h));
}

__global__ void k_xcat_split(const float* __restrict__ x, const float* __restrict__ pe,
                             __nv_bfloat16* __restrict__ hi, __nv_bfloat16* __restrict__ lo,
                             int n) {
    int stride = gridDim.x * blockDim.x;
    for (int idx = blockIdx.x * blockDim.x + threadIdx.x; idx < n * 256; idx += stride) {
        int i = idx >> 8, k = idx & 255;
        float v;
        if (k < 128)       v = x[(size_t)i * 128 + k];
        else if (k < 226)  v = pe[(size_t)i * 98 + (k - 128)];
        else               v = 0.f;
        __nv_bfloat16 h, l; bsplit(v, h, l);
        hi[idx] = h; lo[idx] = l;
    }
}

// WcatT[n][k]
__global__ void k_wtcat(const float* __restrict__ w1, const float* __restrict__ w2,
                        __nv_bfloat16* __restrict__ hi, __nv_bfloat16* __restrict__ lo) {
    int idx = blockIdx.x * blockDim.x + threadIdx.x;
    if (idx >= 256 * 256) return;
    int n = idx >> 8, k = idx & 255;
    float v = 0.f;
    if (k < 226) v = (n < 128) ? w1[k * 128 + n] : w2[k * 128 + (n - 128)];
    __nv_bfloat16 h, l; bsplit(v, h, l);
    hi[idx] = h; lo[idx] = l;
}
// WsT[n][k], stacked [lin1 ; lin2]^T
__global__ void k_wtstk(const float* __restrict__ w1, const float* __restrict__ w2,
                        __nv_bfloat16* __restrict__ hi, __nv_bfloat16* __restrict__ lo) {
    int idx = blockIdx.x * blockDim.x + threadIdx.x;
    if (idx >= 128 * 256) return;
    int n = idx >> 8, k = idx & 255;
    float v = (k < 128) ? w1[k * 128 + n] : w2[(k - 128) * 128 + n];
    __nv_bfloat16 h, l; bsplit(v, h, l);
    hi[idx] = h; lo[idx] = l;
}

// ================= CSR gather -> bf16 hi/lo planes =================
__device__ __forceinline__ void split_store4(__nv_bfloat16* hi, __nv_bfloat16* lo, float4 v) {
    __nv_bfloat16 h, l;
    bsplit(v.x, h, l); hi[0] = h; lo[0] = l;
    bsplit(v.y, h, l); hi[1] = h; lo[1] = l;
    bsplit(v.z, h, l); hi[2] = h; lo[2] = l;
    bsplit(v.w, h, l); hi[3] = h; lo[3] = l;
}

__global__ void k_gather(const float* __restrict__ src, int ld, int off,
                         const int* __restrict__ offs, const EdgeRec* __restrict__ ent,
                         const float* __restrict__ dis,
                         __nv_bfloat16* __restrict__ agg_h, __nv_bfloat16* __restrict__ agg_l,
                         int n) {
    int warp = (blockIdx.x * blockDim.x + threadIdx.x) >> 5;
    int lane = threadIdx.x & 31;
    if (warp >= n) return;
    int b = offs[warp], e = offs[warp + 1];
    float4 a1 = make_float4(0.f, 0.f, 0.f, 0.f);
    float4 a2 = make_float4(0.f, 0.f, 0.f, 0.f);
    for (int i = b; i < e; i++) {
        EdgeRec rec = ent[i];
        const float4 v = *reinterpret_cast<const float4*>(
            src + (size_t)rec.row * ld + off + lane * 4);
        a1.x += rec.c1 * v.x; a1.y += rec.c1 * v.y; a1.z += rec.c1 * v.z; a1.w += rec.c1 * v.w;
        a2.x += rec.c2 * v.x; a2.y += rec.c2 * v.y; a2.z += rec.c2 * v.z; a2.w += rec.c2 * v.w;
    }
    float d = dis[warp];
    float sc = d * d;
    const float4 v = *reinterpret_cast<const float4*>(
        src + (size_t)warp * ld + off + lane * 4);
    a1.x += sc * v.x; a1.y += sc * v.y; a1.z += sc * v.z; a1.w += sc * v.w;
    a2.x += v.x;      a2.y += v.y;      a2.z += v.z;      a2.w += v.w;
    size_t base = (size_t)warp * 256 + lane * 4;
    split_store4(agg_h + base,       agg_l + base,       a1);
    split_store4(agg_h + base + 128, agg_l + base + 128, a2);
}

// ================= HMMA (mma.sync) GEMM =========================
// C[M,NC] = (Ah+Al)[M,256] @ (Bh+Bl)[NC,256]^T  via 3-term bf16 split,
// expressed as 12 mainloop iterations (3 terms x 4 K-chunks of 64).
// CTA tile 128x64, warp grid 4(M) x 2(N), warp tile 32x32.
// epi: 0 store, 1 C=0.5*relu, 2 C+=0.5*relu

__device__ __forceinline__ uint32_t smem_u32(const void* p) {
    uint32_t a;
    asm("{ .reg .u64 t; cvta.to.shared.u64 t, %1; cvt.u32.u64 %0, t; }" : "=r"(a) : "l"(p));
    return a;
}
__device__ __forceinline__ void cp16(uint32_t dst, const void* src) {
    asm volatile("cp.async.cg.shared.global [%0], [%1], 16;" :: "r"(dst), "l"(src));
}
__device__ __forceinline__ void cp_commit() { asm volatile("cp.async.commit_group;"); }
template <int W> __device__ __forceinline__ void cp_wait() {
    asm volatile("cp.async.wait_group %0;" :: "n"(W));
}
__device__ __forceinline__ void ldm_x4(uint32_t* r, uint32_t addr) {
    asm volatile("ldmatrix.sync.aligned.m8n8.x4.shared.b16 {%0,%1,%2,%3}, [%4];"
                 : "=r"(r[0]), "=r"(r[1]), "=r"(r[2]), "=r"(r[3]) : "r"(addr));
}
__device__ __forceinline__ void mma16816(float* c, const uint32_t* a, uint32_t b0, uint32_t b1) {
    asm volatile(
        "mma.sync.aligned.m16n8k16.row.col.f32.bf16.bf16.f32 "
        "{%0,%1,%2,%3}, {%4,%5,%6,%7}, {%8,%9}, {%0,%1,%2,%3};"
        : "+f"(c[0]), "+f"(c[1]), "+f"(c[2]), "+f"(c[3])
        : "r"(a[0]), "r"(a[1]), "r"(a[2]), "r"(a[3]), "r"(b0), "r"(b1));
}

#define SA_BYTES 16384            // 128 rows x 128B
#define SB_BYTES 8192             // 64 rows x 128B
#define BUF_BYTES (SA_BYTES + SB_BYTES)
#define GEMM_SMEM (2 * BUF_BYTES) // 49152

__global__ void __launch_bounds__(256) k_hgemm(
    const __nv_bfloat16* __restrict__ Ah, const __nv_bfloat16* __restrict__ Al,
    const __nv_bfloat16* __restrict__ Bh, const __nv_bfloat16* __restrict__ Bl,
    float* __restrict__ C, int M, int NC, int epi) {
    extern __shared__ char sm[];
    const int tid  = threadIdx.x;
    const int lane = tid & 31;
    const int wid  = tid >> 5;
    const int wm   = wid & 3;          // warp M index (0..3)
    const int wn   = wid >> 2;         // warp N index (0..1)
    const int m0   = blockIdx.y * 128;
    const int n0   = blockIdx.x * 64;

    const uint32_t sbase = smem_u32(sm);

    const __nv_bfloat16* Ap[3] = { Ah, Al, Ah };
    const __nv_bfloat16* Bp[3] = { Bh, Bh, Bl };

    // per-thread load coords (16B chunks; row r, chunk q, swizzle q^(r&7))
    const int ar = tid >> 3;           // A: rows handled: ar, ar+32, ar+64, ar+96
    const int aq = tid & 7;
    const int br = tid >> 3;           // B: rows br, br+32
    const int bq = tid & 7;

    auto issue_load = [&](int it, int buf) {
        const __nv_bfloat16* A = Ap[it >> 2];
        const __nv_bfloat16* B = Bp[it >> 2];
        const int k0 = (it & 3) * 64;
        uint32_t sa = sbase + buf * BUF_BYTES;
        uint32_t sb = sa + SA_BYTES;
#pragma unroll
        for (int j = 0; j < 4; j++) {
            int r = ar + j * 32;
            int gr = m0 + r; if (gr > M - 1) gr = M - 1;
            cp16(sa + r * 128 + ((aq ^ (r & 7)) << 4),
                 A + (size_t)gr * 256 + k0 + aq * 8);
        }
#pragma unroll
        for (int j = 0; j < 2; j++) {
            int r = br + j * 32;
            cp16(sb + r * 128 + ((bq ^ (r & 7)) << 4),
                 B + (size_t)(n0 + r) * 256 + k0 + bq * 8);
        }
        cp_commit();
    };

    float acc[2][4][4];
#pragma unroll
    for (int i = 0; i < 2; i++)
#pragma unroll
        for (int j = 0; j < 4; j++)
#pragma unroll
            for (int k = 0; k < 4; k++) acc[i][j][k] = 0.f;

    issue_load(0, 0);

    for (int it = 0; it < 12; it++) {
        if (it < 11) issue_load(it + 1, (it + 1) & 1);
        if (it < 11) cp_wait<1>(); else cp_wait<0>();
        __syncthreads();

        uint32_t sa = sbase + (it & 1) * BUF_BYTES;
        uint32_t sb = sa + SA_BYTES;

#pragma unroll
        for (int ks = 0; ks < 4; ks++) {
            uint32_t afr[2][4];
#pragma unroll
            for (int mi = 0; mi < 2; mi++) {
                int row = wm * 32 + mi * 16 + (lane & 15);
                int c16 = (2 * ks + (lane >> 4)) ^ (row & 7);
                ldm_x4(afr[mi], sa + row * 128 + (c16 << 4));
            }
            uint32_t bfr[4][2];
#pragma unroll
            for (int np = 0; np < 2; np++) {
                int nrow = wn * 32 + np * 16 + ((lane >> 4) << 3) + (lane & 7);
                int c16 = (2 * ks + ((lane >> 3) & 1)) ^ (nrow & 7);
                uint32_t t[4];
                ldm_x4(t, sb + nrow * 128 + (c16 << 4));
                bfr[np * 2][0] = t[0]; bfr[np * 2][1] = t[1];
                bfr[np * 2 + 1][0] = t[2]; bfr[np * 2 + 1][1] = t[3];
            }
#pragma unroll
            for (int mi = 0; mi < 2; mi++)
#pragma unroll
                for (int ni = 0; ni < 4; ni++)
                    mma16816(acc[mi][ni], afr[mi], bfr[ni][0], bfr[ni][1]);
        }
        __syncthreads();
    }

    // epilogue: direct global stores
#pragma unroll
    for (int mi = 0; mi < 2; mi++) {
#pragma unroll
        for (int half = 0; half < 2; half++) {
            int r = m0 + wm * 32 + mi * 16 + (lane >> 2) + half * 8;
            if (r >= M) continue;
            float* crow = C + (size_t)r * NC + n0 + wn * 32 + (lane & 3) * 2;
#pragma unroll
            for (int ni = 0; ni < 4; ni++) {
                float v0 = acc[mi][ni][half * 2];
                float v1 = acc[mi][ni][half * 2 + 1];
                float* cp = crow + ni * 8;
                if (epi == 0) {
                    cp[0] = v0; cp[1] = v1;
                } else {
                    v0 = 0.5f * fmaxf(v0, 0.f);
                    v1 = 0.5f * fmaxf(v1, 0.f);
                    if (epi == 2) { v0 += cp[0]; v1 += cp[1]; }
                    cp[0] = v0; cp[1] = v1;
                }
            }
        }
    }
}

// ================= host orchestration =================
extern "C" void kernel_launch(void* const* d_in, const int* in_sizes, int n_in,
                              void* d_out, int out_size) {
    const float* x   = (const float*)d_in[0];
    const float* pe  = (const float*)d_in[1];
    const int*   ei0 = (const int*)d_in[2];
    const float* ea0 = (const float*)d_in[3];
    const int*   ei1 = (const int*)d_in[4];
    const float* ea1 = (const float*)d_in[5];
    const float* nl1 = (const float*)d_in[6];
    const float* nl2 = (const float*)d_in[7];
    const float* lw[8] = { (const float*)d_in[8],  (const float*)d_in[9],
                           (const float*)d_in[10], (const float*)d_in[11],
                           (const float*)d_in[12], (const float*)d_in[13],
                           (const float*)d_in[14], (const float*)d_in[15] };
    float* out = (float*)d_out;

    int N = in_sizes[0] / 128;
    int E = in_sizes[3];

    __nv_bfloat16 *xch, *xcl, *a0h, *a0l, *a1h, *a1l, *wbh, *wbl, *wsh, *wsl;
    float *xpe, *xm, *dis0, *dis1;
    int *cnt0, *cnt1, *off0, *off1, *cur0, *cur1;
    EdgeRec *ent0, *ent1;
    cudaGetSymbolAddress((void**)&xch, g_xcat_h);
    cudaGetSymbolAddress((void**)&xcl, g_xcat_l);
    cudaGetSymbolAddress((void**)&xpe, g_xpe);
    cudaGetSymbolAddress((void**)&a0h, g_a0h);
    cudaGetSymbolAddress((void**)&a0l, g_a0l);
    cudaGetSymbolAddress((void**)&a1h, g_a1h);
    cudaGetSymbolAddress((void**)&a1l, g_a1l);
    cudaGetSymbolAddress((void**)&xm,  g_xm);
    cudaGetSymbolAddress((void**)&wbh, g_wbh);
    cudaGetSymbolAddress((void**)&wbl, g_wbl);
    cudaGetSymbolAddress((void**)&wsh, g_wsh);
    cudaGetSymbolAddress((void**)&wsl, g_wsl);
    cudaGetSymbolAddress((void**)&cnt0, g_cnt0);
    cudaGetSymbolAddress((void**)&cnt1, g_cnt1);
    cudaGetSymbolAddress((void**)&off0, g_off0);
    cudaGetSymbolAddress((void**)&off1, g_off1);
    cudaGetSymbolAddress((void**)&cur0, g_cur0);
    cudaGetSymbolAddress((void**)&cur1, g_cur1);
    cudaGetSymbolAddress((void**)&dis0, g_dis0);
    cudaGetSymbolAddress((void**)&dis1, g_dis1);
    cudaGetSymbolAddress((void**)&ent0, g_ent0);
    cudaGetSymbolAddress((void**)&ent1, g_ent1);

    cudaFuncSetAttribute(k_hgemm, cudaFuncAttributeMaxDynamicSharedMemorySize, GEMM_SMEM);

    // ---- graph preprocessing ----
    cudaMemsetAsync(cnt0, 0, N * sizeof(int));
    cudaMemsetAsync(cnt1, 0, N * sizeof(int));
    int eb = (E + 255) / 256;
    k_count<<<eb, 256>>>(ei0 + E, cnt0, E);
    k_count<<<eb, 256>>>(ei1 + E, cnt1, E);
    int nb = (N + 255) / 256;
    k_dis<<<nb, 256>>>(cnt0, dis0, N);
    k_dis<<<nb, 256>>>(cnt1, dis1, N);
    k_scan<<<1, 1024>>>(cnt0, off0, cur0, N);
    k_scan<<<1, 1024>>>(cnt1, off1, cur1, N);
    k_fill<<<eb, 256>>>(ei0, ei0 + E, ea0, dis0, cur0, ent0, E);
    k_fill<<<eb, 256>>>(ei1, ei1 + E, ea1, dis1, cur1, ent1, E);

    // ---- feature / weight prep (bf16 hi/lo planes) ----
    k_xcat_split<<<2048, 256>>>(x, pe, xch, xcl, N);
    k_wtcat<<<256, 256>>>(nl1, nl2, wbh, wbl);
    for (int i = 0; i < 4; i++)
        k_wtstk<<<128, 256>>>(lw[2 * i], lw[2 * i + 1], wsh + i * 128 * 256, wsl + i * 128 * 256);

    int mtiles = (N + 127) / 128;

    // ---- stage B: xpe = xcat @ Wcat  ([N,256]) ----
    k_hgemm<<<dim3(4, mtiles), 256, GEMM_SMEM>>>(xch, xcl, wbh, wbl, xpe, N, 256, 0);

    // ---- stage C: gather per graph ----
    int gw = (N + 7) / 8;
    k_gather<<<gw, 256>>>(xpe, 256, 0,   off0, ent0, dis0, a0h, a0l, N);
    k_gather<<<gw, 256>>>(xpe, 256, 128, off1, ent1, dis1, a1h, a1l, N);

    // ---- stage D: xm = 0.5*relu(agg0@Ws1) + 0.5*relu(agg1@Ws2) ----
    dim3 gD(2, mtiles);
    k_hgemm<<<gD, 256, GEMM_SMEM>>>(a0h, a0l, wsh + 0 * 32768, wsl + 0 * 32768, xm, N, 128, 1);
    k_hgemm<<<gD, 256, GEMM_SMEM>>>(a1h, a1l, wsh + 1 * 32768, wsl + 1 * 32768, xm, N, 128, 2);

    // ---- stage E: gather xm per graph ----
    k_gather<<<gw, 256>>>(xm, 128, 0, off0, ent0, dis0, a0h, a0l, N);
    k_gather<<<gw, 256>>>(xm, 128, 0, off1, ent1, dis1, a1h, a1l, N);

    // ---- stage F: out = 0.5*relu(agg0@Ws3) + 0.5*relu(agg1@Ws4) ----
    k_hgemm<<<gD, 256, GEMM_SMEM>>>(a0h, a0l, wsh + 2 * 32768, wsl + 2 * 32768, out, N, 128, 1);
    k_hgemm<<<gD, 256, GEMM_SMEM>>>(a1h, a1l, wsh + 3 * 32768, wsl + 3 * 32768, out, N, 128, 2);
}

// round 4
// speedup vs baseline: 1.5370x; 1.0470x over previous
#include <cuda_runtime.h>
#include <cuda_bf16.h>
#include <cstdint>

#define MAXN 50000
#define MAXE 800000

// ================= device scratch =================
struct __align__(16) EdgeRec { int row; float c1; float c2; float pad; };

__device__ __nv_bfloat16 g_xcat_h[MAXN * 256];
__device__ __nv_bfloat16 g_xcat_l[MAXN * 256];
__device__ float         g_xpe  [MAXN * 256];
__device__ __nv_bfloat16 g_a0h[MAXN * 256];
__device__ __nv_bfloat16 g_a0l[MAXN * 256];
__device__ __nv_bfloat16 g_a1h[MAXN * 256];
__device__ __nv_bfloat16 g_a1l[MAXN * 256];
__device__ float         g_xm [MAXN * 128];
__device__ __nv_bfloat16 g_wbh[256 * 256];
__device__ __nv_bfloat16 g_wbl[256 * 256];
__device__ __nv_bfloat16 g_wsh[4][128 * 256];
__device__ __nv_bfloat16 g_wsl[4][128 * 256];
__device__ int   g_cnt0[MAXN];
__device__ int   g_cnt1[MAXN];
__device__ int   g_off0[MAXN + 1];
__device__ int   g_off1[MAXN + 1];
__device__ int   g_cur0[MAXN];
__device__ int   g_cur1[MAXN];
__device__ float g_dis0[MAXN];
__device__ float g_dis1[MAXN];
__device__ EdgeRec g_ent0[MAXE];
__device__ EdgeRec g_ent1[MAXE];

// ================= graph preprocessing =================
__global__ void k_count(const int* __restrict__ col, int* __restrict__ cnt, int e) {
    int i = blockIdx.x * blockDim.x + threadIdx.x;
    if (i < e) atomicAdd(&cnt[col[i]], 1);
}
__global__ void k_dis(const int* __restrict__ cnt, float* __restrict__ dis, int n) {
    int i = blockIdx.x * blockDim.x + threadIdx.x;
    if (i < n) dis[i] = rsqrtf((float)(cnt[i] + 1));
}
__global__ void k_scan(const int* __restrict__ cnt, int* __restrict__ off,
                       int* __restrict__ cur, int n) {
    __shared__ int s[1024];
    int t = threadIdx.x;
    int chunk = (n + 1023) >> 10;
    int b = t * chunk;
    int e = min(b + chunk, n);
    int sum = 0;
    for (int i = b; i < e; i++) sum += cnt[i];
    s[t] = sum;
    __syncthreads();
    for (int o = 1; o < 1024; o <<= 1) {
        int v = (t >= o) ? s[t - o] : 0;
        __syncthreads();
        s[t] += v;
        __syncthreads();
    }
    int base = s[t] - sum;
    for (int i = b; i < e; i++) { off[i] = base; cur[i] = base; base += cnt[i]; }
    if (t == 1023) off[n] = s[1023];
}
__global__ void k_fill(const int* __restrict__ row, const int* __restrict__ col,
                       const float* __restrict__ attr, const float* __restrict__ dis,
                       int* __restrict__ cur, EdgeRec* __restrict__ ent, int e) {
    int i = blockIdx.x * blockDim.x + threadIdx.x;
    if (i >= e) return;
    int r = row[i], c = col[i];
    float a = attr[i];
    EdgeRec rec;
    rec.row = r;
    rec.c1  = dis[r] * dis[c];
    rec.c2  = (a > 0.f) ? fminf(rsqrtf(a), 1.f) : 0.f;
    rec.pad = 0.f;
    int p = atomicAdd(&cur[c], 1);
    ent[p] = rec;
}

// ================= feature / weight prep =================
__device__ __forceinline__ void bsplit(float v, __nv_bfloat16& h, __nv_bfloat16& l) {
    h = __float2bfloat16(v);
    l = __float2bfloat16(v - __bfloat162float(h));
}

__global__ void k_xcat_split(const float* __restrict__ x, const float* __restrict__ pe,
                             __nv_bfloat16* __restrict__ hi, __nv_bfloat16* __restrict__ lo,
                             int n) {
    int stride = gridDim.x * blockDim.x;
    for (int idx = blockIdx.x * blockDim.x + threadIdx.x; idx < n * 256; idx += stride) {
        int i = idx >> 8, k = idx & 255;
        float v;
        if (k < 128)       v = x[(size_t)i * 128 + k];
        else if (k < 226)  v = pe[(size_t)i * 98 + (k - 128)];
        else               v = 0.f;
        __nv_bfloat16 h, l; bsplit(v, h, l);
        hi[idx] = h; lo[idx] = l;
    }
}

// WcatT[n][k]
__global__ void k_wtcat(const float* __restrict__ w1, const float* __restrict__ w2,
                        __nv_bfloat16* __restrict__ hi, __nv_bfloat16* __restrict__ lo) {
    int idx = blockIdx.x * blockDim.x + threadIdx.x;
    if (idx >= 256 * 256) return;
    int n = idx >> 8, k = idx & 255;
    float v = 0.f;
    if (k < 226) v = (n < 128) ? w1[k * 128 + n] : w2[k * 128 + (n - 128)];
    __nv_bfloat16 h, l; bsplit(v, h, l);
    hi[idx] = h; lo[idx] = l;
}
// WsT[n][k], stacked [lin1 ; lin2]^T
__global__ void k_wtstk(const float* __restrict__ w1, const float* __restrict__ w2,
                        __nv_bfloat16* __restrict__ hi, __nv_bfloat16* __restrict__ lo) {
    int idx = blockIdx.x * blockDim.x + threadIdx.x;
    if (idx >= 128 * 256) return;
    int n = idx >> 8, k = idx & 255;
    float v = (k < 128) ? w1[k * 128 + n] : w2[(k - 128) * 128 + n];
    __nv_bfloat16 h, l; bsplit(v, h, l);
    hi[idx] = h; lo[idx] = l;
}

// ================= CSR gather -> bf16 hi/lo planes =================
__device__ __forceinline__ void split_store4(__nv_bfloat16* hi, __nv_bfloat16* lo, float4 v) {
    __nv_bfloat16 h, l;
    bsplit(v.x, h, l); hi[0] = h; lo[0] = l;
    bsplit(v.y, h, l); hi[1] = h; lo[1] = l;
    bsplit(v.z, h, l); hi[2] = h; lo[2] = l;
    bsplit(v.w, h, l); hi[3] = h; lo[3] = l;
}

__global__ void k_gather(const float* __restrict__ src, int ld, int off,
                         const int* __restrict__ offs, const EdgeRec* __restrict__ ent,
                         const float* __restrict__ dis,
                         __nv_bfloat16* __restrict__ agg_h, __nv_bfloat16* __restrict__ agg_l,
                         int n) {
    int warp = (blockIdx.x * blockDim.x + threadIdx.x) >> 5;
    int lane = threadIdx.x & 31;
    if (warp >= n) return;
    int b = offs[warp], e = offs[warp + 1];
    float4 a1 = make_float4(0.f, 0.f, 0.f, 0.f);
    float4 a2 = make_float4(0.f, 0.f, 0.f, 0.f);
    for (int i = b; i < e; i++) {
        EdgeRec rec = ent[i];
        const float4 v = *reinterpret_cast<const float4*>(
            src + (size_t)rec.row * ld + off + lane * 4);
        a1.x += rec.c1 * v.x; a1.y += rec.c1 * v.y; a1.z += rec.c1 * v.z; a1.w += rec.c1 * v.w;
        a2.x += rec.c2 * v.x; a2.y += rec.c2 * v.y; a2.z += rec.c2 * v.z; a2.w += rec.c2 * v.w;
    }
    float d = dis[warp];
    float sc = d * d;
    const float4 v = *reinterpret_cast<const float4*>(
        src + (size_t)warp * ld + off + lane * 4);
    a1.x += sc * v.x; a1.y += sc * v.y; a1.z += sc * v.z; a1.w += sc * v.w;
    a2.x += v.x;      a2.y += v.y;      a2.z += v.z;      a2.w += v.w;
    size_t base = (size_t)warp * 256 + lane * 4;
    split_store4(agg_h + base,       agg_l + base,       a1);
    split_store4(agg_h + base + 128, agg_l + base + 128, a2);
}

// ================= HMMA GEMM, kc-restructured =========================
// C[M,NC] = sum_s f( (A_s_h+A_s_l)[M,256] @ (B_s_h+B_s_l)[NT-rows,256]^T )
// 3-term bf16 split per source: AhBh + AlBh + AhBl, terms share per-kc loads.
// NSRC=1: raw store (stage B). NSRC=2: C = 0.5*relu(acc0)+0.5*relu(acc1).

__device__ __forceinline__ uint32_t smem_u32(const void* p) {
    uint32_t a;
    asm("{ .reg .u64 t; cvta.to.shared.u64 t, %1; cvt.u32.u64 %0, t; }" : "=r"(a) : "l"(p));
    return a;
}
__device__ __forceinline__ void cp16(uint32_t dst, const void* src) {
    asm volatile("cp.async.cg.shared.global [%0], [%1], 16;" :: "r"(dst), "l"(src));
}
__device__ __forceinline__ void cp_commit() { asm volatile("cp.async.commit_group;"); }
template <int W> __device__ __forceinline__ void cp_wait() {
    asm volatile("cp.async.wait_group %0;" :: "n"(W));
}
__device__ __forceinline__ void ldm_x4(uint32_t* r, uint32_t addr) {
    asm volatile("ldmatrix.sync.aligned.m8n8.x4.shared.b16 {%0,%1,%2,%3}, [%4];"
                 : "=r"(r[0]), "=r"(r[1]), "=r"(r[2]), "=r"(r[3]) : "r"(addr));
}
__device__ __forceinline__ void mma16816(float* c, const uint32_t* a, uint32_t b0, uint32_t b1) {
    asm volatile(
        "mma.sync.aligned.m16n8k16.row.col.f32.bf16.bf16.f32 "
        "{%0,%1,%2,%3}, {%4,%5,%6,%7}, {%8,%9}, {%0,%1,%2,%3};"
        : "+f"(c[0]), "+f"(c[1]), "+f"(c[2]), "+f"(c[3])
        : "r"(a[0]), "r"(a[1]), "r"(a[2]), "r"(a[3]), "r"(b0), "r"(b1));
}

struct GArgs {
    const __nv_bfloat16* A[2][2];   // [src][hi/lo], [M,256]
    const __nv_bfloat16* B[2][2];   // [src][hi/lo], [*,256] (transposed weights)
    float* C;
    int M, NC;
};

template <int NSRC, int NT>
__global__ void __launch_bounds__(256) k_gemm2(GArgs args) {
    constexpr int APL  = 16384;             // 128 rows x 128B
    constexpr int ABUF = NSRC * 2 * APL;
    constexpr int BPL  = NT * 128;
    constexpr int BBUF = NSRC * 2 * BPL;
    constexpr int BUF  = ABUF + BBUF;
    constexpr int NI   = NT / 16;           // n-submatrices per warp tile

    extern __shared__ char sm[];
    const int tid  = threadIdx.x;
    const int lane = tid & 31;
    const int wid  = tid >> 5;
    const int wm   = wid & 3;               // 4 warps along M
    const int wn   = wid >> 2;              // 2 warps along N
    const int m0   = blockIdx.y * 128;
    const int n0   = blockIdx.x * NT;
    const uint32_t sbase = smem_u32(sm);

    const int lr = tid >> 3, lq = tid & 7;  // load coords

    auto issue_load = [&](int kc, int buf) {
        uint32_t sb = sbase + buf * BUF;
#pragma unroll
        for (int s = 0; s < NSRC; s++)
#pragma unroll
            for (int p = 0; p < 2; p++) {
                const __nv_bfloat16* A = args.A[s][p];
                uint32_t sa = sb + (s * 2 + p) * APL;
#pragma unroll
                for (int j = 0; j < 4; j++) {
                    int r = lr + j * 32;
                    int gr = m0 + r; if (gr > args.M - 1) gr = args.M - 1;
                    cp16(sa + r * 128 + ((lq ^ (r & 7)) << 4),
                         A + (size_t)gr * 256 + kc * 64 + lq * 8);
                }
            }
#pragma unroll
        for (int s = 0; s < NSRC; s++)
#pragma unroll
            for (int p = 0; p < 2; p++) {
                const __nv_bfloat16* B = args.B[s][p];
                uint32_t sbB = sb + ABUF + (s * 2 + p) * BPL;
#pragma unroll
                for (int j = 0; j < NT / 32; j++) {
                    int r = lr + j * 32;
                    cp16(sbB + r * 128 + ((lq ^ (r & 7)) << 4),
                         B + (size_t)(n0 + r) * 256 + kc * 64 + lq * 8);
                }
            }
        cp_commit();
    };

    float acc[NSRC][2][NI][4];
#pragma unroll
    for (int s = 0; s < NSRC; s++)
#pragma unroll
        for (int mi = 0; mi < 2; mi++)
#pragma unroll
            for (int ni = 0; ni < NI; ni++)
#pragma unroll
                for (int k = 0; k < 4; k++) acc[s][mi][ni][k] = 0.f;

    issue_load(0, 0);

    for (int kc = 0; kc < 4; kc++) {
        if (kc < 3) { issue_load(kc + 1, (kc + 1) & 1); cp_wait<1>(); }
        else        { cp_wait<0>(); }
        __syncthreads();

        uint32_t sb = sbase + (kc & 1) * BUF;

#pragma unroll
        for (int ks = 0; ks < 4; ks++) {
#pragma unroll
            for (int s = 0; s < NSRC; s++) {
                uint32_t afH[2][4], afL[2][4];
#pragma unroll
                for (int mi = 0; mi < 2; mi++) {
                    int row = wm * 32 + mi * 16 + (lane & 15);
                    int c16 = (2 * ks + (lane >> 4)) ^ (row & 7);
                    ldm_x4(afH[mi], sb + (s * 2 + 0) * APL + row * 128 + (c16 << 4));
                    ldm_x4(afL[mi], sb + (s * 2 + 1) * APL + row * 128 + (c16 << 4));
                }
                uint32_t bfH[NI][2], bfL[NI][2];
#pragma unroll
                for (int np = 0; np < NT / 32; np++) {
                    int nrow = wn * (NT / 2) + np * 16 + ((lane >> 4) << 3) + (lane & 7);
                    int c16 = (2 * ks + ((lane >> 3) & 1)) ^ (nrow & 7);
                    uint32_t t4[4];
                    ldm_x4(t4, sb + ABUF + (s * 2 + 0) * BPL + nrow * 128 + (c16 << 4));
                    bfH[np * 2][0] = t4[0]; bfH[np * 2][1] = t4[1];
                    bfH[np * 2 + 1][0] = t4[2]; bfH[np * 2 + 1][1] = t4[3];
                    ldm_x4(t4, sb + ABUF + (s * 2 + 1) * BPL + nrow * 128 + (c16 << 4));
                    bfL[np * 2][0] = t4[0]; bfL[np * 2][1] = t4[1];
                    bfL[np * 2 + 1][0] = t4[2]; bfL[np * 2 + 1][1] = t4[3];
                }
#pragma unroll
                for (int mi = 0; mi < 2; mi++)
#pragma unroll
                    for (int ni = 0; ni < NI; ni++) {
                        mma16816(acc[s][mi][ni], afH[mi], bfH[ni][0], bfH[ni][1]);
                        mma16816(acc[s][mi][ni], afL[mi], bfH[ni][0], bfH[ni][1]);
                        mma16816(acc[s][mi][ni], afH[mi], bfL[ni][0], bfL[ni][1]);
                    }
            }
        }
        __syncthreads();
    }

    // epilogue
#pragma unroll
    for (int mi = 0; mi < 2; mi++) {
#pragma unroll
        for (int half = 0; half < 2; half++) {
            int r = m0 + wm * 32 + mi * 16 + (lane >> 2) + half * 8;
            if (r >= args.M) continue;
            float* crow = args.C + (size_t)r * args.NC + n0 + wn * (NT / 2) + (lane & 3) * 2;
#pragma unroll
            for (int ni = 0; ni < NI; ni++) {
                float v0, v1;
                if (NSRC == 1) {
                    v0 = acc[0][mi][ni][half * 2];
                    v1 = acc[0][mi][ni][half * 2 + 1];
                } else {
                    v0 = 0.5f * (fmaxf(acc[0][mi][ni][half * 2], 0.f) +
                                 fmaxf(acc[NSRC - 1][mi][ni][half * 2], 0.f));
                    v1 = 0.5f * (fmaxf(acc[0][mi][ni][half * 2 + 1], 0.f) +
                                 fmaxf(acc[NSRC - 1][mi][ni][half * 2 + 1], 0.f));
                }
                crow[ni * 8] = v0; crow[ni * 8 + 1] = v1;
            }
        }
    }
}

#define SMEM_B1 (2 * (2 * 16384 + 2 * 128 * 128))          // 131072
#define SMEM_B2 (2 * (4 * 16384 + 4 * 64 * 128))           // 196608

// ================= host orchestration =================
extern "C" void kernel_launch(void* const* d_in, const int* in_sizes, int n_in,
                              void* d_out, int out_size) {
    const float* x   = (const float*)d_in[0];
    const float* pe  = (const float*)d_in[1];
    const int*   ei0 = (const int*)d_in[2];
    const float* ea0 = (const float*)d_in[3];
    const int*   ei1 = (const int*)d_in[4];
    const float* ea1 = (const float*)d_in[5];
    const float* nl1 = (const float*)d_in[6];
    const float* nl2 = (const float*)d_in[7];
    const float* lw[8] = { (const float*)d_in[8],  (const float*)d_in[9],
                           (const float*)d_in[10], (const float*)d_in[11],
                           (const float*)d_in[12], (const float*)d_in[13],
                           (const float*)d_in[14], (const float*)d_in[15] };
    float* out = (float*)d_out;

    int N = in_sizes[0] / 128;
    int E = in_sizes[3];

    __nv_bfloat16 *xch, *xcl, *a0h, *a0l, *a1h, *a1l, *wbh, *wbl, *wsh, *wsl;
    float *xpe, *xm, *dis0, *dis1;
    int *cnt0, *cnt1, *off0, *off1, *cur0, *cur1;
    EdgeRec *ent0, *ent1;
    cudaGetSymbolAddress((void**)&xch, g_xcat_h);
    cudaGetSymbolAddress((void**)&xcl, g_xcat_l);
    cudaGetSymbolAddress((void**)&xpe, g_xpe);
    cudaGetSymbolAddress((void**)&a0h, g_a0h);
    cudaGetSymbolAddress((void**)&a0l, g_a0l);
    cudaGetSymbolAddress((void**)&a1h, g_a1h);
    cudaGetSymbolAddress((void**)&a1l, g_a1l);
    cudaGetSymbolAddress((void**)&xm,  g_xm);
    cudaGetSymbolAddress((void**)&wbh, g_wbh);
    cudaGetSymbolAddress((void**)&wbl, g_wbl);
    cudaGetSymbolAddress((void**)&wsh, g_wsh);
    cudaGetSymbolAddress((void**)&wsl, g_wsl);
    cudaGetSymbolAddress((void**)&cnt0, g_cnt0);
    cudaGetSymbolAddress((void**)&cnt1, g_cnt1);
    cudaGetSymbolAddress((void**)&off0, g_off0);
    cudaGetSymbolAddress((void**)&off1, g_off1);
    cudaGetSymbolAddress((void**)&cur0, g_cur0);
    cudaGetSymbolAddress((void**)&cur1, g_cur1);
    cudaGetSymbolAddress((void**)&dis0, g_dis0);
    cudaGetSymbolAddress((void**)&dis1, g_dis1);
    cudaGetSymbolAddress((void**)&ent0, g_ent0);
    cudaGetSymbolAddress((void**)&ent1, g_ent1);

    cudaFuncSetAttribute(k_gemm2<1, 128>, cudaFuncAttributeMaxDynamicSharedMemorySize, SMEM_B1);
    cudaFuncSetAttribute(k_gemm2<2, 64>,  cudaFuncAttributeMaxDynamicSharedMemorySize, SMEM_B2);

    // ---- graph preprocessing ----
    cudaMemsetAsync(cnt0, 0, N * sizeof(int));
    cudaMemsetAsync(cnt1, 0, N * sizeof(int));
    int eb = (E + 255) / 256;
    k_count<<<eb, 256>>>(ei0 + E, cnt0, E);
    k_count<<<eb, 256>>>(ei1 + E, cnt1, E);
    int nb = (N + 255) / 256;
    k_dis<<<nb, 256>>>(cnt0, dis0, N);
    k_dis<<<nb, 256>>>(cnt1, dis1, N);
    k_scan<<<1, 1024>>>(cnt0, off0, cur0, N);
    k_scan<<<1, 1024>>>(cnt1, off1, cur1, N);
    k_fill<<<eb, 256>>>(ei0, ei0 + E, ea0, dis0, cur0, ent0, E);
    k_fill<<<eb, 256>>>(ei1, ei1 + E, ea1, dis1, cur1, ent1, E);

    // ---- feature / weight prep (bf16 hi/lo planes) ----
    k_xcat_split<<<2048, 256>>>(x, pe, xch, xcl, N);
    k_wtcat<<<256, 256>>>(nl1, nl2, wbh, wbl);
    for (int i = 0; i < 4; i++)
        k_wtstk<<<128, 256>>>(lw[2 * i], lw[2 * i + 1], wsh + i * 128 * 256, wsl + i * 128 * 256);

    int mtiles = (N + 127) / 128;

    // ---- stage B: xpe = xcat @ Wcat ----
    {
        GArgs a = {};
        a.A[0][0] = xch; a.A[0][1] = xcl;
        a.B[0][0] = wbh; a.B[0][1] = wbl;
        a.C = xpe; a.M = N; a.NC = 256;
        k_gemm2<1, 128><<<dim3(2, mtiles), 256, SMEM_B1>>>(a);
    }

    // ---- stage C: gather per graph ----
    int gw = (N + 7) / 8;
    k_gather<<<gw, 256>>>(xpe, 256, 0,   off0, ent0, dis0, a0h, a0l, N);
    k_gather<<<gw, 256>>>(xpe, 256, 128, off1, ent1, dis1, a1h, a1l, N);

    // ---- stage D (fused): xm = 0.5*relu(a0@Ws1) + 0.5*relu(a1@Ws2) ----
    {
        GArgs a = {};
        a.A[0][0] = a0h; a.A[0][1] = a0l;
        a.A[1][0] = a1h; a.A[1][1] = a1l;
        a.B[0][0] = wsh + 0 * 32768; a.B[0][1] = wsl + 0 * 32768;
        a.B[1][0] = wsh + 1 * 32768; a.B[1][1] = wsl + 1 * 32768;
        a.C = xm; a.M = N; a.NC = 128;
        k_gemm2<2, 64><<<dim3(2, mtiles), 256, SMEM_B2>>>(a);
    }

    // ---- stage E: gather xm per graph ----
    k_gather<<<gw, 256>>>(xm, 128, 0, off0, ent0, dis0, a0h, a0l, N);
    k_gather<<<gw, 256>>>(xm, 128, 0, off1, ent1, dis1, a1h, a1l, N);

    // ---- stage F (fused): out = 0.5*relu(a0@Ws3) + 0.5*relu(a1@Ws4) ----
    {
        GArgs a = {};
        a.A[0][0] = a0h; a.A[0][1] = a0l;
        a.A[1][0] = a1h; a.A[1][1] = a1l;
        a.B[0][0] = wsh + 2 * 32768; a.B[0][1] = wsl + 2 * 32768;
        a.B[1][0] = wsh + 3 * 32768; a.B[1][1] = wsl + 3 * 32768;
        a.C = out; a.M = N; a.NC = 128;
        k_gemm2<2, 64><<<dim3(2, mtiles), 256, SMEM_B2>>>(a);
    }
}

// round 5
// speedup vs baseline: 2.1368x; 1.3903x over previous
#include <cuda_runtime.h>
#include <cuda_bf16.h>
#include <cstdint>

#define MAXN 50000
#define MAXE 800000

// ================= device scratch =================
struct __align__(16) EdgeRec { int row; float c1; float c2; float pad; };

__device__ __nv_bfloat16 g_xcat_h[MAXN * 256];
__device__ __nv_bfloat16 g_xcat_l[MAXN * 256];
__device__ float         g_xpe  [MAXN * 256];
__device__ __nv_bfloat16 g_a0h[MAXN * 256];
__device__ __nv_bfloat16 g_a0l[MAXN * 256];
__device__ __nv_bfloat16 g_a1h[MAXN * 256];
__device__ __nv_bfloat16 g_a1l[MAXN * 256];
__device__ float         g_xm [MAXN * 128];
__device__ __nv_bfloat16 g_wbh[256 * 256];
__device__ __nv_bfloat16 g_wbl[256 * 256];
__device__ __nv_bfloat16 g_wsh[4][128 * 256];
__device__ __nv_bfloat16 g_wsl[4][128 * 256];
__device__ int   g_cnt0[MAXN];
__device__ int   g_cnt1[MAXN];
__device__ int   g_off0[MAXN + 1];
__device__ int   g_off1[MAXN + 1];
__device__ int   g_cur0[MAXN];
__device__ int   g_cur1[MAXN];
__device__ float g_dis0[MAXN];
__device__ float g_dis1[MAXN];
__device__ EdgeRec g_ent0[MAXE];
__device__ EdgeRec g_ent1[MAXE];

// ================= batched graph preprocessing (both graphs per launch) ======
__global__ void k_count2(const int* __restrict__ c0, const int* __restrict__ c1,
                         int* __restrict__ cnt0, int* __restrict__ cnt1, int e) {
    int i = blockIdx.x * blockDim.x + threadIdx.x;
    const int* col = blockIdx.y ? c1 : c0;
    int* cnt = blockIdx.y ? cnt1 : cnt0;
    if (i < e) atomicAdd(&cnt[col[i]], 1);
}
__global__ void k_dis2(const int* __restrict__ cnt0, const int* __restrict__ cnt1,
                       float* __restrict__ dis0, float* __restrict__ dis1, int n) {
    int i = blockIdx.x * blockDim.x + threadIdx.x;
    const int* cnt = blockIdx.y ? cnt1 : cnt0;
    float* dis = blockIdx.y ? dis1 : dis0;
    if (i < n) dis[i] = rsqrtf((float)(cnt[i] + 1));
}
__global__ void k_scan2(const int* __restrict__ cnt0, const int* __restrict__ cnt1,
                        int* __restrict__ off0, int* __restrict__ off1,
                        int* __restrict__ cur0, int* __restrict__ cur1, int n) {
    __shared__ int s[1024];
    const int* cnt = blockIdx.x ? cnt1 : cnt0;
    int* off = blockIdx.x ? off1 : off0;
    int* cur = blockIdx.x ? cur1 : cur0;
    int t = threadIdx.x;
    int chunk = (n + 1023) >> 10;
    int b = t * chunk;
    int e = min(b + chunk, n);
    int sum = 0;
    for (int i = b; i < e; i++) sum += cnt[i];
    s[t] = sum;
    __syncthreads();
    for (int o = 1; o < 1024; o <<= 1) {
        int v = (t >= o) ? s[t - o] : 0;
        __syncthreads();
        s[t] += v;
        __syncthreads();
    }
    int base = s[t] - sum;
    for (int i = b; i < e; i++) { off[i] = base; cur[i] = base; base += cnt[i]; }
    if (t == 1023) off[n] = s[1023];
}
__global__ void k_fill2(const int* __restrict__ ei0, const float* __restrict__ ea0,
                        const int* __restrict__ ei1, const float* __restrict__ ea1,
                        const float* __restrict__ dis0, const float* __restrict__ dis1,
                        int* __restrict__ cur0, int* __restrict__ cur1,
                        EdgeRec* __restrict__ ent0, EdgeRec* __restrict__ ent1, int e) {
    int i = blockIdx.x * blockDim.x + threadIdx.x;
    if (i >= e) return;
    const int* ei = blockIdx.y ? ei1 : ei0;
    const float* attr = blockIdx.y ? ea1 : ea0;
    const float* dis = blockIdx.y ? dis1 : dis0;
    int* cur = blockIdx.y ? cur1 : cur0;
    EdgeRec* ent = blockIdx.y ? ent1 : ent0;
    int r = ei[i], c = ei[e + i];
    float a = attr[i];
    EdgeRec rec;
    rec.row = r;
    rec.c1  = dis[r] * dis[c];
    rec.c2  = (a > 0.f) ? fminf(rsqrtf(a), 1.f) : 0.f;
    rec.pad = 0.f;
    int p = atomicAdd(&cur[c], 1);
    ent[p] = rec;
}

// ================= feature / weight prep =================
__device__ __forceinline__ void bsplit(float v, __nv_bfloat16& h, __nv_bfloat16& l) {
    h = __float2bfloat16(v);
    l = __float2bfloat16(v - __bfloat162float(h));
}

__global__ void k_xcat_split(const float* __restrict__ x, const float* __restrict__ pe,
                             __nv_bfloat16* __restrict__ hi, __nv_bfloat16* __restrict__ lo,
                             int n) {
    int stride = gridDim.x * blockDim.x;
    for (int idx = blockIdx.x * blockDim.x + threadIdx.x; idx < n * 256; idx += stride) {
        int i = idx >> 8, k = idx & 255;
        float v;
        if (k < 128)       v = x[(size_t)i * 128 + k];
        else if (k < 226)  v = pe[(size_t)i * 98 + (k - 128)];
        else               v = 0.f;
        __nv_bfloat16 h, l; bsplit(v, h, l);
        hi[idx] = h; lo[idx] = l;
    }
}

// WcatT[n][k]
__global__ void k_wtcat(const float* __restrict__ w1, const float* __restrict__ w2,
                        __nv_bfloat16* __restrict__ hi, __nv_bfloat16* __restrict__ lo) {
    int idx = blockIdx.x * blockDim.x + threadIdx.x;
    if (idx >= 256 * 256) return;
    int n = idx >> 8, k = idx & 255;
    float v = 0.f;
    if (k < 226) v = (n < 128) ? w1[k * 128 + n] : w2[k * 128 + (n - 128)];
    __nv_bfloat16 h, l; bsplit(v, h, l);
    hi[idx] = h; lo[idx] = l;
}
// WsT[n][k], stacked [lin1 ; lin2]^T, 4 layer pairs batched via blockIdx.y
__global__ void k_wtstk4(const float* __restrict__ w10, const float* __restrict__ w20,
                         const float* __restrict__ w11, const float* __restrict__ w21,
                         const float* __restrict__ w12, const float* __restrict__ w22,
                         const float* __restrict__ w13, const float* __restrict__ w23,
                         __nv_bfloat16* __restrict__ hi, __nv_bfloat16* __restrict__ lo) {
    int idx = blockIdx.x * blockDim.x + threadIdx.x;
    if (idx >= 128 * 256) return;
    int g = blockIdx.y;
    const float* w1 = (g == 0) ? w10 : (g == 1) ? w11 : (g == 2) ? w12 : w13;
    const float* w2 = (g == 0) ? w20 : (g == 1) ? w21 : (g == 2) ? w22 : w23;
    int n = idx >> 8, k = idx & 255;
    float v = (k < 128) ? w1[k * 128 + n] : w2[(k - 128) * 128 + n];
    __nv_bfloat16 h, l; bsplit(v, h, l);
    hi[g * 32768 + idx] = h; lo[g * 32768 + idx] = l;
}

// ================= CSR gather -> bf16 hi/lo planes =================
__device__ __forceinline__ void split_store4(__nv_bfloat16* hi, __nv_bfloat16* lo, float4 v) {
    __nv_bfloat16 h, l;
    bsplit(v.x, h, l); hi[0] = h; lo[0] = l;
    bsplit(v.y, h, l); hi[1] = h; lo[1] = l;
    bsplit(v.z, h, l); hi[2] = h; lo[2] = l;
    bsplit(v.w, h, l); hi[3] = h; lo[3] = l;
}

__global__ void k_gather(const float* __restrict__ src, int ld, int off,
                         const int* __restrict__ offs, const EdgeRec* __restrict__ ent,
                         const float* __restrict__ dis,
                         __nv_bfloat16* __restrict__ agg_h, __nv_bfloat16* __restrict__ agg_l,
                         int n) {
    int warp = (blockIdx.x * blockDim.x + threadIdx.x) >> 5;
    int lane = threadIdx.x & 31;
    if (warp >= n) return;
    int b = offs[warp], e = offs[warp + 1];
    float4 a1 = make_float4(0.f, 0.f, 0.f, 0.f);
    float4 a2 = make_float4(0.f, 0.f, 0.f, 0.f);
    int i = b;
    // unroll-by-2: two independent gather loads in flight
    for (; i + 2 <= e; i += 2) {
        EdgeRec r0 = ent[i];
        EdgeRec r1 = ent[i + 1];
        const float4 v0 = *reinterpret_cast<const float4*>(
            src + (size_t)r0.row * ld + off + lane * 4);
        const float4 v1 = *reinterpret_cast<const float4*>(
            src + (size_t)r1.row * ld + off + lane * 4);
        a1.x += r0.c1 * v0.x; a1.y += r0.c1 * v0.y; a1.z += r0.c1 * v0.z; a1.w += r0.c1 * v0.w;
        a2.x += r0.c2 * v0.x; a2.y += r0.c2 * v0.y; a2.z += r0.c2 * v0.z; a2.w += r0.c2 * v0.w;
        a1.x += r1.c1 * v1.x; a1.y += r1.c1 * v1.y; a1.z += r1.c1 * v1.z; a1.w += r1.c1 * v1.w;
        a2.x += r1.c2 * v1.x; a2.y += r1.c2 * v1.y; a2.z += r1.c2 * v1.z; a2.w += r1.c2 * v1.w;
    }
    if (i < e) {
        EdgeRec rec = ent[i];
        const float4 v = *reinterpret_cast<const float4*>(
            src + (size_t)rec.row * ld + off + lane * 4);
        a1.x += rec.c1 * v.x; a1.y += rec.c1 * v.y; a1.z += rec.c1 * v.z; a1.w += rec.c1 * v.w;
        a2.x += rec.c2 * v.x; a2.y += rec.c2 * v.y; a2.z += rec.c2 * v.z; a2.w += rec.c2 * v.w;
    }
    float d = dis[warp];
    float sc = d * d;
    const float4 v = *reinterpret_cast<const float4*>(
        src + (size_t)warp * ld + off + lane * 4);
    a1.x += sc * v.x; a1.y += sc * v.y; a1.z += sc * v.z; a1.w += sc * v.w;
    a2.x += v.x;      a2.y += v.y;      a2.z += v.z;      a2.w += v.w;
    size_t base = (size_t)warp * 256 + lane * 4;
    split_store4(agg_h + base,       agg_l + base,       a1);
    split_store4(agg_h + base + 128, agg_l + base + 128, a2);
}

// ================= HMMA GEMM, kc-restructured =========================
__device__ __forceinline__ uint32_t smem_u32(const void* p) {
    uint32_t a;
    asm("{ .reg .u64 t; cvta.to.shared.u64 t, %1; cvt.u32.u64 %0, t; }" : "=r"(a) : "l"(p));
    return a;
}
__device__ __forceinline__ void cp16(uint32_t dst, const void* src) {
    asm volatile("cp.async.cg.shared.global [%0], [%1], 16;" :: "r"(dst), "l"(src));
}
__device__ __forceinline__ void cp_commit() { asm volatile("cp.async.commit_group;"); }
template <int W> __device__ __forceinline__ void cp_wait() {
    asm volatile("cp.async.wait_group %0;" :: "n"(W));
}
__device__ __forceinline__ void ldm_x4(uint32_t* r, uint32_t addr) {
    asm volatile("ldmatrix.sync.aligned.m8n8.x4.shared.b16 {%0,%1,%2,%3}, [%4];"
                 : "=r"(r[0]), "=r"(r[1]), "=r"(r[2]), "=r"(r[3]) : "r"(addr));
}
__device__ __forceinline__ void mma16816(float* c, const uint32_t* a, uint32_t b0, uint32_t b1) {
    asm volatile(
        "mma.sync.aligned.m16n8k16.row.col.f32.bf16.bf16.f32 "
        "{%0,%1,%2,%3}, {%4,%5,%6,%7}, {%8,%9}, {%0,%1,%2,%3};"
        : "+f"(c[0]), "+f"(c[1]), "+f"(c[2]), "+f"(c[3])
        : "r"(a[0]), "r"(a[1]), "r"(a[2]), "r"(a[3]), "r"(b0), "r"(b1));
}

struct GArgs {
    const __nv_bfloat16* A[2][2];   // [src][hi/lo], [M,256]
    const __nv_bfloat16* B[2][2];   // [src][hi/lo], [*,256] (transposed weights)
    float* C;
    int M, NC;
};

template <int NSRC, int NT>
__global__ void __launch_bounds__(256) k_gemm2(GArgs args) {
    constexpr int APL  = 16384;
    constexpr int ABUF = NSRC * 2 * APL;
    constexpr int BPL  = NT * 128;
    constexpr int BBUF = NSRC * 2 * BPL;
    constexpr int BUF  = ABUF + BBUF;
    constexpr int NI   = NT / 16;

    extern __shared__ char sm[];
    const int tid  = threadIdx.x;
    const int lane = tid & 31;
    const int wid  = tid >> 5;
    const int wm   = wid & 3;
    const int wn   = wid >> 2;
    const int m0   = blockIdx.y * 128;
    const int n0   = blockIdx.x * NT;
    const uint32_t sbase = smem_u32(sm);

    const int lr = tid >> 3, lq = tid & 7;

    auto issue_load = [&](int kc, int buf) {
        uint32_t sb = sbase + buf * BUF;
#pragma unroll
        for (int s = 0; s < NSRC; s++)
#pragma unroll
            for (int p = 0; p < 2; p++) {
                const __nv_bfloat16* A = args.A[s][p];
                uint32_t sa = sb + (s * 2 + p) * APL;
#pragma unroll
                for (int j = 0; j < 4; j++) {
                    int r = lr + j * 32;
                    int gr = m0 + r; if (gr > args.M - 1) gr = args.M - 1;
                    cp16(sa + r * 128 + ((lq ^ (r & 7)) << 4),
                         A + (size_t)gr * 256 + kc * 64 + lq * 8);
                }
            }
#pragma unroll
        for (int s = 0; s < NSRC; s++)
#pragma unroll
            for (int p = 0; p < 2; p++) {
                const __nv_bfloat16* B = args.B[s][p];
                uint32_t sbB = sb + ABUF + (s * 2 + p) * BPL;
#pragma unroll
                for (int j = 0; j < NT / 32; j++) {
                    int r = lr + j * 32;
                    cp16(sbB + r * 128 + ((lq ^ (r & 7)) << 4),
                         B + (size_t)(n0 + r) * 256 + kc * 64 + lq * 8);
                }
            }
        cp_commit();
    };

    float acc[NSRC][2][NI][4];
#pragma unroll
    for (int s = 0; s < NSRC; s++)
#pragma unroll
        for (int mi = 0; mi < 2; mi++)
#pragma unroll
            for (int ni = 0; ni < NI; ni++)
#pragma unroll
                for (int k = 0; k < 4; k++) acc[s][mi][ni][k] = 0.f;

    issue_load(0, 0);

    for (int kc = 0; kc < 4; kc++) {
        if (kc < 3) { issue_load(kc + 1, (kc + 1) & 1); cp_wait<1>(); }
        else        { cp_wait<0>(); }
        __syncthreads();

        uint32_t sb = sbase + (kc & 1) * BUF;

#pragma unroll
        for (int ks = 0; ks < 4; ks++) {
#pragma unroll
            for (int s = 0; s < NSRC; s++) {
                uint32_t afH[2][4], afL[2][4];
#pragma unroll
                for (int mi = 0; mi < 2; mi++) {
                    int row = wm * 32 + mi * 16 + (lane & 15);
                    int c16 = (2 * ks + (lane >> 4)) ^ (row & 7);
                    ldm_x4(afH[mi], sb + (s * 2 + 0) * APL + row * 128 + (c16 << 4));
                    ldm_x4(afL[mi], sb + (s * 2 + 1) * APL + row * 128 + (c16 << 4));
                }
                uint32_t bfH[NI][2], bfL[NI][2];
#pragma unroll
                for (int np = 0; np < NT / 32; np++) {
                    int nrow = wn * (NT / 2) + np * 16 + ((lane >> 4) << 3) + (lane & 7);
                    int c16 = (2 * ks + ((lane >> 3) & 1)) ^ (nrow & 7);
                    uint32_t t4[4];
                    ldm_x4(t4, sb + ABUF + (s * 2 + 0) * BPL + nrow * 128 + (c16 << 4));
                    bfH[np * 2][0] = t4[0]; bfH[np * 2][1] = t4[1];
                    bfH[np * 2 + 1][0] = t4[2]; bfH[np * 2 + 1][1] = t4[3];
                    ldm_x4(t4, sb + ABUF + (s * 2 + 1) * BPL + nrow * 128 + (c16 << 4));
                    bfL[np * 2][0] = t4[0]; bfL[np * 2][1] = t4[1];
                    bfL[np * 2 + 1][0] = t4[2]; bfL[np * 2 + 1][1] = t4[3];
                }
#pragma unroll
                for (int mi = 0; mi < 2; mi++)
#pragma unroll
                    for (int ni = 0; ni < NI; ni++) {
                        mma16816(acc[s][mi][ni], afH[mi], bfH[ni][0], bfH[ni][1]);
                        mma16816(acc[s][mi][ni], afL[mi], bfH[ni][0], bfH[ni][1]);
                        mma16816(acc[s][mi][ni], afH[mi], bfL[ni][0], bfL[ni][1]);
                    }
            }
        }
        __syncthreads();
    }

#pragma unroll
    for (int mi = 0; mi < 2; mi++) {
#pragma unroll
        for (int half = 0; half < 2; half++) {
            int r = m0 + wm * 32 + mi * 16 + (lane >> 2) + half * 8;
            if (r >= args.M) continue;
            float* crow = args.C + (size_t)r * args.NC + n0 + wn * (NT / 2) + (lane & 3) * 2;
#pragma unroll
            for (int ni = 0; ni < NI; ni++) {
                float v0, v1;
                if (NSRC == 1) {
                    v0 = acc[0][mi][ni][half * 2];
                    v1 = acc[0][mi][ni][half * 2 + 1];
                } else {
                    v0 = 0.5f * (fmaxf(acc[0][mi][ni][half * 2], 0.f) +
                                 fmaxf(acc[NSRC - 1][mi][ni][half * 2], 0.f));
                    v1 = 0.5f * (fmaxf(acc[0][mi][ni][half * 2 + 1], 0.f) +
                                 fmaxf(acc[NSRC - 1][mi][ni][half * 2 + 1], 0.f));
                }
                crow[ni * 8] = v0; crow[ni * 8 + 1] = v1;
            }
        }
    }
}

#define SMEM_B1 (2 * (2 * 16384 + 2 * 128 * 128))          // 131072
#define SMEM_B2 (2 * (4 * 16384 + 4 * 64 * 128))           // 196608

// ================= host orchestration =================
extern "C" void kernel_launch(void* const* d_in, const int* in_sizes, int n_in,
                              void* d_out, int out_size) {
    const float* x   = (const float*)d_in[0];
    const float* pe  = (const float*)d_in[1];
    const int*   ei0 = (const int*)d_in[2];
    const float* ea0 = (const float*)d_in[3];
    const int*   ei1 = (const int*)d_in[4];
    const float* ea1 = (const float*)d_in[5];
    const float* nl1 = (const float*)d_in[6];
    const float* nl2 = (const float*)d_in[7];
    const float* lw[8] = { (const float*)d_in[8],  (const float*)d_in[9],
                           (const float*)d_in[10], (const float*)d_in[11],
                           (const float*)d_in[12], (const float*)d_in[13],
                           (const float*)d_in[14], (const float*)d_in[15] };
    float* out = (float*)d_out;

    int N = in_sizes[0] / 128;
    int E = in_sizes[3];

    __nv_bfloat16 *xch, *xcl, *a0h, *a0l, *a1h, *a1l, *wbh, *wbl, *wsh, *wsl;
    float *xpe, *xm, *dis0, *dis1;
    int *cnt0, *cnt1, *off0, *off1, *cur0, *cur1;
    EdgeRec *ent0, *ent1;
    cudaGetSymbolAddress((void**)&xch, g_xcat_h);
    cudaGetSymbolAddress((void**)&xcl, g_xcat_l);
    cudaGetSymbolAddress((void**)&xpe, g_xpe);
    cudaGetSymbolAddress((void**)&a0h, g_a0h);
    cudaGetSymbolAddress((void**)&a0l, g_a0l);
    cudaGetSymbolAddress((void**)&a1h, g_a1h);
    cudaGetSymbolAddress((void**)&a1l, g_a1l);
    cudaGetSymbolAddress((void**)&xm,  g_xm);
    cudaGetSymbolAddress((void**)&wbh, g_wbh);
    cudaGetSymbolAddress((void**)&wbl, g_wbl);
    cudaGetSymbolAddress((void**)&wsh, g_wsh);
    cudaGetSymbolAddress((void**)&wsl, g_wsl);
    cudaGetSymbolAddress((void**)&cnt0, g_cnt0);
    cudaGetSymbolAddress((void**)&cnt1, g_cnt1);
    cudaGetSymbolAddress((void**)&off0, g_off0);
    cudaGetSymbolAddress((void**)&off1, g_off1);
    cudaGetSymbolAddress((void**)&cur0, g_cur0);
    cudaGetSymbolAddress((void**)&cur1, g_cur1);
    cudaGetSymbolAddress((void**)&dis0, g_dis0);
    cudaGetSymbolAddress((void**)&dis1, g_dis1);
    cudaGetSymbolAddress((void**)&ent0, g_ent0);
    cudaGetSymbolAddress((void**)&ent1, g_ent1);

    cudaFuncSetAttribute(k_gemm2<1, 128>, cudaFuncAttributeMaxDynamicSharedMemorySize, SMEM_B1);
    cudaFuncSetAttribute(k_gemm2<2, 64>,  cudaFuncAttributeMaxDynamicSharedMemorySize, SMEM_B2);

    // lazy one-time stream/event setup (resource creation, not work)
    static cudaStream_t s1 = nullptr;
    static cudaEvent_t ev[6];
    if (s1 == nullptr) {
        cudaStreamCreateWithFlags(&s1, cudaStreamNonBlocking);
        for (int i = 0; i < 6; i++) cudaEventCreateWithFlags(&ev[i], cudaEventDisableTiming);
    }

    int eb = (E + 255) / 256;
    int nb = (N + 255) / 256;
    int mtiles = (N + 127) / 128;
    int gw = (N + 7) / 8;

    // ======== fork: preprocessing on s1, prep + stage B on main ========
    cudaEventRecord(ev[0], 0);
    cudaStreamWaitEvent(s1, ev[0], 0);

    cudaMemsetAsync(cnt0, 0, N * sizeof(int), s1);
    cudaMemsetAsync(cnt1, 0, N * sizeof(int), s1);
    k_count2<<<dim3(eb, 2), 256, 0, s1>>>(ei0 + E, ei1 + E, cnt0, cnt1, E);
    k_dis2<<<dim3(nb, 2), 256, 0, s1>>>(cnt0, cnt1, dis0, dis1, N);
    k_scan2<<<2, 1024, 0, s1>>>(cnt0, cnt1, off0, off1, cur0, cur1, N);
    k_fill2<<<dim3(eb, 2), 256, 0, s1>>>(ei0, ea0, ei1, ea1, dis0, dis1,
                                         cur0, cur1, ent0, ent1, E);
    cudaEventRecord(ev[1], s1);

    // main: feature/weight prep + stage B
    k_xcat_split<<<2048, 256>>>(x, pe, xch, xcl, N);
    k_wtcat<<<256, 256>>>(nl1, nl2, wbh, wbl);
    k_wtstk4<<<dim3(128, 4), 256>>>(lw[0], lw[1], lw[2], lw[3],
                                    lw[4], lw[5], lw[6], lw[7], wsh, wsl);
    {
        GArgs a = {};
        a.A[0][0] = xch; a.A[0][1] = xcl;
        a.B[0][0] = wbh; a.B[0][1] = wbl;
        a.C = xpe; a.M = N; a.NC = 256;
        k_gemm2<1, 128><<<dim3(2, mtiles), 256, SMEM_B1>>>(a);
    }
    cudaStreamWaitEvent(0, ev[1], 0);   // join preprocessing

    // ======== stage C: two gathers in parallel ========
    cudaEventRecord(ev[2], 0);
    cudaStreamWaitEvent(s1, ev[2], 0);
    k_gather<<<gw, 256, 0, s1>>>(xpe, 256, 0, off0, ent0, dis0, a0h, a0l, N);
    cudaEventRecord(ev[3], s1);
    k_gather<<<gw, 256>>>(xpe, 256, 128, off1, ent1, dis1, a1h, a1l, N);
    cudaStreamWaitEvent(0, ev[3], 0);

    // ======== stage D (fused dual-source GEMM) ========
    {
        GArgs a = {};
        a.A[0][0] = a0h; a.A[0][1] = a0l;
        a.A[1][0] = a1h; a.A[1][1] = a1l;
        a.B[0][0] = wsh + 0 * 32768; a.B[0][1] = wsl + 0 * 32768;
        a.B[1][0] = wsh + 1 * 32768; a.B[1][1] = wsl + 1 * 32768;
        a.C = xm; a.M = N; a.NC = 128;
        k_gemm2<2, 64><<<dim3(2, mtiles), 256, SMEM_B2>>>(a);
    }

    // ======== stage E: two gathers in parallel ========
    cudaEventRecord(ev[4], 0);
    cudaStreamWaitEvent(s1, ev[4], 0);
    k_gather<<<gw, 256, 0, s1>>>(xm, 128, 0, off0, ent0, dis0, a0h, a0l, N);
    cudaEventRecord(ev[5], s1);
    k_gather<<<gw, 256>>>(xm, 128, 0, off1, ent1, dis1, a1h, a1l, N);
    cudaStreamWaitEvent(0, ev[5], 0);

    // ======== stage F (fused dual-source GEMM) ========
    {
        GArgs a = {};
        a.A[0][0] = a0h; a.A[0][1] = a0l;
        a.A[1][0] = a1h; a.A[1][1] = a1l;
        a.B[0][0] = wsh + 2 * 32768; a.B[0][1] = wsl + 2 * 32768;
        a.B[1][0] = wsh + 3 * 32768; a.B[1][1] = wsl + 3 * 32768;
        a.C = out; a.M = N; a.NC = 128;
        k_gemm2<2, 64><<<dim3(2, mtiles), 256, SMEM_B2>>>(a);
    }
}

// round 6
// speedup vs baseline: 2.2166x; 1.0374x over previous
#include <cuda_runtime.h>
#include <cuda_bf16.h>
#include <cuda_fp16.h>
#include <cstdint>

#define MAXN 50000
#define MAXE 800000

// ================= device scratch =================
struct __align__(16) EdgeRec { int row; float c1; float c2; float pad; };

__device__ __nv_bfloat16 g_xcat_h[MAXN * 256];
__device__ __nv_bfloat16 g_xcat_l[MAXN * 256];
__device__ __half        g_xpeh [MAXN * 256];
__device__ __nv_bfloat16 g_a0h[MAXN * 256];
__device__ __nv_bfloat16 g_a0l[MAXN * 256];
__device__ __nv_bfloat16 g_a1h[MAXN * 256];
__device__ __nv_bfloat16 g_a1l[MAXN * 256];
__device__ __half        g_xmh [MAXN * 128];
__device__ __nv_bfloat16 g_wbh[256 * 256];
__device__ __nv_bfloat16 g_wbl[256 * 256];
__device__ __nv_bfloat16 g_wsh[4][128 * 256];
__device__ __nv_bfloat16 g_wsl[4][128 * 256];
__device__ int   g_cnt0[MAXN];
__device__ int   g_cnt1[MAXN];
__device__ int   g_off0[MAXN + 1];
__device__ int   g_off1[MAXN + 1];
__device__ int   g_cur0[MAXN];
__device__ int   g_cur1[MAXN];
__device__ float g_dis0[MAXN];
__device__ float g_dis1[MAXN];
__device__ EdgeRec g_ent0[MAXE];
__device__ EdgeRec g_ent1[MAXE];

// ================= batched graph preprocessing (both graphs per launch) ======
__global__ void k_count2(const int* __restrict__ c0, const int* __restrict__ c1,
                         int* __restrict__ cnt0, int* __restrict__ cnt1, int e) {
    int i = blockIdx.x * blockDim.x + threadIdx.x;
    const int* col = blockIdx.y ? c1 : c0;
    int* cnt = blockIdx.y ? cnt1 : cnt0;
    if (i < e) atomicAdd(&cnt[col[i]], 1);
}
__global__ void k_dis2(const int* __restrict__ cnt0, const int* __restrict__ cnt1,
                       float* __restrict__ dis0, float* __restrict__ dis1, int n) {
    int i = blockIdx.x * blockDim.x + threadIdx.x;
    const int* cnt = blockIdx.y ? cnt1 : cnt0;
    float* dis = blockIdx.y ? dis1 : dis0;
    if (i < n) dis[i] = rsqrtf((float)(cnt[i] + 1));
}
__global__ void k_scan2(const int* __restrict__ cnt0, const int* __restrict__ cnt1,
                        int* __restrict__ off0, int* __restrict__ off1,
                        int* __restrict__ cur0, int* __restrict__ cur1, int n) {
    __shared__ int s[1024];
    const int* cnt = blockIdx.x ? cnt1 : cnt0;
    int* off = blockIdx.x ? off1 : off0;
    int* cur = blockIdx.x ? cur1 : cur0;
    int t = threadIdx.x;
    int chunk = (n + 1023) >> 10;
    int b = t * chunk;
    int e = min(b + chunk, n);
    int sum = 0;
    for (int i = b; i < e; i++) sum += cnt[i];
    s[t] = sum;
    __syncthreads();
    for (int o = 1; o < 1024; o <<= 1) {
        int v = (t >= o) ? s[t - o] : 0;
        __syncthreads();
        s[t] += v;
        __syncthreads();
    }
    int base = s[t] - sum;
    for (int i = b; i < e; i++) { off[i] = base; cur[i] = base; base += cnt[i]; }
    if (t == 1023) off[n] = s[1023];
}
__global__ void k_fill2(const int* __restrict__ ei0, const float* __restrict__ ea0,
                        const int* __restrict__ ei1, const float* __restrict__ ea1,
                        const float* __restrict__ dis0, const float* __restrict__ dis1,
                        int* __restrict__ cur0, int* __restrict__ cur1,
                        EdgeRec* __restrict__ ent0, EdgeRec* __restrict__ ent1, int e) {
    int i = blockIdx.x * blockDim.x + threadIdx.x;
    if (i >= e) return;
    const int* ei = blockIdx.y ? ei1 : ei0;
    const float* attr = blockIdx.y ? ea1 : ea0;
    const float* dis = blockIdx.y ? dis1 : dis0;
    int* cur = blockIdx.y ? cur1 : cur0;
    EdgeRec* ent = blockIdx.y ? ent1 : ent0;
    int r = ei[i], c = ei[e + i];
    float a = attr[i];
    EdgeRec rec;
    rec.row = r;
    rec.c1  = dis[r] * dis[c];
    rec.c2  = (a > 0.f) ? fminf(rsqrtf(a), 1.f) : 0.f;
    rec.pad = 0.f;
    int p = atomicAdd(&cur[c], 1);
    ent[p] = rec;
}

// ================= feature / weight prep =================
__device__ __forceinline__ void bsplit(float v, __nv_bfloat16& h, __nv_bfloat16& l) {
    h = __float2bfloat16(v);
    l = __float2bfloat16(v - __bfloat162float(h));
}

__global__ void k_xcat_split(const float* __restrict__ x, const float* __restrict__ pe,
                             __nv_bfloat16* __restrict__ hi, __nv_bfloat16* __restrict__ lo,
                             int n) {
    int stride = gridDim.x * blockDim.x;
    for (int idx = blockIdx.x * blockDim.x + threadIdx.x; idx < n * 256; idx += stride) {
        int i = idx >> 8, k = idx & 255;
        float v;
        if (k < 128)       v = x[(size_t)i * 128 + k];
        else if (k < 226)  v = pe[(size_t)i * 98 + (k - 128)];
        else               v = 0.f;
        __nv_bfloat16 h, l; bsplit(v, h, l);
        hi[idx] = h; lo[idx] = l;
    }
}

// WcatT[n][k]
__global__ void k_wtcat(const float* __restrict__ w1, const float* __restrict__ w2,
                        __nv_bfloat16* __restrict__ hi, __nv_bfloat16* __restrict__ lo) {
    int idx = blockIdx.x * blockDim.x + threadIdx.x;
    if (idx >= 256 * 256) return;
    int n = idx >> 8, k = idx & 255;
    float v = 0.f;
    if (k < 226) v = (n < 128) ? w1[k * 128 + n] : w2[k * 128 + (n - 128)];
    __nv_bfloat16 h, l; bsplit(v, h, l);
    hi[idx] = h; lo[idx] = l;
}
// WsT[n][k], stacked [lin1 ; lin2]^T, 4 layer pairs batched via blockIdx.y
__global__ void k_wtstk4(const float* __restrict__ w10, const float* __restrict__ w20,
                         const float* __restrict__ w11, const float* __restrict__ w21,
                         const float* __restrict__ w12, const float* __restrict__ w22,
                         const float* __restrict__ w13, const float* __restrict__ w23,
                         __nv_bfloat16* __restrict__ hi, __nv_bfloat16* __restrict__ lo) {
    int idx = blockIdx.x * blockDim.x + threadIdx.x;
    if (idx >= 128 * 256) return;
    int g = blockIdx.y;
    const float* w1 = (g == 0) ? w10 : (g == 1) ? w11 : (g == 2) ? w12 : w13;
    const float* w2 = (g == 0) ? w20 : (g == 1) ? w21 : (g == 2) ? w22 : w23;
    int n = idx >> 8, k = idx & 255;
    float v = (k < 128) ? w1[k * 128 + n] : w2[(k - 128) * 128 + n];
    __nv_bfloat16 h, l; bsplit(v, h, l);
    hi[g * 32768 + idx] = h; lo[g * 32768 + idx] = l;
}

// ================= CSR gather (fp16 source) -> bf16 hi/lo planes =============
__device__ __forceinline__ void split_store4(__nv_bfloat16* hi, __nv_bfloat16* lo, float4 v) {
    __nv_bfloat16 h, l;
    bsplit(v.x, h, l); hi[0] = h; lo[0] = l;
    bsplit(v.y, h, l); hi[1] = h; lo[1] = l;
    bsplit(v.z, h, l); hi[2] = h; lo[2] = l;
    bsplit(v.w, h, l); hi[3] = h; lo[3] = l;
}
__device__ __forceinline__ float4 ld_half4(const __half* p) {
    uint2 raw = *reinterpret_cast<const uint2*>(p);
    __half2 h0 = *reinterpret_cast<const __half2*>(&raw.x);
    __half2 h1 = *reinterpret_cast<const __half2*>(&raw.y);
    float2 f0 = __half22float2(h0), f1 = __half22float2(h1);
    return make_float4(f0.x, f0.y, f1.x, f1.y);
}

__global__ void k_gather(const __half* __restrict__ src, int ld, int off,
                         const int* __restrict__ offs, const EdgeRec* __restrict__ ent,
                         const float* __restrict__ dis,
                         __nv_bfloat16* __restrict__ agg_h, __nv_bfloat16* __restrict__ agg_l,
                         int n) {
    int warp = (blockIdx.x * blockDim.x + threadIdx.x) >> 5;
    int lane = threadIdx.x & 31;
    if (warp >= n) return;
    int b = offs[warp], e = offs[warp + 1];
    float4 a1 = make_float4(0.f, 0.f, 0.f, 0.f);
    float4 a2 = make_float4(0.f, 0.f, 0.f, 0.f);
    int i = b;
    for (; i + 2 <= e; i += 2) {
        EdgeRec r0 = ent[i];
        EdgeRec r1 = ent[i + 1];
        const float4 v0 = ld_half4(src + (size_t)r0.row * ld + off + lane * 4);
        const float4 v1 = ld_half4(src + (size_t)r1.row * ld + off + lane * 4);
        a1.x += r0.c1 * v0.x; a1.y += r0.c1 * v0.y; a1.z += r0.c1 * v0.z; a1.w += r0.c1 * v0.w;
        a2.x += r0.c2 * v0.x; a2.y += r0.c2 * v0.y; a2.z += r0.c2 * v0.z; a2.w += r0.c2 * v0.w;
        a1.x += r1.c1 * v1.x; a1.y += r1.c1 * v1.y; a1.z += r1.c1 * v1.z; a1.w += r1.c1 * v1.w;
        a2.x += r1.c2 * v1.x; a2.y += r1.c2 * v1.y; a2.z += r1.c2 * v1.z; a2.w += r1.c2 * v1.w;
    }
    if (i < e) {
        EdgeRec rec = ent[i];
        const float4 v = ld_half4(src + (size_t)rec.row * ld + off + lane * 4);
        a1.x += rec.c1 * v.x; a1.y += rec.c1 * v.y; a1.z += rec.c1 * v.z; a1.w += rec.c1 * v.w;
        a2.x += rec.c2 * v.x; a2.y += rec.c2 * v.y; a2.z += rec.c2 * v.z; a2.w += rec.c2 * v.w;
    }
    float d = dis[warp];
    float sc = d * d;
    const float4 v = ld_half4(src + (size_t)warp * ld + off + lane * 4);
    a1.x += sc * v.x; a1.y += sc * v.y; a1.z += sc * v.z; a1.w += sc * v.w;
    a2.x += v.x;      a2.y += v.y;      a2.z += v.z;      a2.w += v.w;
    size_t base = (size_t)warp * 256 + lane * 4;
    split_store4(agg_h + base,       agg_l + base,       a1);
    split_store4(agg_h + base + 128, agg_l + base + 128, a2);
}

// ================= HMMA GEMM, kc-restructured =========================
__device__ __forceinline__ uint32_t smem_u32(const void* p) {
    uint32_t a;
    asm("{ .reg .u64 t; cvta.to.shared.u64 t, %1; cvt.u32.u64 %0, t; }" : "=r"(a) : "l"(p));
    return a;
}
__device__ __forceinline__ void cp16(uint32_t dst, const void* src) {
    asm volatile("cp.async.cg.shared.global [%0], [%1], 16;" :: "r"(dst), "l"(src));
}
__device__ __forceinline__ void cp_commit() { asm volatile("cp.async.commit_group;"); }
template <int W> __device__ __forceinline__ void cp_wait() {
    asm volatile("cp.async.wait_group %0;" :: "n"(W));
}
__device__ __forceinline__ void ldm_x4(uint32_t* r, uint32_t addr) {
    asm volatile("ldmatrix.sync.aligned.m8n8.x4.shared.b16 {%0,%1,%2,%3}, [%4];"
                 : "=r"(r[0]), "=r"(r[1]), "=r"(r[2]), "=r"(r[3]) : "r"(addr));
}
__device__ __forceinline__ void mma16816(float* c, const uint32_t* a, uint32_t b0, uint32_t b1) {
    asm volatile(
        "mma.sync.aligned.m16n8k16.row.col.f32.bf16.bf16.f32 "
        "{%0,%1,%2,%3}, {%4,%5,%6,%7}, {%8,%9}, {%0,%1,%2,%3};"
        : "+f"(c[0]), "+f"(c[1]), "+f"(c[2]), "+f"(c[3])
        : "r"(a[0]), "r"(a[1]), "r"(a[2]), "r"(a[3]), "r"(b0), "r"(b1));
}

struct GArgs {
    const __nv_bfloat16* A[2][2];   // [src][hi/lo], [M,256]
    const __nv_bfloat16* B[2][2];   // [src][hi/lo], [*,256] (transposed weights)
    void* C;
    int M, NC;
};

// NSRC=1: raw value; NSRC=2: 0.5*relu(acc0)+0.5*relu(acc1). OUTH: fp16 output.
template <int NSRC, int NT, bool OUTH>
__global__ void __launch_bounds__(256) k_gemm2(GArgs args) {
    constexpr int APL  = 16384;
    constexpr int ABUF = NSRC * 2 * APL;
    constexpr int BPL  = NT * 128;
    constexpr int BBUF = NSRC * 2 * BPL;
    constexpr int BUF  = ABUF + BBUF;
    constexpr int NI   = NT / 16;

    extern __shared__ char sm[];
    const int tid  = threadIdx.x;
    const int lane = tid & 31;
    const int wid  = tid >> 5;
    const int wm   = wid & 3;
    const int wn   = wid >> 2;
    const int m0   = blockIdx.y * 128;
    const int n0   = blockIdx.x * NT;
    const uint32_t sbase = smem_u32(sm);

    const int lr = tid >> 3, lq = tid & 7;

    auto issue_load = [&](int kc, int buf) {
        uint32_t sb = sbase + buf * BUF;
#pragma unroll
        for (int s = 0; s < NSRC; s++)
#pragma unroll
            for (int p = 0; p < 2; p++) {
                const __nv_bfloat16* A = args.A[s][p];
                uint32_t sa = sb + (s * 2 + p) * APL;
#pragma unroll
                for (int j = 0; j < 4; j++) {
                    int r = lr + j * 32;
                    int gr = m0 + r; if (gr > args.M - 1) gr = args.M - 1;
                    cp16(sa + r * 128 + ((lq ^ (r & 7)) << 4),
                         A + (size_t)gr * 256 + kc * 64 + lq * 8);
                }
            }
#pragma unroll
        for (int s = 0; s < NSRC; s++)
#pragma unroll
            for (int p = 0; p < 2; p++) {
                const __nv_bfloat16* B = args.B[s][p];
                uint32_t sbB = sb + ABUF + (s * 2 + p) * BPL;
#pragma unroll
                for (int j = 0; j < NT / 32; j++) {
                    int r = lr + j * 32;
                    cp16(sbB + r * 128 + ((lq ^ (r & 7)) << 4),
                         B + (size_t)(n0 + r) * 256 + kc * 64 + lq * 8);
                }
            }
        cp_commit();
    };

    float acc[NSRC][2][NI][4];
#pragma unroll
    for (int s = 0; s < NSRC; s++)
#pragma unroll
        for (int mi = 0; mi < 2; mi++)
#pragma unroll
            for (int ni = 0; ni < NI; ni++)
#pragma unroll
                for (int k = 0; k < 4; k++) acc[s][mi][ni][k] = 0.f;

    issue_load(0, 0);

    for (int kc = 0; kc < 4; kc++) {
        if (kc < 3) { issue_load(kc + 1, (kc + 1) & 1); cp_wait<1>(); }
        else        { cp_wait<0>(); }
        __syncthreads();

        uint32_t sb = sbase + (kc & 1) * BUF;

#pragma unroll
        for (int ks = 0; ks < 4; ks++) {
#pragma unroll
            for (int s = 0; s < NSRC; s++) {
                uint32_t afH[2][4], afL[2][4];
#pragma unroll
                for (int mi = 0; mi < 2; mi++) {
                    int row = wm * 32 + mi * 16 + (lane & 15);
                    int c16 = (2 * ks + (lane >> 4)) ^ (row & 7);
                    ldm_x4(afH[mi], sb + (s * 2 + 0) * APL + row * 128 + (c16 << 4));
                    ldm_x4(afL[mi], sb + (s * 2 + 1) * APL + row * 128 + (c16 << 4));
                }
                uint32_t bfH[NI][2], bfL[NI][2];
#pragma unroll
                for (int np = 0; np < NT / 32; np++) {
                    int nrow = wn * (NT / 2) + np * 16 + ((lane >> 4) << 3) + (lane & 7);
                    int c16 = (2 * ks + ((lane >> 3) & 1)) ^ (nrow & 7);
                    uint32_t t4[4];
                    ldm_x4(t4, sb + ABUF + (s * 2 + 0) * BPL + nrow * 128 + (c16 << 4));
                    bfH[np * 2][0] = t4[0]; bfH[np * 2][1] = t4[1];
                    bfH[np * 2 + 1][0] = t4[2]; bfH[np * 2 + 1][1] = t4[3];
                    ldm_x4(t4, sb + ABUF + (s * 2 + 1) * BPL + nrow * 128 + (c16 << 4));
                    bfL[np * 2][0] = t4[0]; bfL[np * 2][1] = t4[1];
                    bfL[np * 2 + 1][0] = t4[2]; bfL[np * 2 + 1][1] = t4[3];
                }
#pragma unroll
                for (int mi = 0; mi < 2; mi++)
#pragma unroll
                    for (int ni = 0; ni < NI; ni++) {
                        mma16816(acc[s][mi][ni], afH[mi], bfH[ni][0], bfH[ni][1]);
                        mma16816(acc[s][mi][ni], afL[mi], bfH[ni][0], bfH[ni][1]);
                        mma16816(acc[s][mi][ni], afH[mi], bfL[ni][0], bfL[ni][1]);
                    }
            }
        }
        __syncthreads();
    }

#pragma unroll
    for (int mi = 0; mi < 2; mi++) {
#pragma unroll
        for (int half = 0; half < 2; half++) {
            int r = m0 + wm * 32 + mi * 16 + (lane >> 2) + half * 8;
            if (r >= args.M) continue;
            size_t cbase = (size_t)r * args.NC + n0 + wn * (NT / 2) + (lane & 3) * 2;
#pragma unroll
            for (int ni = 0; ni < NI; ni++) {
                float v0, v1;
                if (NSRC == 1) {
                    v0 = acc[0][mi][ni][half * 2];
                    v1 = acc[0][mi][ni][half * 2 + 1];
                } else {
                    v0 = 0.5f * (fmaxf(acc[0][mi][ni][half * 2], 0.f) +
                                 fmaxf(acc[NSRC - 1][mi][ni][half * 2], 0.f));
                    v1 = 0.5f * (fmaxf(acc[0][mi][ni][half * 2 + 1], 0.f) +
                                 fmaxf(acc[NSRC - 1][mi][ni][half * 2 + 1], 0.f));
                }
                if (OUTH) {
                    __half2 hv = __floats2half2_rn(v0, v1);
                    *reinterpret_cast<__half2*>((__half*)args.C + cbase + ni * 8) = hv;
                } else {
                    float* cp = (float*)args.C + cbase + ni * 8;
                    cp[0] = v0; cp[1] = v1;
                }
            }
        }
    }
}

#define SMEM_B1 (2 * (2 * 16384 + 2 * 128 * 128))          // 131072
#define SMEM_B2 (2 * (4 * 16384 + 4 * 64 * 128))           // 196608

// ================= host orchestration =================
extern "C" void kernel_launch(void* const* d_in, const int* in_sizes, int n_in,
                              void* d_out, int out_size) {
    const float* x   = (const float*)d_in[0];
    const float* pe  = (const float*)d_in[1];
    const int*   ei0 = (const int*)d_in[2];
    const float* ea0 = (const float*)d_in[3];
    const int*   ei1 = (const int*)d_in[4];
    const float* ea1 = (const float*)d_in[5];
    const float* nl1 = (const float*)d_in[6];
    const float* nl2 = (const float*)d_in[7];
    const float* lw[8] = { (const float*)d_in[8],  (const float*)d_in[9],
                           (const float*)d_in[10], (const float*)d_in[11],
                           (const float*)d_in[12], (const float*)d_in[13],
                           (const float*)d_in[14], (const float*)d_in[15] };
    float* out = (float*)d_out;

    int N = in_sizes[0] / 128;
    int E = in_sizes[3];

    __nv_bfloat16 *xch, *xcl, *a0h, *a0l, *a1h, *a1l, *wbh, *wbl, *wsh, *wsl;
    __half *xpeh, *xmh;
    float *dis0, *dis1;
    int *cnt0, *cnt1, *off0, *off1, *cur0, *cur1;
    EdgeRec *ent0, *ent1;
    cudaGetSymbolAddress((void**)&xch, g_xcat_h);
    cudaGetSymbolAddress((void**)&xcl, g_xcat_l);
    cudaGetSymbolAddress((void**)&xpeh, g_xpeh);
    cudaGetSymbolAddress((void**)&a0h, g_a0h);
    cudaGetSymbolAddress((void**)&a0l, g_a0l);
    cudaGetSymbolAddress((void**)&a1h, g_a1h);
    cudaGetSymbolAddress((void**)&a1l, g_a1l);
    cudaGetSymbolAddress((void**)&xmh, g_xmh);
    cudaGetSymbolAddress((void**)&wbh, g_wbh);
    cudaGetSymbolAddress((void**)&wbl, g_wbl);
    cudaGetSymbolAddress((void**)&wsh, g_wsh);
    cudaGetSymbolAddress((void**)&wsl, g_wsl);
    cudaGetSymbolAddress((void**)&cnt0, g_cnt0);
    cudaGetSymbolAddress((void**)&cnt1, g_cnt1);
    cudaGetSymbolAddress((void**)&off0, g_off0);
    cudaGetSymbolAddress((void**)&off1, g_off1);
    cudaGetSymbolAddress((void**)&cur0, g_cur0);
    cudaGetSymbolAddress((void**)&cur1, g_cur1);
    cudaGetSymbolAddress((void**)&dis0, g_dis0);
    cudaGetSymbolAddress((void**)&dis1, g_dis1);
    cudaGetSymbolAddress((void**)&ent0, g_ent0);
    cudaGetSymbolAddress((void**)&ent1, g_ent1);

    cudaFuncSetAttribute((const void*)k_gemm2<1, 128, true>,
                         cudaFuncAttributeMaxDynamicSharedMemorySize, SMEM_B1);
    cudaFuncSetAttribute((const void*)k_gemm2<2, 64, true>,
                         cudaFuncAttributeMaxDynamicSharedMemorySize, SMEM_B2);
    cudaFuncSetAttribute((const void*)k_gemm2<2, 64, false>,
                         cudaFuncAttributeMaxDynamicSharedMemorySize, SMEM_B2);

    static cudaStream_t s1 = nullptr;
    static cudaEvent_t ev[6];
    if (s1 == nullptr) {
        cudaStreamCreateWithFlags(&s1, cudaStreamNonBlocking);
        for (int i = 0; i < 6; i++) cudaEventCreateWithFlags(&ev[i], cudaEventDisableTiming);
    }

    int eb = (E + 255) / 256;
    int nb = (N + 255) / 256;
    int mtiles = (N + 127) / 128;
    int gw = (N + 7) / 8;

    // ======== fork: preprocessing on s1, prep + stage B on main ========
    cudaEventRecord(ev[0], 0);
    cudaStreamWaitEvent(s1, ev[0], 0);

    cudaMemsetAsync(cnt0, 0, N * sizeof(int), s1);
    cudaMemsetAsync(cnt1, 0, N * sizeof(int), s1);
    k_count2<<<dim3(eb, 2), 256, 0, s1>>>(ei0 + E, ei1 + E, cnt0, cnt1, E);
    k_dis2<<<dim3(nb, 2), 256, 0, s1>>>(cnt0, cnt1, dis0, dis1, N);
    k_scan2<<<2, 1024, 0, s1>>>(cnt0, cnt1, off0, off1, cur0, cur1, N);
    k_fill2<<<dim3(eb, 2), 256, 0, s1>>>(ei0, ea0, ei1, ea1, dis0, dis1,
                                         cur0, cur1, ent0, ent1, E);
    cudaEventRecord(ev[1], s1);

    // main: feature/weight prep + stage B (fp16 output)
    k_xcat_split<<<2048, 256>>>(x, pe, xch, xcl, N);
    k_wtcat<<<256, 256>>>(nl1, nl2, wbh, wbl);
    k_wtstk4<<<dim3(128, 4), 256>>>(lw[0], lw[1], lw[2], lw[3],
                                    lw[4], lw[5], lw[6], lw[7], wsh, wsl);
    {
        GArgs a = {};
        a.A[0][0] = xch; a.A[0][1] = xcl;
        a.B[0][0] = wbh; a.B[0][1] = wbl;
        a.C = xpeh; a.M = N; a.NC = 256;
        k_gemm2<1, 128, true><<<dim3(2, mtiles), 256, SMEM_B1>>>(a);
    }
    cudaStreamWaitEvent(0, ev[1], 0);   // join preprocessing

    // ======== stage C: two gathers in parallel (fp16 reads) ========
    cudaEventRecord(ev[2], 0);
    cudaStreamWaitEvent(s1, ev[2], 0);
    k_gather<<<gw, 256, 0, s1>>>(xpeh, 256, 0, off0, ent0, dis0, a0h, a0l, N);
    cudaEventRecord(ev[3], s1);
    k_gather<<<gw, 256>>>(xpeh, 256, 128, off1, ent1, dis1, a1h, a1l, N);
    cudaStreamWaitEvent(0, ev[3], 0);

    // ======== stage D (fused dual-source GEMM, fp16 xm output) ========
    {
        GArgs a = {};
        a.A[0][0] = a0h; a.A[0][1] = a0l;
        a.A[1][0] = a1h; a.A[1][1] = a1l;
        a.B[0][0] = wsh + 0 * 32768; a.B[0][1] = wsl + 0 * 32768;
        a.B[1][0] = wsh + 1 * 32768; a.B[1][1] = wsl + 1 * 32768;
        a.C = xmh; a.M = N; a.NC = 128;
        k_gemm2<2, 64, true><<<dim3(2, mtiles), 256, SMEM_B2>>>(a);
    }

    // ======== stage E: two gathers in parallel (fp16 reads) ========
    cudaEventRecord(ev[4], 0);
    cudaStreamWaitEvent(s1, ev[4], 0);
    k_gather<<<gw, 256, 0, s1>>>(xmh, 128, 0, off0, ent0, dis0, a0h, a0l, N);
    cudaEventRecord(ev[5], s1);
    k_gather<<<gw, 256>>>(xmh, 128, 0, off1, ent1, dis1, a1h, a1l, N);
    cudaStreamWaitEvent(0, ev[5], 0);

    // ======== stage F (fused dual-source GEMM, fp32 out) ========
    {
        GArgs a = {};
        a.A[0][0] = a0h; a.A[0][1] = a0l;
        a.A[1][0] = a1h; a.A[1][1] = a1l;
        a.B[0][0] = wsh + 2 * 32768; a.B[0][1] = wsl + 2 * 32768;
        a.B[1][0] = wsh + 3 * 32768; a.B[1][1] = wsl + 3 * 32768;
        a.C = out; a.M = N; a.NC = 128;
        k_gemm2<2, 64, false><<<dim3(2, mtiles), 256, SMEM_B2>>>(a);
    }
}

// round 7
// speedup vs baseline: 2.3560x; 1.0629x over previous
#include <cuda_runtime.h>
#include <cuda_fp16.h>
#include <cstdint>

#define MAXN 50000
#define MAXE 800000

// ================= device scratch =================
struct __align__(16) EdgeRec { int row; float c1; float c2; float pad; };

__device__ __half g_xcat_h[MAXN * 256];
__device__ __half g_xcat_l[MAXN * 256];
__device__ __half g_xpeh [MAXN * 256];
__device__ __half g_a0h[MAXN * 256];
__device__ __half g_a0l[MAXN * 256];
__device__ __half g_a1h[MAXN * 256];
__device__ __half g_a1l[MAXN * 256];
__device__ __half g_xmh [MAXN * 128];
__device__ __half g_wb [256 * 256];
__device__ __half g_ws [4][128 * 256];
__device__ int   g_cnt0[MAXN];
__device__ int   g_cnt1[MAXN];
__device__ int   g_off0[MAXN + 1];
__device__ int   g_off1[MAXN + 1];
__device__ int   g_cur0[MAXN];
__device__ int   g_cur1[MAXN];
__device__ float g_dis0[MAXN];
__device__ float g_dis1[MAXN];
__device__ EdgeRec g_ent0[MAXE];
__device__ EdgeRec g_ent1[MAXE];

// ================= batched graph preprocessing =================
__global__ void k_count2(const int* __restrict__ c0, const int* __restrict__ c1,
                         int* __restrict__ cnt0, int* __restrict__ cnt1, int e) {
    int i = blockIdx.x * blockDim.x + threadIdx.x;
    const int* col = blockIdx.y ? c1 : c0;
    int* cnt = blockIdx.y ? cnt1 : cnt0;
    if (i < e) atomicAdd(&cnt[col[i]], 1);
}
__global__ void k_dis2(const int* __restrict__ cnt0, const int* __restrict__ cnt1,
                       float* __restrict__ dis0, float* __restrict__ dis1, int n) {
    int i = blockIdx.x * blockDim.x + threadIdx.x;
    const int* cnt = blockIdx.y ? cnt1 : cnt0;
    float* dis = blockIdx.y ? dis1 : dis0;
    if (i < n) dis[i] = rsqrtf((float)(cnt[i] + 1));
}
__global__ void k_scan2(const int* __restrict__ cnt0, const int* __restrict__ cnt1,
                        int* __restrict__ off0, int* __restrict__ off1,
                        int* __restrict__ cur0, int* __restrict__ cur1, int n) {
    __shared__ int s[1024];
    const int* cnt = blockIdx.x ? cnt1 : cnt0;
    int* off = blockIdx.x ? off1 : off0;
    int* cur = blockIdx.x ? cur1 : cur0;
    int t = threadIdx.x;
    int chunk = (n + 1023) >> 10;
    int b = t * chunk;
    int e = min(b + chunk, n);
    int sum = 0;
    for (int i = b; i < e; i++) sum += cnt[i];
    s[t] = sum;
    __syncthreads();
    for (int o = 1; o < 1024; o <<= 1) {
        int v = (t >= o) ? s[t - o] : 0;
        __syncthreads();
        s[t] += v;
        __syncthreads();
    }
    int base = s[t] - sum;
    for (int i = b; i < e; i++) { off[i] = base; cur[i] = base; base += cnt[i]; }
    if (t == 1023) off[n] = s[1023];
}
__global__ void k_fill2(const int* __restrict__ ei0, const float* __restrict__ ea0,
                        const int* __restrict__ ei1, const float* __restrict__ ea1,
                        const float* __restrict__ dis0, const float* __restrict__ dis1,
                        int* __restrict__ cur0, int* __restrict__ cur1,
                        EdgeRec* __restrict__ ent0, EdgeRec* __restrict__ ent1, int e) {
    int i = blockIdx.x * blockDim.x + threadIdx.x;
    if (i >= e) return;
    const int* ei = blockIdx.y ? ei1 : ei0;
    const float* attr = blockIdx.y ? ea1 : ea0;
    const float* dis = blockIdx.y ? dis1 : dis0;
    int* cur = blockIdx.y ? cur1 : cur0;
    EdgeRec* ent = blockIdx.y ? ent1 : ent0;
    int r = ei[i], c = ei[e + i];
    float a = attr[i];
    EdgeRec rec;
    rec.row = r;
    rec.c1  = dis[r] * dis[c];
    rec.c2  = (a > 0.f) ? fminf(rsqrtf(a), 1.f) : 0.f;
    rec.pad = 0.f;
    int p = atomicAdd(&cur[c], 1);
    ent[p] = rec;
}

// ================= feature / weight prep (fp16 hi/lo) =================
__device__ __forceinline__ void hsplit(float v, __half& h, __half& l) {
    h = __float2half_rn(v);
    l = __float2half_rn(v - __half2float(h));
}

__global__ void k_xcat_split(const float* __restrict__ x, const float* __restrict__ pe,
                             __half* __restrict__ hi, __half* __restrict__ lo, int n) {
    int stride = gridDim.x * blockDim.x;
    for (int idx = blockIdx.x * blockDim.x + threadIdx.x; idx < n * 256; idx += stride) {
        int i = idx >> 8, k = idx & 255;
        float v;
        if (k < 128)       v = x[(size_t)i * 128 + k];
        else if (k < 226)  v = pe[(size_t)i * 98 + (k - 128)];
        else               v = 0.f;
        __half h, l; hsplit(v, h, l);
        hi[idx] = h; lo[idx] = l;
    }
}

// WcatT[n][k] single fp16 plane
__global__ void k_wtcat(const float* __restrict__ w1, const float* __restrict__ w2,
                        __half* __restrict__ w) {
    int idx = blockIdx.x * blockDim.x + threadIdx.x;
    if (idx >= 256 * 256) return;
    int n = idx >> 8, k = idx & 255;
    float v = 0.f;
    if (k < 226) v = (n < 128) ? w1[k * 128 + n] : w2[k * 128 + (n - 128)];
    w[idx] = __float2half_rn(v);
}
// WsT[n][k], stacked [lin1 ; lin2]^T, 4 layer pairs, single fp16 plane
__global__ void k_wtstk4(const float* __restrict__ w10, const float* __restrict__ w20,
                         const float* __restrict__ w11, const float* __restrict__ w21,
                         const float* __restrict__ w12, const float* __restrict__ w22,
                         const float* __restrict__ w13, const float* __restrict__ w23,
                         __half* __restrict__ w) {
    int idx = blockIdx.x * blockDim.x + threadIdx.x;
    if (idx >= 128 * 256) return;
    int g = blockIdx.y;
    const float* w1 = (g == 0) ? w10 : (g == 1) ? w11 : (g == 2) ? w12 : w13;
    const float* w2 = (g == 0) ? w20 : (g == 1) ? w21 : (g == 2) ? w22 : w23;
    int n = idx >> 8, k = idx & 255;
    float v = (k < 128) ? w1[k * 128 + n] : w2[(k - 128) * 128 + n];
    w[g * 32768 + idx] = __float2half_rn(v);
}

// ================= CSR gather (fp16 source) -> fp16 hi/lo planes =============
__device__ __forceinline__ void hsplit_store4(__half* hi, __half* lo, float4 v) {
    __half h, l;
    hsplit(v.x, h, l); hi[0] = h; lo[0] = l;
    hsplit(v.y, h, l); hi[1] = h; lo[1] = l;
    hsplit(v.z, h, l); hi[2] = h; lo[2] = l;
    hsplit(v.w, h, l); hi[3] = h; lo[3] = l;
}
__device__ __forceinline__ float4 ld_half4(const __half* p) {
    uint2 raw = *reinterpret_cast<const uint2*>(p);
    __half2 h0 = *reinterpret_cast<const __half2*>(&raw.x);
    __half2 h1 = *reinterpret_cast<const __half2*>(&raw.y);
    float2 f0 = __half22float2(h0), f1 = __half22float2(h1);
    return make_float4(f0.x, f0.y, f1.x, f1.y);
}

__global__ void k_gather(const __half* __restrict__ src, int ld, int off,
                         const int* __restrict__ offs, const EdgeRec* __restrict__ ent,
                         const float* __restrict__ dis,
                         __half* __restrict__ agg_h, __half* __restrict__ agg_l, int n) {
    int warp = (blockIdx.x * blockDim.x + threadIdx.x) >> 5;
    int lane = threadIdx.x & 31;
    if (warp >= n) return;
    int b = offs[warp], e = offs[warp + 1];
    float4 a1 = make_float4(0.f, 0.f, 0.f, 0.f);
    float4 a2 = make_float4(0.f, 0.f, 0.f, 0.f);
    int i = b;
    for (; i + 2 <= e; i += 2) {
        EdgeRec r0 = ent[i];
        EdgeRec r1 = ent[i + 1];
        const float4 v0 = ld_half4(src + (size_t)r0.row * ld + off + lane * 4);
        const float4 v1 = ld_half4(src + (size_t)r1.row * ld + off + lane * 4);
        a1.x += r0.c1 * v0.x; a1.y += r0.c1 * v0.y; a1.z += r0.c1 * v0.z; a1.w += r0.c1 * v0.w;
        a2.x += r0.c2 * v0.x; a2.y += r0.c2 * v0.y; a2.z += r0.c2 * v0.z; a2.w += r0.c2 * v0.w;
        a1.x += r1.c1 * v1.x; a1.y += r1.c1 * v1.y; a1.z += r1.c1 * v1.z; a1.w += r1.c1 * v1.w;
        a2.x += r1.c2 * v1.x; a2.y += r1.c2 * v1.y; a2.z += r1.c2 * v1.z; a2.w += r1.c2 * v1.w;
    }
    if (i < e) {
        EdgeRec rec = ent[i];
        const float4 v = ld_half4(src + (size_t)rec.row * ld + off + lane * 4);
        a1.x += rec.c1 * v.x; a1.y += rec.c1 * v.y; a1.z += rec.c1 * v.z; a1.w += rec.c1 * v.w;
        a2.x += rec.c2 * v.x; a2.y += rec.c2 * v.y; a2.z += rec.c2 * v.z; a2.w += rec.c2 * v.w;
    }
    float d = dis[warp];
    float sc = d * d;
    const float4 v = ld_half4(src + (size_t)warp * ld + off + lane * 4);
    a1.x += sc * v.x; a1.y += sc * v.y; a1.z += sc * v.z; a1.w += sc * v.w;
    a2.x += v.x;      a2.y += v.y;      a2.z += v.z;      a2.w += v.w;
    size_t base = (size_t)warp * 256 + lane * 4;
    hsplit_store4(agg_h + base,       agg_l + base,       a1);
    hsplit_store4(agg_h + base + 128, agg_l + base + 128, a2);
}

// ================= HMMA fp16 2-term GEMM =========================
// C = f( sum_s (A_s_h + A_s_l)[M,256] @ B_s[NT,256]^T )
__device__ __forceinline__ uint32_t smem_u32(const void* p) {
    uint32_t a;
    asm("{ .reg .u64 t; cvta.to.shared.u64 t, %1; cvt.u32.u64 %0, t; }" : "=r"(a) : "l"(p));
    return a;
}
__device__ __forceinline__ void cp16(uint32_t dst, const void* src) {
    asm volatile("cp.async.cg.shared.global [%0], [%1], 16;" :: "r"(dst), "l"(src));
}
__device__ __forceinline__ void cp_commit() { asm volatile("cp.async.commit_group;"); }
template <int W> __device__ __forceinline__ void cp_wait() {
    asm volatile("cp.async.wait_group %0;" :: "n"(W));
}
__device__ __forceinline__ void ldm_x4(uint32_t* r, uint32_t addr) {
    asm volatile("ldmatrix.sync.aligned.m8n8.x4.shared.b16 {%0,%1,%2,%3}, [%4];"
                 : "=r"(r[0]), "=r"(r[1]), "=r"(r[2]), "=r"(r[3]) : "r"(addr));
}
__device__ __forceinline__ void mma16816(float* c, const uint32_t* a, uint32_t b0, uint32_t b1) {
    asm volatile(
        "mma.sync.aligned.m16n8k16.row.col.f32.f16.f16.f32 "
        "{%0,%1,%2,%3}, {%4,%5,%6,%7}, {%8,%9}, {%0,%1,%2,%3};"
        : "+f"(c[0]), "+f"(c[1]), "+f"(c[2]), "+f"(c[3])
        : "r"(a[0]), "r"(a[1]), "r"(a[2]), "r"(a[3]), "r"(b0), "r"(b1));
}

struct GArgs {
    const __half* A[2][2];   // [src][hi/lo], [M,256]
    const __half* B[2];      // [src], single fp16 plane, [*,256] transposed
    void* C;
    int M, NC;
};

template <int NSRC, int NT, bool OUTH>
__global__ void __launch_bounds__(256) k_gemm2(GArgs args) {
    constexpr int APL  = 16384;          // 128 rows x 128B per kc chunk
    constexpr int ABUF = NSRC * 2 * APL;
    constexpr int BPL  = NT * 128;
    constexpr int BBUF = NSRC * BPL;
    constexpr int BUF  = ABUF + BBUF;
    constexpr int NI   = NT / 16;

    extern __shared__ char sm[];
    const int tid  = threadIdx.x;
    const int lane = tid & 31;
    const int wid  = tid >> 5;
    const int wm   = wid & 3;
    const int wn   = wid >> 2;
    const int m0   = blockIdx.y * 128;
    const int n0   = blockIdx.x * NT;
    const uint32_t sbase = smem_u32(sm);

    const int lr = tid >> 3, lq = tid & 7;

    auto issue_load = [&](int kc, int buf) {
        uint32_t sb = sbase + buf * BUF;
#pragma unroll
        for (int s = 0; s < NSRC; s++)
#pragma unroll
            for (int p = 0; p < 2; p++) {
                const __half* A = args.A[s][p];
                uint32_t sa = sb + (s * 2 + p) * APL;
#pragma unroll
                for (int j = 0; j < 4; j++) {
                    int r = lr + j * 32;
                    int gr = m0 + r; if (gr > args.M - 1) gr = args.M - 1;
                    cp16(sa + r * 128 + ((lq ^ (r & 7)) << 4),
                         A + (size_t)gr * 256 + kc * 64 + lq * 8);
                }
            }
#pragma unroll
        for (int s = 0; s < NSRC; s++) {
            const __half* B = args.B[s];
            uint32_t sbB = sb + ABUF + s * BPL;
#pragma unroll
            for (int j = 0; j < NT / 32; j++) {
                int r = lr + j * 32;
                cp16(sbB + r * 128 + ((lq ^ (r & 7)) << 4),
                     B + (size_t)(n0 + r) * 256 + kc * 64 + lq * 8);
            }
        }
        cp_commit();
    };

    float acc[NSRC][2][NI][4];
#pragma unroll
    for (int s = 0; s < NSRC; s++)
#pragma unroll
        for (int mi = 0; mi < 2; mi++)
#pragma unroll
            for (int ni = 0; ni < NI; ni++)
#pragma unroll
                for (int k = 0; k < 4; k++) acc[s][mi][ni][k] = 0.f;

    issue_load(0, 0);

    for (int kc = 0; kc < 4; kc++) {
        if (kc < 3) { issue_load(kc + 1, (kc + 1) & 1); cp_wait<1>(); }
        else        { cp_wait<0>(); }
        __syncthreads();

        uint32_t sb = sbase + (kc & 1) * BUF;

#pragma unroll
        for (int ks = 0; ks < 4; ks++) {
#pragma unroll
            for (int s = 0; s < NSRC; s++) {
                uint32_t afH[2][4], afL[2][4];
#pragma unroll
                for (int mi = 0; mi < 2; mi++) {
                    int row = wm * 32 + mi * 16 + (lane & 15);
                    int c16 = (2 * ks + (lane >> 4)) ^ (row & 7);
                    ldm_x4(afH[mi], sb + (s * 2 + 0) * APL + row * 128 + (c16 << 4));
                    ldm_x4(afL[mi], sb + (s * 2 + 1) * APL + row * 128 + (c16 << 4));
                }
                uint32_t bf[NI][2];
#pragma unroll
                for (int np = 0; np < NT / 32; np++) {
                    int nrow = wn * (NT / 2) + np * 16 + ((lane >> 4) << 3) + (lane & 7);
                    int c16 = (2 * ks + ((lane >> 3) & 1)) ^ (nrow & 7);
                    uint32_t t4[4];
                    ldm_x4(t4, sb + ABUF + s * BPL + nrow * 128 + (c16 << 4));
                    bf[np * 2][0] = t4[0]; bf[np * 2][1] = t4[1];
                    bf[np * 2 + 1][0] = t4[2]; bf[np * 2 + 1][1] = t4[3];
                }
#pragma unroll
                for (int mi = 0; mi < 2; mi++)
#pragma unroll
                    for (int ni = 0; ni < NI; ni++) {
                        mma16816(acc[s][mi][ni], afH[mi], bf[ni][0], bf[ni][1]);
                        mma16816(acc[s][mi][ni], afL[mi], bf[ni][0], bf[ni][1]);
                    }
            }
        }
        __syncthreads();
    }

#pragma unroll
    for (int mi = 0; mi < 2; mi++) {
#pragma unroll
        for (int half = 0; half < 2; half++) {
            int r = m0 + wm * 32 + mi * 16 + (lane >> 2) + half * 8;
            if (r >= args.M) continue;
            size_t cbase = (size_t)r * args.NC + n0 + wn * (NT / 2) + (lane & 3) * 2;
#pragma unroll
            for (int ni = 0; ni < NI; ni++) {
                float v0, v1;
                if (NSRC == 1) {
                    v0 = acc[0][mi][ni][half * 2];
                    v1 = acc[0][mi][ni][half * 2 + 1];
                } else {
                    v0 = 0.5f * (fmaxf(acc[0][mi][ni][half * 2], 0.f) +
                                 fmaxf(acc[NSRC - 1][mi][ni][half * 2], 0.f));
                    v1 = 0.5f * (fmaxf(acc[0][mi][ni][half * 2 + 1], 0.f) +
                                 fmaxf(acc[NSRC - 1][mi][ni][half * 2 + 1], 0.f));
                }
                if (OUTH) {
                    __half2 hv = __floats2half2_rn(v0, v1);
                    *reinterpret_cast<__half2*>((__half*)args.C + cbase + ni * 8) = hv;
                } else {
                    float* cp = (float*)args.C + cbase + ni * 8;
                    cp[0] = v0; cp[1] = v1;
                }
            }
        }
    }
}

#define SMEM_B1 (2 * (2 * 16384 + 128 * 128))          // 98304
#define SMEM_B2 (2 * (4 * 16384 + 2 * 64 * 128))       // 163840

// ================= host orchestration =================
extern "C" void kernel_launch(void* const* d_in, const int* in_sizes, int n_in,
                              void* d_out, int out_size) {
    const float* x   = (const float*)d_in[0];
    const float* pe  = (const float*)d_in[1];
    const int*   ei0 = (const int*)d_in[2];
    const float* ea0 = (const float*)d_in[3];
    const int*   ei1 = (const int*)d_in[4];
    const float* ea1 = (const float*)d_in[5];
    const float* nl1 = (const float*)d_in[6];
    const float* nl2 = (const float*)d_in[7];
    const float* lw[8] = { (const float*)d_in[8],  (const float*)d_in[9],
                           (const float*)d_in[10], (const float*)d_in[11],
                           (const float*)d_in[12], (const float*)d_in[13],
                           (const float*)d_in[14], (const float*)d_in[15] };
    float* out = (float*)d_out;

    int N = in_sizes[0] / 128;
    int E = in_sizes[3];

    __half *xch, *xcl, *xpeh, *a0h, *a0l, *a1h, *a1l, *xmh, *wb, *ws;
    float *dis0, *dis1;
    int *cnt0, *cnt1, *off0, *off1, *cur0, *cur1;
    EdgeRec *ent0, *ent1;
    cudaGetSymbolAddress((void**)&xch, g_xcat_h);
    cudaGetSymbolAddress((void**)&xcl, g_xcat_l);
    cudaGetSymbolAddress((void**)&xpeh, g_xpeh);
    cudaGetSymbolAddress((void**)&a0h, g_a0h);
    cudaGetSymbolAddress((void**)&a0l, g_a0l);
    cudaGetSymbolAddress((void**)&a1h, g_a1h);
    cudaGetSymbolAddress((void**)&a1l, g_a1l);
    cudaGetSymbolAddress((void**)&xmh, g_xmh);
    cudaGetSymbolAddress((void**)&wb,  g_wb);
    cudaGetSymbolAddress((void**)&ws,  g_ws);
    cudaGetSymbolAddress((void**)&cnt0, g_cnt0);
    cudaGetSymbolAddress((void**)&cnt1, g_cnt1);
    cudaGetSymbolAddress((void**)&off0, g_off0);
    cudaGetSymbolAddress((void**)&off1, g_off1);
    cudaGetSymbolAddress((void**)&cur0, g_cur0);
    cudaGetSymbolAddress((void**)&cur1, g_cur1);
    cudaGetSymbolAddress((void**)&dis0, g_dis0);
    cudaGetSymbolAddress((void**)&dis1, g_dis1);
    cudaGetSymbolAddress((void**)&ent0, g_ent0);
    cudaGetSymbolAddress((void**)&ent1, g_ent1);

    cudaFuncSetAttribute((const void*)k_gemm2<1, 128, true>,
                         cudaFuncAttributeMaxDynamicSharedMemorySize, SMEM_B1);
    cudaFuncSetAttribute((const void*)k_gemm2<2, 64, true>,
                         cudaFuncAttributeMaxDynamicSharedMemorySize, SMEM_B2);
    cudaFuncSetAttribute((const void*)k_gemm2<2, 64, false>,
                         cudaFuncAttributeMaxDynamicSharedMemorySize, SMEM_B2);

    static cudaStream_t s1 = nullptr;
    static cudaEvent_t ev[6];
    if (s1 == nullptr) {
        cudaStreamCreateWithFlags(&s1, cudaStreamNonBlocking);
        for (int i = 0; i < 6; i++) cudaEventCreateWithFlags(&ev[i], cudaEventDisableTiming);
    }

    int eb = (E + 255) / 256;
    int nb = (N + 255) / 256;
    int mtiles = (N + 127) / 128;
    int gw = (N + 7) / 8;

    // ======== fork: preprocessing on s1, prep + stage B on main ========
    cudaEventRecord(ev[0], 0);
    cudaStreamWaitEvent(s1, ev[0], 0);

    cudaMemsetAsync(cnt0, 0, N * sizeof(int), s1);
    cudaMemsetAsync(cnt1, 0, N * sizeof(int), s1);
    k_count2<<<dim3(eb, 2), 256, 0, s1>>>(ei0 + E, ei1 + E, cnt0, cnt1, E);
    k_dis2<<<dim3(nb, 2), 256, 0, s1>>>(cnt0, cnt1, dis0, dis1, N);
    k_scan2<<<2, 1024, 0, s1>>>(cnt0, cnt1, off0, off1, cur0, cur1, N);
    k_fill2<<<dim3(eb, 2), 256, 0, s1>>>(ei0, ea0, ei1, ea1, dis0, dis1,
                                         cur0, cur1, ent0, ent1, E);
    cudaEventRecord(ev[1], s1);

    // main: feature/weight prep + stage B (fp16 output)
    k_xcat_split<<<2048, 256>>>(x, pe, xch, xcl, N);
    k_wtcat<<<256, 256>>>(nl1, nl2, wb);
    k_wtstk4<<<dim3(128, 4), 256>>>(lw[0], lw[1], lw[2], lw[3],
                                    lw[4], lw[5], lw[6], lw[7], ws);
    {
        GArgs a = {};
        a.A[0][0] = xch; a.A[0][1] = xcl;
        a.B[0] = wb;
        a.C = xpeh; a.M = N; a.NC = 256;
        k_gemm2<1, 128, true><<<dim3(2, mtiles), 256, SMEM_B1>>>(a);
    }
    cudaStreamWaitEvent(0, ev[1], 0);

    // ======== stage C: two gathers in parallel ========
    cudaEventRecord(ev[2], 0);
    cudaStreamWaitEvent(s1, ev[2], 0);
    k_gather<<<gw, 256, 0, s1>>>(xpeh, 256, 0, off0, ent0, dis0, a0h, a0l, N);
    cudaEventRecord(ev[3], s1);
    k_gather<<<gw, 256>>>(xpeh, 256, 128, off1, ent1, dis1, a1h, a1l, N);
    cudaStreamWaitEvent(0, ev[3], 0);

    // ======== stage D (fused dual-source GEMM, fp16 xm output) ========
    {
        GArgs a = {};
        a.A[0][0] = a0h; a.A[0][1] = a0l;
        a.A[1][0] = a1h; a.A[1][1] = a1l;
        a.B[0] = ws + 0 * 32768;
        a.B[1] = ws + 1 * 32768;
        a.C = xmh; a.M = N; a.NC = 128;
        k_gemm2<2, 64, true><<<dim3(2, mtiles), 256, SMEM_B2>>>(a);
    }

    // ======== stage E: two gathers in parallel ========
    cudaEventRecord(ev[4], 0);
    cudaStreamWaitEvent(s1, ev[4], 0);
    k_gather<<<gw, 256, 0, s1>>>(xmh, 128, 0, off0, ent0, dis0, a0h, a0l, N);
    cudaEventRecord(ev[5], s1);
    k_gather<<<gw, 256>>>(xmh, 128, 0, off1, ent1, dis1, a1h, a1l, N);
    cudaStreamWaitEvent(0, ev[5], 0);

    // ======== stage F (fused dual-source GEMM, fp32 out) ========
    {
        GArgs a = {};
        a.A[0][0] = a0h; a.A[0][1] = a0l;
        a.A[1][0] = a1h; a.A[1][1] = a1l;
        a.B[0] = ws + 2 * 32768;
        a.B[1] = ws + 3 * 32768;
        a.C = out; a.M = N; a.NC = 128;
        k_gemm2<2, 64, false><<<dim3(2, mtiles), 256, SMEM_B2>>>(a);
    }
}

// round 8
// speedup vs baseline: 2.3832x; 1.0116x over previous
#include <cuda_runtime.h>
#include <cuda_fp16.h>
#include <cstdint>

#define MAXN 50000
#define MAXE 800000

// ================= device scratch =================
struct __align__(8) Edge8 { int row; __half2 c; };   // c = (c1, c2)

__device__ __half g_xcat_h[MAXN * 256];
__device__ __half g_xcat_l[MAXN * 256];
__device__ __half g_xpeh [MAXN * 256];
__device__ __half g_a0h[MAXN * 256];
__device__ __half g_a0l[MAXN * 256];
__device__ __half g_a1h[MAXN * 256];
__device__ __half g_a1l[MAXN * 256];
__device__ __half g_xmh [MAXN * 128];
__device__ __half g_wb [256 * 256];
__device__ __half g_ws [4][128 * 256];
__device__ int   g_cnt0[MAXN];
__device__ int   g_cnt1[MAXN];
__device__ int   g_off0[MAXN + 1];
__device__ int   g_off1[MAXN + 1];
__device__ int   g_cur0[MAXN];
__device__ int   g_cur1[MAXN];
__device__ float g_dis0[MAXN];
__device__ float g_dis1[MAXN];
__device__ Edge8 g_ent0[MAXE];
__device__ Edge8 g_ent1[MAXE];

// ================= batched graph preprocessing =================
__global__ void k_count2(const int* __restrict__ c0, const int* __restrict__ c1,
                         int* __restrict__ cnt0, int* __restrict__ cnt1, int e) {
    int i = blockIdx.x * blockDim.x + threadIdx.x;
    const int* col = blockIdx.y ? c1 : c0;
    int* cnt = blockIdx.y ? cnt1 : cnt0;
    if (i < e) atomicAdd(&cnt[col[i]], 1);
}
// scan + dis fused (one launch, 2 blocks)
__global__ void k_scan2(const int* __restrict__ cnt0, const int* __restrict__ cnt1,
                        int* __restrict__ off0, int* __restrict__ off1,
                        int* __restrict__ cur0, int* __restrict__ cur1,
                        float* __restrict__ dis0, float* __restrict__ dis1, int n) {
    __shared__ int s[1024];
    const int* cnt = blockIdx.x ? cnt1 : cnt0;
    int* off = blockIdx.x ? off1 : off0;
    int* cur = blockIdx.x ? cur1 : cur0;
    float* dis = blockIdx.x ? dis1 : dis0;
    int t = threadIdx.x;
    int chunk = (n + 1023) >> 10;
    int b = t * chunk;
    int e = min(b + chunk, n);
    int sum = 0;
    for (int i = b; i < e; i++) sum += cnt[i];
    s[t] = sum;
    __syncthreads();
    for (int o = 1; o < 1024; o <<= 1) {
        int v = (t >= o) ? s[t - o] : 0;
        __syncthreads();
        s[t] += v;
        __syncthreads();
    }
    int base = s[t] - sum;
    for (int i = b; i < e; i++) {
        int c = cnt[i];
        off[i] = base; cur[i] = base; base += c;
        dis[i] = rsqrtf((float)(c + 1));
    }
    if (t == 1023) off[n] = s[1023];
}
__global__ void k_fill2(const int* __restrict__ ei0, const float* __restrict__ ea0,
                        const int* __restrict__ ei1, const float* __restrict__ ea1,
                        const float* __restrict__ dis0, const float* __restrict__ dis1,
                        int* __restrict__ cur0, int* __restrict__ cur1,
                        Edge8* __restrict__ ent0, Edge8* __restrict__ ent1, int e) {
    int i = blockIdx.x * blockDim.x + threadIdx.x;
    if (i >= e) return;
    const int* ei = blockIdx.y ? ei1 : ei0;
    const float* attr = blockIdx.y ? ea1 : ea0;
    const float* dis = blockIdx.y ? dis1 : dis0;
    int* cur = blockIdx.y ? cur1 : cur0;
    Edge8* ent = blockIdx.y ? ent1 : ent0;
    int r = ei[i], c = ei[e + i];
    float a = attr[i];
    float c1 = dis[r] * dis[c];
    float c2 = (a > 0.f) ? fminf(rsqrtf(a), 1.f) : 0.f;
    Edge8 rec;
    rec.row = r;
    rec.c = __floats2half2_rn(c1, c2);
    int p = atomicAdd(&cur[c], 1);
    ent[p] = rec;
}

// ================= feature / weight prep (fp16 hi/lo) =================
__device__ __forceinline__ void hsplit(float v, __half& h, __half& l) {
    h = __float2half_rn(v);
    l = __float2half_rn(v - __half2float(h));
}

__global__ void k_xcat_split(const float* __restrict__ x, const float* __restrict__ pe,
                             __half* __restrict__ hi, __half* __restrict__ lo, int n) {
    int stride = gridDim.x * blockDim.x;
    for (int idx = blockIdx.x * blockDim.x + threadIdx.x; idx < n * 256; idx += stride) {
        int i = idx >> 8, k = idx & 255;
        float v;
        if (k < 128)       v = x[(size_t)i * 128 + k];
        else if (k < 226)  v = pe[(size_t)i * 98 + (k - 128)];
        else               v = 0.f;
        __half h, l; hsplit(v, h, l);
        hi[idx] = h; lo[idx] = l;
    }
}

__global__ void k_wtcat(const float* __restrict__ w1, const float* __restrict__ w2,
                        __half* __restrict__ w) {
    int idx = blockIdx.x * blockDim.x + threadIdx.x;
    if (idx >= 256 * 256) return;
    int n = idx >> 8, k = idx & 255;
    float v = 0.f;
    if (k < 226) v = (n < 128) ? w1[k * 128 + n] : w2[k * 128 + (n - 128)];
    w[idx] = __float2half_rn(v);
}
__global__ void k_wtstk4(const float* __restrict__ w10, const float* __restrict__ w20,
                         const float* __restrict__ w11, const float* __restrict__ w21,
                         const float* __restrict__ w12, const float* __restrict__ w22,
                         const float* __restrict__ w13, const float* __restrict__ w23,
                         __half* __restrict__ w) {
    int idx = blockIdx.x * blockDim.x + threadIdx.x;
    if (idx >= 128 * 256) return;
    int g = blockIdx.y;
    const float* w1 = (g == 0) ? w10 : (g == 1) ? w11 : (g == 2) ? w12 : w13;
    const float* w2 = (g == 0) ? w20 : (g == 1) ? w21 : (g == 2) ? w22 : w23;
    int n = idx >> 8, k = idx & 255;
    float v = (k < 128) ? w1[k * 128 + n] : w2[(k - 128) * 128 + n];
    w[g * 32768 + idx] = __float2half_rn(v);
}

// ================= merged CSR gather (both graphs in one launch) ==============
__device__ __forceinline__ void hsplit_store4(__half* hi, __half* lo, float4 v) {
    __half h, l;
    hsplit(v.x, h, l); hi[0] = h; lo[0] = l;
    hsplit(v.y, h, l); hi[1] = h; lo[1] = l;
    hsplit(v.z, h, l); hi[2] = h; lo[2] = l;
    hsplit(v.w, h, l); hi[3] = h; lo[3] = l;
}
__device__ __forceinline__ float4 ld_half4(const __half* p) {
    uint2 raw = *reinterpret_cast<const uint2*>(p);
    __half2 h0 = *reinterpret_cast<const __half2*>(&raw.x);
    __half2 h1 = *reinterpret_cast<const __half2*>(&raw.y);
    float2 f0 = __half22float2(h0), f1 = __half22float2(h1);
    return make_float4(f0.x, f0.y, f1.x, f1.y);
}

__global__ void k_gather2(const __half* __restrict__ src, int ld, int coff1,
                          const int* __restrict__ offs0, const int* __restrict__ offs1,
                          const Edge8* __restrict__ ent0, const Edge8* __restrict__ ent1,
                          const float* __restrict__ dis0, const float* __restrict__ dis1,
                          __half* __restrict__ o0h, __half* __restrict__ o0l,
                          __half* __restrict__ o1h, __half* __restrict__ o1l, int n) {
    int g = blockIdx.y;
    const int* offs = g ? offs1 : offs0;
    const Edge8* ent = g ? ent1 : ent0;
    const float* dis = g ? dis1 : dis0;
    __half* oh = g ? o1h : o0h;
    __half* ol = g ? o1l : o0l;
    int off = g ? coff1 : 0;

    int warp = (blockIdx.x * blockDim.x + threadIdx.x) >> 5;
    int lane = threadIdx.x & 31;
    if (warp >= n) return;
    int b = offs[warp], e = offs[warp + 1];
    float4 a1 = make_float4(0.f, 0.f, 0.f, 0.f);
    float4 a2 = make_float4(0.f, 0.f, 0.f, 0.f);
    int i = b;
    for (; i + 4 <= e; i += 4) {
        Edge8 r[4];
#pragma unroll
        for (int j = 0; j < 4; j++) r[j] = ent[i + j];
        float4 v[4];
#pragma unroll
        for (int j = 0; j < 4; j++)
            v[j] = ld_half4(src + (size_t)r[j].row * ld + off + lane * 4);
#pragma unroll
        for (int j = 0; j < 4; j++) {
            float c1 = __low2float(r[j].c), c2 = __high2float(r[j].c);
            a1.x += c1 * v[j].x; a1.y += c1 * v[j].y; a1.z += c1 * v[j].z; a1.w += c1 * v[j].w;
            a2.x += c2 * v[j].x; a2.y += c2 * v[j].y; a2.z += c2 * v[j].z; a2.w += c2 * v[j].w;
        }
    }
    for (; i < e; i++) {
        Edge8 rec = ent[i];
        const float4 v = ld_half4(src + (size_t)rec.row * ld + off + lane * 4);
        float c1 = __low2float(rec.c), c2 = __high2float(rec.c);
        a1.x += c1 * v.x; a1.y += c1 * v.y; a1.z += c1 * v.z; a1.w += c1 * v.w;
        a2.x += c2 * v.x; a2.y += c2 * v.y; a2.z += c2 * v.z; a2.w += c2 * v.w;
    }
    float d = dis[warp];
    float sc = d * d;
    const float4 v = ld_half4(src + (size_t)warp * ld + off + lane * 4);
    a1.x += sc * v.x; a1.y += sc * v.y; a1.z += sc * v.z; a1.w += sc * v.w;
    a2.x += v.x;      a2.y += v.y;      a2.z += v.z;      a2.w += v.w;
    size_t base = (size_t)warp * 256 + lane * 4;
    hsplit_store4(oh + base,       ol + base,       a1);
    hsplit_store4(oh + base + 128, ol + base + 128, a2);
}

// ================= HMMA fp16 2-term GEMM =========================
__device__ __forceinline__ uint32_t smem_u32(const void* p) {
    uint32_t a;
    asm("{ .reg .u64 t; cvta.to.shared.u64 t, %1; cvt.u32.u64 %0, t; }" : "=r"(a) : "l"(p));
    return a;
}
__device__ __forceinline__ void cp16(uint32_t dst, const void* src) {
    asm volatile("cp.async.cg.shared.global [%0], [%1], 16;" :: "r"(dst), "l"(src));
}
__device__ __forceinline__ void cp_commit() { asm volatile("cp.async.commit_group;"); }
template <int W> __device__ __forceinline__ void cp_wait() {
    asm volatile("cp.async.wait_group %0;" :: "n"(W));
}
__device__ __forceinline__ void ldm_x4(uint32_t* r, uint32_t addr) {
    asm volatile("ldmatrix.sync.aligned.m8n8.x4.shared.b16 {%0,%1,%2,%3}, [%4];"
                 : "=r"(r[0]), "=r"(r[1]), "=r"(r[2]), "=r"(r[3]) : "r"(addr));
}
__device__ __forceinline__ void mma16816(float* c, const uint32_t* a, uint32_t b0, uint32_t b1) {
    asm volatile(
        "mma.sync.aligned.m16n8k16.row.col.f32.f16.f16.f32 "
        "{%0,%1,%2,%3}, {%4,%5,%6,%7}, {%8,%9}, {%0,%1,%2,%3};"
        : "+f"(c[0]), "+f"(c[1]), "+f"(c[2]), "+f"(c[3])
        : "r"(a[0]), "r"(a[1]), "r"(a[2]), "r"(a[3]), "r"(b0), "r"(b1));
}

struct GArgs {
    const __half* A[2][2];   // [src][hi/lo], [M,256]
    const __half* B[2];      // [src], single fp16 plane, [*,256] transposed
    void* C;
    int M, NC;
};

// DB: double-buffered (stage B). Single-buffered variants rely on 2 CTAs/SM.
template <int NSRC, int NT, bool OUTH, bool DB>
__global__ void __launch_bounds__(256, 2) k_gemm2(GArgs args) {
    constexpr int APL  = 16384;
    constexpr int ABUF = NSRC * 2 * APL;
    constexpr int BPL  = NT * 128;
    constexpr int BBUF = NSRC * BPL;
    constexpr int BUF  = ABUF + BBUF;
    constexpr int NI   = NT / 16;

    extern __shared__ char sm[];
    const int tid  = threadIdx.x;
    const int lane = tid & 31;
    const int wid  = tid >> 5;
    const int wm   = wid & 3;
    const int wn   = wid >> 2;
    const int m0   = blockIdx.y * 128;
    const int n0   = blockIdx.x * NT;
    const uint32_t sbase = smem_u32(sm);

    const int lr = tid >> 3, lq = tid & 7;

    auto issue_load = [&](int kc, int buf) {
        uint32_t sb = sbase + buf * BUF;
#pragma unroll
        for (int s = 0; s < NSRC; s++)
#pragma unroll
            for (int p = 0; p < 2; p++) {
                const __half* A = args.A[s][p];
                uint32_t sa = sb + (s * 2 + p) * APL;
#pragma unroll
                for (int j = 0; j < 4; j++) {
                    int r = lr + j * 32;
                    int gr = m0 + r; if (gr > args.M - 1) gr = args.M - 1;
                    cp16(sa + r * 128 + ((lq ^ (r & 7)) << 4),
                         A + (size_t)gr * 256 + kc * 64 + lq * 8);
                }
            }
#pragma unroll
        for (int s = 0; s < NSRC; s++) {
            const __half* B = args.B[s];
            uint32_t sbB = sb + ABUF + s * BPL;
#pragma unroll
            for (int j = 0; j < NT / 32; j++) {
                int r = lr + j * 32;
                cp16(sbB + r * 128 + ((lq ^ (r & 7)) << 4),
                     B + (size_t)(n0 + r) * 256 + kc * 64 + lq * 8);
            }
        }
        cp_commit();
    };

    float acc[NSRC][2][NI][4];
#pragma unroll
    for (int s = 0; s < NSRC; s++)
#pragma unroll
        for (int mi = 0; mi < 2; mi++)
#pragma unroll
            for (int ni = 0; ni < NI; ni++)
#pragma unroll
                for (int k = 0; k < 4; k++) acc[s][mi][ni][k] = 0.f;

    auto compute = [&](uint32_t sb) {
#pragma unroll
        for (int ks = 0; ks < 4; ks++) {
#pragma unroll
            for (int s = 0; s < NSRC; s++) {
                uint32_t afH[2][4], afL[2][4];
#pragma unroll
                for (int mi = 0; mi < 2; mi++) {
                    int row = wm * 32 + mi * 16 + (lane & 15);
                    int c16 = (2 * ks + (lane >> 4)) ^ (row & 7);
                    ldm_x4(afH[mi], sb + (s * 2 + 0) * APL + row * 128 + (c16 << 4));
                    ldm_x4(afL[mi], sb + (s * 2 + 1) * APL + row * 128 + (c16 << 4));
                }
                uint32_t bf[NI][2];
#pragma unroll
                for (int np = 0; np < NT / 32; np++) {
                    int nrow = wn * (NT / 2) + np * 16 + ((lane >> 4) << 3) + (lane & 7);
                    int c16 = (2 * ks + ((lane >> 3) & 1)) ^ (nrow & 7);
                    uint32_t t4[4];
                    ldm_x4(t4, sb + ABUF + s * BPL + nrow * 128 + (c16 << 4));
                    bf[np * 2][0] = t4[0]; bf[np * 2][1] = t4[1];
                    bf[np * 2 + 1][0] = t4[2]; bf[np * 2 + 1][1] = t4[3];
                }
#pragma unroll
                for (int mi = 0; mi < 2; mi++)
#pragma unroll
                    for (int ni = 0; ni < NI; ni++) {
                        mma16816(acc[s][mi][ni], afH[mi], bf[ni][0], bf[ni][1]);
                        mma16816(acc[s][mi][ni], afL[mi], bf[ni][0], bf[ni][1]);
                    }
            }
        }
    };

    if (DB) {
        issue_load(0, 0);
        for (int kc = 0; kc < 4; kc++) {
            if (kc < 3) { issue_load(kc + 1, (kc + 1) & 1); cp_wait<1>(); }
            else        { cp_wait<0>(); }
            __syncthreads();
            compute(sbase + (kc & 1) * BUF);
            __syncthreads();
        }
    } else {
        for (int kc = 0; kc < 4; kc++) {
            issue_load(kc, 0);
            cp_wait<0>();
            __syncthreads();
            compute(sbase);
            __syncthreads();
        }
    }

#pragma unroll
    for (int mi = 0; mi < 2; mi++) {
#pragma unroll
        for (int half = 0; half < 2; half++) {
            int r = m0 + wm * 32 + mi * 16 + (lane >> 2) + half * 8;
            if (r >= args.M) continue;
            size_t cbase = (size_t)r * args.NC + n0 + wn * (NT / 2) + (lane & 3) * 2;
#pragma unroll
            for (int ni = 0; ni < NI; ni++) {
                float v0, v1;
                if (NSRC == 1) {
                    v0 = acc[0][mi][ni][half * 2];
                    v1 = acc[0][mi][ni][half * 2 + 1];
                } else {
                    v0 = 0.5f * (fmaxf(acc[0][mi][ni][half * 2], 0.f) +
                                 fmaxf(acc[NSRC - 1][mi][ni][half * 2], 0.f));
                    v1 = 0.5f * (fmaxf(acc[0][mi][ni][half * 2 + 1], 0.f) +
                                 fmaxf(acc[NSRC - 1][mi][ni][half * 2 + 1], 0.f));
                }
                if (OUTH) {
                    __half2 hv = __floats2half2_rn(v0, v1);
                    *reinterpret_cast<__half2*>((__half*)args.C + cbase + ni * 8) = hv;
                } else {
                    float* cp = (float*)args.C + cbase + ni * 8;
                    cp[0] = v0; cp[1] = v1;
                }
            }
        }
    }
}

#define SMEM_B1 (2 * (2 * 16384 + 128 * 128))          // 98304, double-buffered
#define SMEM_DF (4 * 16384 + 2 * 64 * 128)             // 81920, single-buffered

// ================= host orchestration =================
extern "C" void kernel_launch(void* const* d_in, const int* in_sizes, int n_in,
                              void* d_out, int out_size) {
    const float* x   = (const float*)d_in[0];
    const float* pe  = (const float*)d_in[1];
    const int*   ei0 = (const int*)d_in[2];
    const float* ea0 = (const float*)d_in[3];
    const int*   ei1 = (const int*)d_in[4];
    const float* ea1 = (const float*)d_in[5];
    const float* nl1 = (const float*)d_in[6];
    const float* nl2 = (const float*)d_in[7];
    const float* lw[8] = { (const float*)d_in[8],  (const float*)d_in[9],
                           (const float*)d_in[10], (const float*)d_in[11],
                           (const float*)d_in[12], (const float*)d_in[13],
                           (const float*)d_in[14], (const float*)d_in[15] };
    float* out = (float*)d_out;

    int N = in_sizes[0] / 128;
    int E = in_sizes[3];

    __half *xch, *xcl, *xpeh, *a0h, *a0l, *a1h, *a1l, *xmh, *wb, *ws;
    float *dis0, *dis1;
    int *cnt0, *cnt1, *off0, *off1, *cur0, *cur1;
    Edge8 *ent0, *ent1;
    cudaGetSymbolAddress((void**)&xch, g_xcat_h);
    cudaGetSymbolAddress((void**)&xcl, g_xcat_l);
    cudaGetSymbolAddress((void**)&xpeh, g_xpeh);
    cudaGetSymbolAddress((void**)&a0h, g_a0h);
    cudaGetSymbolAddress((void**)&a0l, g_a0l);
    cudaGetSymbolAddress((void**)&a1h, g_a1h);
    cudaGetSymbolAddress((void**)&a1l, g_a1l);
    cudaGetSymbolAddress((void**)&xmh, g_xmh);
    cudaGetSymbolAddress((void**)&wb,  g_wb);
    cudaGetSymbolAddress((void**)&ws,  g_ws);
    cudaGetSymbolAddress((void**)&cnt0, g_cnt0);
    cudaGetSymbolAddress((void**)&cnt1, g_cnt1);
    cudaGetSymbolAddress((void**)&off0, g_off0);
    cudaGetSymbolAddress((void**)&off1, g_off1);
    cudaGetSymbolAddress((void**)&cur0, g_cur0);
    cudaGetSymbolAddress((void**)&cur1, g_cur1);
    cudaGetSymbolAddress((void**)&dis0, g_dis0);
    cudaGetSymbolAddress((void**)&dis1, g_dis1);
    cudaGetSymbolAddress((void**)&ent0, g_ent0);
    cudaGetSymbolAddress((void**)&ent1, g_ent1);

    cudaFuncSetAttribute((const void*)k_gemm2<1, 128, true, true>,
                         cudaFuncAttributeMaxDynamicSharedMemorySize, SMEM_B1);
    cudaFuncSetAttribute((const void*)k_gemm2<2, 64, true, false>,
                         cudaFuncAttributeMaxDynamicSharedMemorySize, SMEM_DF);
    cudaFuncSetAttribute((const void*)k_gemm2<2, 64, false, false>,
                         cudaFuncAttributeMaxDynamicSharedMemorySize, SMEM_DF);

    static cudaStream_t s1 = nullptr;
    static cudaEvent_t ev[2];
    if (s1 == nullptr) {
        cudaStreamCreateWithFlags(&s1, cudaStreamNonBlocking);
        for (int i = 0; i < 2; i++) cudaEventCreateWithFlags(&ev[i], cudaEventDisableTiming);
    }

    int eb = (E + 255) / 256;
    int mtiles = (N + 127) / 128;
    int gw = (N + 7) / 8;

    // ======== fork: preprocessing on s1, prep + stage B on main ========
    cudaEventRecord(ev[0], 0);
    cudaStreamWaitEvent(s1, ev[0], 0);

    cudaMemsetAsync(cnt0, 0, N * sizeof(int), s1);
    cudaMemsetAsync(cnt1, 0, N * sizeof(int), s1);
    k_count2<<<dim3(eb, 2), 256, 0, s1>>>(ei0 + E, ei1 + E, cnt0, cnt1, E);
    k_scan2<<<2, 1024, 0, s1>>>(cnt0, cnt1, off0, off1, cur0, cur1, dis0, dis1, N);
    k_fill2<<<dim3(eb, 2), 256, 0, s1>>>(ei0, ea0, ei1, ea1, dis0, dis1,
                                         cur0, cur1, ent0, ent1, E);
    cudaEventRecord(ev[1], s1);

    // main: feature prep + stage B
    k_xcat_split<<<2048, 256>>>(x, pe, xch, xcl, N);
    k_wtcat<<<256, 256>>>(nl1, nl2, wb);
    {
        GArgs a = {};
        a.A[0][0] = xch; a.A[0][1] = xcl;
        a.B[0] = wb;
        a.C = xpeh; a.M = N; a.NC = 256;
        k_gemm2<1, 128, true, true><<<dim3(2, mtiles), 256, SMEM_B1>>>(a);
    }
    // ws prep only gates stage D — launch after B
    k_wtstk4<<<dim3(128, 4), 256>>>(lw[0], lw[1], lw[2], lw[3],
                                    lw[4], lw[5], lw[6], lw[7], ws);
    cudaStreamWaitEvent(0, ev[1], 0);   // join preprocessing

    // ======== stage C: both graphs in one launch ========
    k_gather2<<<dim3(gw, 2), 256>>>(xpeh, 256, 128, off0, off1, ent0, ent1,
                                    dis0, dis1, a0h, a0l, a1h, a1l, N);

    // ======== stage D (fused dual-source GEMM, fp16 xm output) ========
    {
        GArgs a = {};
        a.A[0][0] = a0h; a.A[0][1] = a0l;
        a.A[1][0] = a1h; a.A[1][1] = a1l;
        a.B[0] = ws + 0 * 32768;
        a.B[1] = ws + 1 * 32768;
        a.C = xmh; a.M = N; a.NC = 128;
        k_gemm2<2, 64, true, false><<<dim3(2, mtiles), 256, SMEM_DF>>>(a);
    }

    // ======== stage E: both graphs in one launch ========
    k_gather2<<<dim3(gw, 2), 256>>>(xmh, 128, 0, off0, off1, ent0, ent1,
                                    dis0, dis1, a0h, a0l, a1h, a1l, N);

    // ======== stage F (fused dual-source GEMM, fp32 out) ========
    {
        GArgs a = {};
        a.A[0][0] = a0h; a.A[0][1] = a0l;
        a.A[1][0] = a1h; a.A[1][1] = a1l;
        a.B[0] = ws + 2 * 32768;
        a.B[1] = ws + 3 * 32768;
        a.C = out; a.M = N; a.NC = 128;
        k_gemm2<2, 64, false, false><<<dim3(2, mtiles), 256, SMEM_DF>>>(a);
    }
}

// round 9
// speedup vs baseline: 2.4630x; 1.0335x over previous
#include <cuda_runtime.h>
#include <cuda_fp16.h>
#include <cstdint>

#define MAXN 50000
#define MAXE 800000

// ================= device scratch =================
struct __align__(8) Edge8 { int row; __half2 c; };   // c = (dis[row], c2)

__device__ __half g_xcat_h[MAXN * 256];
__device__ __half g_xcat_l[MAXN * 256];
__device__ __half g_xpeh [MAXN * 256];
__device__ __half g_a0h[MAXN * 256];
__device__ __half g_a0l[MAXN * 256];
__device__ __half g_a1h[MAXN * 256];
__device__ __half g_a1l[MAXN * 256];
__device__ __half g_xmh [MAXN * 128];
__device__ __half g_wb [256 * 256];
__device__ __half g_ws [4][128 * 256];
__device__ int   g_cnt [2 * MAXN];
__device__ int   g_off0[MAXN + 1];
__device__ int   g_off1[MAXN + 1];
__device__ int   g_cur0[MAXN];
__device__ int   g_cur1[MAXN];
__device__ float g_dis0[MAXN];
__device__ float g_dis1[MAXN];
__device__ Edge8 g_ent0[MAXE];
__device__ Edge8 g_ent1[MAXE];

// ================= batched graph preprocessing =================
__global__ void k_count2(const int* __restrict__ c0, const int* __restrict__ c1,
                         int* __restrict__ cnt0, int* __restrict__ cnt1, int e) {
    int i = blockIdx.x * blockDim.x + threadIdx.x;
    const int* col = blockIdx.y ? c1 : c0;
    int* cnt = blockIdx.y ? cnt1 : cnt0;
    if (i < e) atomicAdd(&cnt[col[i]], 1);
}
// scan + dis fused (one launch, 2 blocks)
__global__ void k_scan2(const int* __restrict__ cnt0, const int* __restrict__ cnt1,
                        int* __restrict__ off0, int* __restrict__ off1,
                        int* __restrict__ cur0, int* __restrict__ cur1,
                        float* __restrict__ dis0, float* __restrict__ dis1, int n) {
    __shared__ int s[1024];
    const int* cnt = blockIdx.x ? cnt1 : cnt0;
    int* off = blockIdx.x ? off1 : off0;
    int* cur = blockIdx.x ? cur1 : cur0;
    float* dis = blockIdx.x ? dis1 : dis0;
    int t = threadIdx.x;
    int chunk = (n + 1023) >> 10;
    int b = t * chunk;
    int e = min(b + chunk, n);
    int sum = 0;
    for (int i = b; i < e; i++) sum += cnt[i];
    s[t] = sum;
    __syncthreads();
    for (int o = 1; o < 1024; o <<= 1) {
        int v = (t >= o) ? s[t - o] : 0;
        __syncthreads();
        s[t] += v;
        __syncthreads();
    }
    int base = s[t] - sum;
    for (int i = b; i < e; i++) {
        int c = cnt[i];
        off[i] = base; cur[i] = base; base += c;
        dis[i] = rsqrtf((float)(c + 1));
    }
    if (t == 1023) off[n] = s[1023];
}
__global__ void k_fill2(const int* __restrict__ ei0, const float* __restrict__ ea0,
                        const int* __restrict__ ei1, const float* __restrict__ ea1,
                        const float* __restrict__ dis0, const float* __restrict__ dis1,
                        int* __restrict__ cur0, int* __restrict__ cur1,
                        Edge8* __restrict__ ent0, Edge8* __restrict__ ent1, int e) {
    int i = blockIdx.x * blockDim.x + threadIdx.x;
    if (i >= e) return;
    const int* ei = blockIdx.y ? ei1 : ei0;
    const float* attr = blockIdx.y ? ea1 : ea0;
    const float* dis = blockIdx.y ? dis1 : dis0;
    int* cur = blockIdx.y ? cur1 : cur0;
    Edge8* ent = blockIdx.y ? ent1 : ent0;
    int r = ei[i], c = ei[e + i];
    float a = attr[i];
    float c2 = (a > 0.f) ? fminf(rsqrtf(a), 1.f) : 0.f;
    Edge8 rec;
    rec.row = r;
    rec.c = __floats2half2_rn(dis[r], c2);   // c1 = dis[r]*dis[c] finished at gather
    int p = atomicAdd(&cur[c], 1);
    ent[p] = rec;
}

// ================= fused xcat split + wtcat prep ======================
__device__ __forceinline__ void hsplit(float v, __half& h, __half& l) {
    h = __float2half_rn(v);
    l = __float2half_rn(v - __half2float(h));
}

// blocks [0, nxblk): xcat rows (4 rows/block, 64 threads/row, 4 elems/thread)
// blocks [nxblk, nxblk+256): wtcat (1 elem/thread)
__global__ void k_xcatwt(const float* __restrict__ x, const float* __restrict__ pe,
                         const float* __restrict__ w1, const float* __restrict__ w2,
                         __half* __restrict__ hi, __half* __restrict__ lo,
                         __half* __restrict__ wb, int n, int nxblk) {
    int b = blockIdx.x;
    int t = threadIdx.x;
    if (b >= nxblk) {
        int idx = (b - nxblk) * 256 + t;
        int nn = idx >> 8, k = idx & 255;
        float v = 0.f;
        if (k < 226) v = (nn < 128) ? w1[k * 128 + nn] : w2[k * 128 + (nn - 128)];
        wb[idx] = __float2half_rn(v);
        return;
    }
    int row = b * 4 + (t >> 6);
    if (row >= n) return;
    int k = (t & 63) * 4;
    float v0, v1, v2, v3;
    if (k < 128) {
        float4 xv = *reinterpret_cast<const float4*>(x + (size_t)row * 128 + k);
        v0 = xv.x; v1 = xv.y; v2 = xv.z; v3 = xv.w;
    } else {
        int pk = k - 128;                       // even, 0..124
        const float* pr = pe + (size_t)row * 98;
        if (pk + 1 < 98) { float2 p = *reinterpret_cast<const float2*>(pr + pk); v0 = p.x; v1 = p.y; }
        else             { v0 = 0.f; v1 = 0.f; }
        if (pk + 3 < 98) { float2 p = *reinterpret_cast<const float2*>(pr + pk + 2); v2 = p.x; v3 = p.y; }
        else             { v2 = 0.f; v3 = 0.f; }
    }
    __half h0, l0, h1, l1, h2, l2, h3, l3;
    hsplit(v0, h0, l0); hsplit(v1, h1, l1);
    hsplit(v2, h2, l2); hsplit(v3, h3, l3);
    size_t o = (size_t)row * 256 + k;
    __half2* hp = reinterpret_cast<__half2*>(hi + o);
    hp[0] = __halves2half2(h0, h1); hp[1] = __halves2half2(h2, h3);
    __half2* lp = reinterpret_cast<__half2*>(lo + o);
    lp[0] = __halves2half2(l0, l1); lp[1] = __halves2half2(l2, l3);
}

__global__ void k_wtstk4(const float* __restrict__ w10, const float* __restrict__ w20,
                         const float* __restrict__ w11, const float* __restrict__ w21,
                         const float* __restrict__ w12, const float* __restrict__ w22,
                         const float* __restrict__ w13, const float* __restrict__ w23,
                         __half* __restrict__ w) {
    int idx = blockIdx.x * blockDim.x + threadIdx.x;
    if (idx >= 128 * 256) return;
    int g = blockIdx.y;
    const float* w1 = (g == 0) ? w10 : (g == 1) ? w11 : (g == 2) ? w12 : w13;
    const float* w2 = (g == 0) ? w20 : (g == 1) ? w21 : (g == 2) ? w22 : w23;
    int n = idx >> 8, k = idx & 255;
    float v = (k < 128) ? w1[k * 128 + n] : w2[(k - 128) * 128 + n];
    w[g * 32768 + idx] = __float2half_rn(v);
}

// ================= merged CSR gather (both graphs in one launch) ==============
__device__ __forceinline__ void hsplit_store4(__half* hi, __half* lo, float4 v) {
    __half h, l;
    hsplit(v.x, h, l); hi[0] = h; lo[0] = l;
    hsplit(v.y, h, l); hi[1] = h; lo[1] = l;
    hsplit(v.z, h, l); hi[2] = h; lo[2] = l;
    hsplit(v.w, h, l); hi[3] = h; lo[3] = l;
}
__device__ __forceinline__ float4 ld_half4(const __half* p) {
    uint2 raw = *reinterpret_cast<const uint2*>(p);
    __half2 h0 = *reinterpret_cast<const __half2*>(&raw.x);
    __half2 h1 = *reinterpret_cast<const __half2*>(&raw.y);
    float2 f0 = __half22float2(h0), f1 = __half22float2(h1);
    return make_float4(f0.x, f0.y, f1.x, f1.y);
}

__global__ void k_gather2(const __half* __restrict__ src, int ld, int coff1,
                          const int* __restrict__ offs0, const int* __restrict__ offs1,
                          const Edge8* __restrict__ ent0, const Edge8* __restrict__ ent1,
                          const float* __restrict__ dis0, const float* __restrict__ dis1,
                          __half* __restrict__ o0h, __half* __restrict__ o0l,
                          __half* __restrict__ o1h, __half* __restrict__ o1l, int n) {
    int g = blockIdx.y;
    const int* offs = g ? offs1 : offs0;
    const Edge8* ent = g ? ent1 : ent0;
    const float* dis = g ? dis1 : dis0;
    __half* oh = g ? o1h : o0h;
    __half* ol = g ? o1l : o0l;
    int off = g ? coff1 : 0;

    int warp = (blockIdx.x * blockDim.x + threadIdx.x) >> 5;
    int lane = threadIdx.x & 31;
    if (warp >= n) return;
    float d = dis[warp];                       // dest-node dis (also self-loop)
    int b = offs[warp], e = offs[warp + 1];
    float4 a1 = make_float4(0.f, 0.f, 0.f, 0.f);
    float4 a2 = make_float4(0.f, 0.f, 0.f, 0.f);
    int i = b;
    for (; i + 4 <= e; i += 4) {
        Edge8 r[4];
#pragma unroll
        for (int j = 0; j < 4; j++) r[j] = ent[i + j];
        float4 v[4];
#pragma unroll
        for (int j = 0; j < 4; j++)
            v[j] = ld_half4(src + (size_t)r[j].row * ld + off + lane * 4);
#pragma unroll
        for (int j = 0; j < 4; j++) {
            float c1 = __low2float(r[j].c) * d, c2 = __high2float(r[j].c);
            a1.x += c1 * v[j].x; a1.y += c1 * v[j].y; a1.z += c1 * v[j].z; a1.w += c1 * v[j].w;
            a2.x += c2 * v[j].x; a2.y += c2 * v[j].y; a2.z += c2 * v[j].z; a2.w += c2 * v[j].w;
        }
    }
    for (; i < e; i++) {
        Edge8 rec = ent[i];
        const float4 v = ld_half4(src + (size_t)rec.row * ld + off + lane * 4);
        float c1 = __low2float(rec.c) * d, c2 = __high2float(rec.c);
        a1.x += c1 * v.x; a1.y += c1 * v.y; a1.z += c1 * v.z; a1.w += c1 * v.w;
        a2.x += c2 * v.x; a2.y += c2 * v.y; a2.z += c2 * v.z; a2.w += c2 * v.w;
    }
    float sc = d * d;
    const float4 v = ld_half4(src + (size_t)warp * ld + off + lane * 4);
    a1.x += sc * v.x; a1.y += sc * v.y; a1.z += sc * v.z; a1.w += sc * v.w;
    a2.x += v.x;      a2.y += v.y;      a2.z += v.z;      a2.w += v.w;
    size_t base = (size_t)warp * 256 + lane * 4;
    hsplit_store4(oh + base,       ol + base,       a1);
    hsplit_store4(oh + base + 128, ol + base + 128, a2);
}

// ================= HMMA fp16 2-term GEMM =========================
__device__ __forceinline__ uint32_t smem_u32(const void* p) {
    uint32_t a;
    asm("{ .reg .u64 t; cvta.to.shared.u64 t, %1; cvt.u32.u64 %0, t; }" : "=r"(a) : "l"(p));
    return a;
}
__device__ __forceinline__ void cp16(uint32_t dst, const void* src) {
    asm volatile("cp.async.cg.shared.global [%0], [%1], 16;" :: "r"(dst), "l"(src));
}
__device__ __forceinline__ void cp_commit() { asm volatile("cp.async.commit_group;"); }
template <int W> __device__ __forceinline__ void cp_wait() {
    asm volatile("cp.async.wait_group %0;" :: "n"(W));
}
__device__ __forceinline__ void ldm_x4(uint32_t* r, uint32_t addr) {
    asm volatile("ldmatrix.sync.aligned.m8n8.x4.shared.b16 {%0,%1,%2,%3}, [%4];"
                 : "=r"(r[0]), "=r"(r[1]), "=r"(r[2]), "=r"(r[3]) : "r"(addr));
}
__device__ __forceinline__ void mma16816(float* c, const uint32_t* a, uint32_t b0, uint32_t b1) {
    asm volatile(
        "mma.sync.aligned.m16n8k16.row.col.f32.f16.f16.f32 "
        "{%0,%1,%2,%3}, {%4,%5,%6,%7}, {%8,%9}, {%0,%1,%2,%3};"
        : "+f"(c[0]), "+f"(c[1]), "+f"(c[2]), "+f"(c[3])
        : "r"(a[0]), "r"(a[1]), "r"(a[2]), "r"(a[3]), "r"(b0), "r"(b1));
}

struct GArgs {
    const __half* A[2][2];   // [src][hi/lo], [M,256]
    const __half* B[2];      // [src], single fp16 plane, [*,256] transposed
    void* C;
    int M, NC;
};

template <int NSRC, int NT, bool OUTH, bool DB>
__global__ void __launch_bounds__(256, 2) k_gemm2(GArgs args) {
    constexpr int APL  = 16384;
    constexpr int ABUF = NSRC * 2 * APL;
    constexpr int BPL  = NT * 128;
    constexpr int BBUF = NSRC * BPL;
    constexpr int BUF  = ABUF + BBUF;
    constexpr int NI   = NT / 16;

    extern __shared__ char sm[];
    const int tid  = threadIdx.x;
    const int lane = tid & 31;
    const int wid  = tid >> 5;
    const int wm   = wid & 3;
    const int wn   = wid >> 2;
    const int m0   = blockIdx.y * 128;
    const int n0   = blockIdx.x * NT;
    const uint32_t sbase = smem_u32(sm);

    const int lr = tid >> 3, lq = tid & 7;

    auto issue_load = [&](int kc, int buf) {
        uint32_t sb = sbase + buf * BUF;
#pragma unroll
        for (int s = 0; s < NSRC; s++)
#pragma unroll
            for (int p = 0; p < 2; p++) {
                const __half* A = args.A[s][p];
                uint32_t sa = sb + (s * 2 + p) * APL;
#pragma unroll
                for (int j = 0; j < 4; j++) {
                    int r = lr + j * 32;
                    int gr = m0 + r; if (gr > args.M - 1) gr = args.M - 1;
                    cp16(sa + r * 128 + ((lq ^ (r & 7)) << 4),
                         A + (size_t)gr * 256 + kc * 64 + lq * 8);
                }
            }
#pragma unroll
        for (int s = 0; s < NSRC; s++) {
            const __half* B = args.B[s];
            uint32_t sbB = sb + ABUF + s * BPL;
#pragma unroll
            for (int j = 0; j < NT / 32; j++) {
                int r = lr + j * 32;
                cp16(sbB + r * 128 + ((lq ^ (r & 7)) << 4),
                     B + (size_t)(n0 + r) * 256 + kc * 64 + lq * 8);
            }
        }
        cp_commit();
    };

    float acc[NSRC][2][NI][4];
#pragma unroll
    for (int s = 0; s < NSRC; s++)
#pragma unroll
        for (int mi = 0; mi < 2; mi++)
#pragma unroll
            for (int ni = 0; ni < NI; ni++)
#pragma unroll
                for (int k = 0; k < 4; k++) acc[s][mi][ni][k] = 0.f;

    auto compute = [&](uint32_t sb) {
#pragma unroll
        for (int ks = 0; ks < 4; ks++) {
#pragma unroll
            for (int s = 0; s < NSRC; s++) {
                uint32_t afH[2][4], afL[2][4];
#pragma unroll
                for (int mi = 0; mi < 2; mi++) {
                    int row = wm * 32 + mi * 16 + (lane & 15);
                    int c16 = (2 * ks + (lane >> 4)) ^ (row & 7);
                    ldm_x4(afH[mi], sb + (s * 2 + 0) * APL + row * 128 + (c16 << 4));
                    ldm_x4(afL[mi], sb + (s * 2 + 1) * APL + row * 128 + (c16 << 4));
                }
                uint32_t bf[NI][2];
#pragma unroll
                for (int np = 0; np < NT / 32; np++) {
                    int nrow = wn * (NT / 2) + np * 16 + ((lane >> 4) << 3) + (lane & 7);
                    int c16 = (2 * ks + ((lane >> 3) & 1)) ^ (nrow & 7);
                    uint32_t t4[4];
                    ldm_x4(t4, sb + ABUF + s * BPL + nrow * 128 + (c16 << 4));
                    bf[np * 2][0] = t4[0]; bf[np * 2][1] = t4[1];
                    bf[np * 2 + 1][0] = t4[2]; bf[np * 2 + 1][1] = t4[3];
                }
#pragma unroll
                for (int mi = 0; mi < 2; mi++)
#pragma unroll
                    for (int ni = 0; ni < NI; ni++) {
                        mma16816(acc[s][mi][ni], afH[mi], bf[ni][0], bf[ni][1]);
                        mma16816(acc[s][mi][ni], afL[mi], bf[ni][0], bf[ni][1]);
                    }
            }
        }
    };

    if (DB) {
        issue_load(0, 0);
        for (int kc = 0; kc < 4; kc++) {
            if (kc < 3) { issue_load(kc + 1, (kc + 1) & 1); cp_wait<1>(); }
            else        { cp_wait<0>(); }
            __syncthreads();
            compute(sbase + (kc & 1) * BUF);
            __syncthreads();
        }
    } else {
        for (int kc = 0; kc < 4; kc++) {
            issue_load(kc, 0);
            cp_wait<0>();
            __syncthreads();
            compute(sbase);
            __syncthreads();
        }
    }

#pragma unroll
    for (int mi = 0; mi < 2; mi++) {
#pragma unroll
        for (int half = 0; half < 2; half++) {
            int r = m0 + wm * 32 + mi * 16 + (lane >> 2) + half * 8;
            if (r >= args.M) continue;
            size_t cbase = (size_t)r * args.NC + n0 + wn * (NT / 2) + (lane & 3) * 2;
#pragma unroll
            for (int ni = 0; ni < NI; ni++) {
                float v0, v1;
                if (NSRC == 1) {
                    v0 = acc[0][mi][ni][half * 2];
                    v1 = acc[0][mi][ni][half * 2 + 1];
                } else {
                    v0 = 0.5f * (fmaxf(acc[0][mi][ni][half * 2], 0.f) +
                                 fmaxf(acc[NSRC - 1][mi][ni][half * 2], 0.f));
                    v1 = 0.5f * (fmaxf(acc[0][mi][ni][half * 2 + 1], 0.f) +
                                 fmaxf(acc[NSRC - 1][mi][ni][half * 2 + 1], 0.f));
                }
                if (OUTH) {
                    __half2 hv = __floats2half2_rn(v0, v1);
                    *reinterpret_cast<__half2*>((__half*)args.C + cbase + ni * 8) = hv;
                } else {
                    float* cp = (float*)args.C + cbase + ni * 8;
                    cp[0] = v0; cp[1] = v1;
                }
            }
        }
    }
}

#define SMEM_B1 (2 * (2 * 16384 + 128 * 128))          // 98304, double-buffered
#define SMEM_DF (4 * 16384 + 2 * 64 * 128)             // 81920, single-buffered

// ================= host orchestration =================
extern "C" void kernel_launch(void* const* d_in, const int* in_sizes, int n_in,
                              void* d_out, int out_size) {
    const float* x   = (const float*)d_in[0];
    const float* pe  = (const float*)d_in[1];
    const int*   ei0 = (const int*)d_in[2];
    const float* ea0 = (const float*)d_in[3];
    const int*   ei1 = (const int*)d_in[4];
    const float* ea1 = (const float*)d_in[5];
    const float* nl1 = (const float*)d_in[6];
    const float* nl2 = (const float*)d_in[7];
    const float* lw[8] = { (const float*)d_in[8],  (const float*)d_in[9],
                           (const float*)d_in[10], (const float*)d_in[11],
                           (const float*)d_in[12], (const float*)d_in[13],
                           (const float*)d_in[14], (const float*)d_in[15] };
    float* out = (float*)d_out;

    int N = in_sizes[0] / 128;
    int E = in_sizes[3];

    __half *xch, *xcl, *xpeh, *a0h, *a0l, *a1h, *a1l, *xmh, *wb, *ws;
    float *dis0, *dis1;
    int *cnt, *off0, *off1, *cur0, *cur1;
    Edge8 *ent0, *ent1;
    cudaGetSymbolAddress((void**)&xch, g_xcat_h);
    cudaGetSymbolAddress((void**)&xcl, g_xcat_l);
    cudaGetSymbolAddress((void**)&xpeh, g_xpeh);
    cudaGetSymbolAddress((void**)&a0h, g_a0h);
    cudaGetSymbolAddress((void**)&a0l, g_a0l);
    cudaGetSymbolAddress((void**)&a1h, g_a1h);
    cudaGetSymbolAddress((void**)&a1l, g_a1l);
    cudaGetSymbolAddress((void**)&xmh, g_xmh);
    cudaGetSymbolAddress((void**)&wb,  g_wb);
    cudaGetSymbolAddress((void**)&ws,  g_ws);
    cudaGetSymbolAddress((void**)&cnt, g_cnt);
    cudaGetSymbolAddress((void**)&off0, g_off0);
    cudaGetSymbolAddress((void**)&off1, g_off1);
    cudaGetSymbolAddress((void**)&cur0, g_cur0);
    cudaGetSymbolAddress((void**)&cur1, g_cur1);
    cudaGetSymbolAddress((void**)&dis0, g_dis0);
    cudaGetSymbolAddress((void**)&dis1, g_dis1);
    cudaGetSymbolAddress((void**)&ent0, g_ent0);
    cudaGetSymbolAddress((void**)&ent1, g_ent1);
    int* cnt0 = cnt;
    int* cnt1 = cnt + MAXN;

    cudaFuncSetAttribute((const void*)k_gemm2<1, 128, true, true>,
                         cudaFuncAttributeMaxDynamicSharedMemorySize, SMEM_B1);
    cudaFuncSetAttribute((const void*)k_gemm2<2, 64, true, false>,
                         cudaFuncAttributeMaxDynamicSharedMemorySize, SMEM_DF);
    cudaFuncSetAttribute((const void*)k_gemm2<2, 64, false, false>,
                         cudaFuncAttributeMaxDynamicSharedMemorySize, SMEM_DF);

    static cudaStream_t s1 = nullptr;
    static cudaEvent_t ev[2];
    if (s1 == nullptr) {
        cudaStreamCreateWithFlags(&s1, cudaStreamNonBlocking);
        for (int i = 0; i < 2; i++) cudaEventCreateWithFlags(&ev[i], cudaEventDisableTiming);
    }

    int eb = (E + 255) / 256;
    int mtiles = (N + 127) / 128;
    int gw = (N + 7) / 8;
    int nxblk = (N + 3) / 4;

    // ======== fork: preprocessing on s1 (submissions #1-#4) ========
    cudaEventRecord(ev[0], 0);
    cudaStreamWaitEvent(s1, ev[0], 0);

    cudaMemsetAsync(cnt, 0, 2 * MAXN * sizeof(int), s1);                       // #1
    k_count2<<<dim3(eb, 2), 256, 0, s1>>>(ei0 + E, ei1 + E, cnt0, cnt1, E);    // #2
    k_scan2<<<2, 1024, 0, s1>>>(cnt0, cnt1, off0, off1, cur0, cur1,
                                dis0, dis1, N);                                 // #3
    k_fill2<<<dim3(eb, 2), 256, 0, s1>>>(ei0, ea0, ei1, ea1, dis0, dis1,
                                         cur0, cur1, ent0, ent1, E);            // #4
    cudaEventRecord(ev[1], s1);

    // main: fused feature+wcat prep (#5), stage B GEMM (#6 -> ncu target)
    k_xcatwt<<<nxblk + 256, 256>>>(x, pe, nl1, nl2, xch, xcl, wb, N, nxblk);    // #5
    {
        GArgs a = {};
        a.A[0][0] = xch; a.A[0][1] = xcl;
        a.B[0] = wb;
        a.C = xpeh; a.M = N; a.NC = 256;
        k_gemm2<1, 128, true, true><<<dim3(2, mtiles), 256, SMEM_B1>>>(a);      // #6
    }
    k_wtstk4<<<dim3(128, 4), 256>>>(lw[0], lw[1], lw[2], lw[3],
                                    lw[4], lw[5], lw[6], lw[7], ws);            // #7
    cudaStreamWaitEvent(0, ev[1], 0);   // join preprocessing

    // ======== stage C: both graphs in one launch ========
    k_gather2<<<dim3(gw, 2), 256>>>(xpeh, 256, 128, off0, off1, ent0, ent1,
                                    dis0, dis1, a0h, a0l, a1h, a1l, N);         // #8

    // ======== stage D (fused dual-source GEMM, fp16 xm output) ========
    {
        GArgs a = {};
        a.A[0][0] = a0h; a.A[0][1] = a0l;
        a.A[1][0] = a1h; a.A[1][1] = a1l;
        a.B[0] = ws + 0 * 32768;
        a.B[1] = ws + 1 * 32768;
        a.C = xmh; a.M = N; a.NC = 128;
        k_gemm2<2, 64, true, false><<<dim3(2, mtiles), 256, SMEM_DF>>>(a);      // #9
    }

    // ======== stage E ========
    k_gather2<<<dim3(gw, 2), 256>>>(xmh, 128, 0, off0, off1, ent0, ent1,
                                    dis0, dis1, a0h, a0l, a1h, a1l, N);         // #10

    // ======== stage F (fused dual-source GEMM, fp32 out) ========
    {
        GArgs a = {};
        a.A[0][0] = a0h; a.A[0][1] = a0l;
        a.A[1][0] = a1h; a.A[1][1] = a1l;
        a.B[0] = ws + 2 * 32768;
        a.B[1] = ws + 3 * 32768;
        a.C = out; a.M = N; a.NC = 128;
        k_gemm2<2, 64, false, false><<<dim3(2, mtiles), 256, SMEM_DF>>>(a);     // #11
    }
}

// round 10
// speedup vs baseline: 3.0059x; 1.2204x over previous
#include <cuda_runtime.h>
#include <cuda_fp16.h>
#include <cstdint>

#define MAXN 50000
#define MAXE 800000

// ================= device scratch =================
struct __align__(8) Edge8 { int row; __half2 c; };   // c = (dis[row], c2)

__device__ __half g_xcat[MAXN * 256];
__device__ __half g_xpeh[MAXN * 256];
__device__ __half g_a0  [MAXN * 256];
__device__ __half g_a1  [MAXN * 256];
__device__ __half g_xmh [MAXN * 128];
__device__ __half g_wb  [256 * 256];
__device__ __half g_ws  [4][128 * 256];
__device__ int   g_cnt [2 * MAXN];
__device__ int   g_off0[MAXN + 1];
__device__ int   g_off1[MAXN + 1];
__device__ int   g_cur0[MAXN];
__device__ int   g_cur1[MAXN];
__device__ float g_dis0[MAXN];
__device__ float g_dis1[MAXN];
__device__ Edge8 g_ent0[MAXE];
__device__ Edge8 g_ent1[MAXE];

// ================= batched graph preprocessing =================
__global__ void k_count2(const int* __restrict__ c0, const int* __restrict__ c1,
                         int* __restrict__ cnt0, int* __restrict__ cnt1, int e) {
    int i = blockIdx.x * blockDim.x + threadIdx.x;
    const int* col = blockIdx.y ? c1 : c0;
    int* cnt = blockIdx.y ? cnt1 : cnt0;
    if (i < e) atomicAdd(&cnt[col[i]], 1);
}
__global__ void k_scan2(const int* __restrict__ cnt0, const int* __restrict__ cnt1,
                        int* __restrict__ off0, int* __restrict__ off1,
                        int* __restrict__ cur0, int* __restrict__ cur1,
                        float* __restrict__ dis0, float* __restrict__ dis1, int n) {
    __shared__ int s[1024];
    const int* cnt = blockIdx.x ? cnt1 : cnt0;
    int* off = blockIdx.x ? off1 : off0;
    int* cur = blockIdx.x ? cur1 : cur0;
    float* dis = blockIdx.x ? dis1 : dis0;
    int t = threadIdx.x;
    int chunk = (n + 1023) >> 10;
    int b = t * chunk;
    int e = min(b + chunk, n);
    int sum = 0;
    for (int i = b; i < e; i++) sum += cnt[i];
    s[t] = sum;
    __syncthreads();
    for (int o = 1; o < 1024; o <<= 1) {
        int v = (t >= o) ? s[t - o] : 0;
        __syncthreads();
        s[t] += v;
        __syncthreads();
    }
    int base = s[t] - sum;
    for (int i = b; i < e; i++) {
        int c = cnt[i];
        off[i] = base; cur[i] = base; base += c;
        dis[i] = rsqrtf((float)(c + 1));
    }
    if (t == 1023) off[n] = s[1023];
}
__global__ void k_fill2(const int* __restrict__ ei0, const float* __restrict__ ea0,
                        const int* __restrict__ ei1, const float* __restrict__ ea1,
                        const float* __restrict__ dis0, const float* __restrict__ dis1,
                        int* __restrict__ cur0, int* __restrict__ cur1,
                        Edge8* __restrict__ ent0, Edge8* __restrict__ ent1, int e) {
    int i = blockIdx.x * blockDim.x + threadIdx.x;
    if (i >= e) return;
    const int* ei = blockIdx.y ? ei1 : ei0;
    const float* attr = blockIdx.y ? ea1 : ea0;
    const float* dis = blockIdx.y ? dis1 : dis0;
    int* cur = blockIdx.y ? cur1 : cur0;
    Edge8* ent = blockIdx.y ? ent1 : ent0;
    int r = ei[i], c = ei[e + i];
    float a = attr[i];
    float c2 = (a > 0.f) ? fminf(rsqrtf(a), 1.f) : 0.f;
    Edge8 rec;
    rec.row = r;
    rec.c = __floats2half2_rn(dis[r], c2);   // c1 = dis[r]*dis[c] finished at gather
    int p = atomicAdd(&cur[c], 1);
    ent[p] = rec;
}

// ================= fused xcat (fp16) + wtcat prep ======================
// blocks [0, nxblk): xcat rows (4 rows/block, 64 threads/row, 4 elems/thread)
// blocks [nxblk, nxblk+256): wtcat (1 elem/thread)
__global__ void k_xcatwt(const float* __restrict__ x, const float* __restrict__ pe,
                         const float* __restrict__ w1, const float* __restrict__ w2,
                         __half* __restrict__ xc, __half* __restrict__ wb,
                         int n, int nxblk) {
    int b = blockIdx.x;
    int t = threadIdx.x;
    if (b >= nxblk) {
        int idx = (b - nxblk) * 256 + t;
        int nn = idx >> 8, k = idx & 255;
        float v = 0.f;
        if (k < 226) v = (nn < 128) ? w1[k * 128 + nn] : w2[k * 128 + (nn - 128)];
        wb[idx] = __float2half_rn(v);
        return;
    }
    int row = b * 4 + (t >> 6);
    if (row >= n) return;
    int k = (t & 63) * 4;
    float v0, v1, v2, v3;
    if (k < 128) {
        float4 xv = *reinterpret_cast<const float4*>(x + (size_t)row * 128 + k);
        v0 = xv.x; v1 = xv.y; v2 = xv.z; v3 = xv.w;
    } else {
        int pk = k - 128;
        const float* pr = pe + (size_t)row * 98;
        if (pk + 1 < 98) { float2 p = *reinterpret_cast<const float2*>(pr + pk); v0 = p.x; v1 = p.y; }
        else             { v0 = 0.f; v1 = 0.f; }
        if (pk + 3 < 98) { float2 p = *reinterpret_cast<const float2*>(pr + pk + 2); v2 = p.x; v3 = p.y; }
        else             { v2 = 0.f; v3 = 0.f; }
    }
    size_t o = (size_t)row * 256 + k;
    __half2* hp = reinterpret_cast<__half2*>(xc + o);
    hp[0] = __floats2half2_rn(v0, v1);
    hp[1] = __floats2half2_rn(v2, v3);
}

__global__ void k_wtstk4(const float* __restrict__ w10, const float* __restrict__ w20,
                         const float* __restrict__ w11, const float* __restrict__ w21,
                         const float* __restrict__ w12, const float* __restrict__ w22,
                         const float* __restrict__ w13, const float* __restrict__ w23,
                         __half* __restrict__ w) {
    int idx = blockIdx.x * blockDim.x + threadIdx.x;
    if (idx >= 128 * 256) return;
    int g = blockIdx.y;
    const float* w1 = (g == 0) ? w10 : (g == 1) ? w11 : (g == 2) ? w12 : w13;
    const float* w2 = (g == 0) ? w20 : (g == 1) ? w21 : (g == 2) ? w22 : w23;
    int n = idx >> 8, k = idx & 255;
    float v = (k < 128) ? w1[k * 128 + n] : w2[(k - 128) * 128 + n];
    w[g * 32768 + idx] = __float2half_rn(v);
}

// ================= merged CSR gather (both graphs, fp16 out) ==============
__device__ __forceinline__ float4 ld_half4(const __half* p) {
    uint2 raw = *reinterpret_cast<const uint2*>(p);
    __half2 h0 = *reinterpret_cast<const __half2*>(&raw.x);
    __half2 h1 = *reinterpret_cast<const __half2*>(&raw.y);
    float2 f0 = __half22float2(h0), f1 = __half22float2(h1);
    return make_float4(f0.x, f0.y, f1.x, f1.y);
}
__device__ __forceinline__ void st_half4(__half* p, float4 v) {
    __half2* hp = reinterpret_cast<__half2*>(p);
    hp[0] = __floats2half2_rn(v.x, v.y);
    hp[1] = __floats2half2_rn(v.z, v.w);
}

__global__ void k_gather2(const __half* __restrict__ src, int ld, int coff1,
                          const int* __restrict__ offs0, const int* __restrict__ offs1,
                          const Edge8* __restrict__ ent0, const Edge8* __restrict__ ent1,
                          const float* __restrict__ dis0, const float* __restrict__ dis1,
                          __half* __restrict__ o0, __half* __restrict__ o1, int n) {
    int g = blockIdx.y;
    const int* offs = g ? offs1 : offs0;
    const Edge8* ent = g ? ent1 : ent0;
    const float* dis = g ? dis1 : dis0;
    __half* oh = g ? o1 : o0;
    int off = g ? coff1 : 0;

    int warp = (blockIdx.x * blockDim.x + threadIdx.x) >> 5;
    int lane = threadIdx.x & 31;
    if (warp >= n) return;
    float d = dis[warp];
    int b = offs[warp], e = offs[warp + 1];
    float4 a1 = make_float4(0.f, 0.f, 0.f, 0.f);
    float4 a2 = make_float4(0.f, 0.f, 0.f, 0.f);
    int i = b;
    for (; i + 4 <= e; i += 4) {
        Edge8 r[4];
#pragma unroll
        for (int j = 0; j < 4; j++) r[j] = ent[i + j];
        float4 v[4];
#pragma unroll
        for (int j = 0; j < 4; j++)
            v[j] = ld_half4(src + (size_t)r[j].row * ld + off + lane * 4);
#pragma unroll
        for (int j = 0; j < 4; j++) {
            float c1 = __low2float(r[j].c) * d, c2 = __high2float(r[j].c);
            a1.x += c1 * v[j].x; a1.y += c1 * v[j].y; a1.z += c1 * v[j].z; a1.w += c1 * v[j].w;
            a2.x += c2 * v[j].x; a2.y += c2 * v[j].y; a2.z += c2 * v[j].z; a2.w += c2 * v[j].w;
        }
    }
    for (; i < e; i++) {
        Edge8 rec = ent[i];
        const float4 v = ld_half4(src + (size_t)rec.row * ld + off + lane * 4);
        float c1 = __low2float(rec.c) * d, c2 = __high2float(rec.c);
        a1.x += c1 * v.x; a1.y += c1 * v.y; a1.z += c1 * v.z; a1.w += c1 * v.w;
        a2.x += c2 * v.x; a2.y += c2 * v.y; a2.z += c2 * v.z; a2.w += c2 * v.w;
    }
    float sc = d * d;
    const float4 v = ld_half4(src + (size_t)warp * ld + off + lane * 4);
    a1.x += sc * v.x; a1.y += sc * v.y; a1.z += sc * v.z; a1.w += sc * v.w;
    a2.x += v.x;      a2.y += v.y;      a2.z += v.z;      a2.w += v.w;
    size_t base = (size_t)warp * 256 + lane * 4;
    st_half4(oh + base,       a1);
    st_half4(oh + base + 128, a2);
}

// ================= HMMA fp16 single-term GEMM =========================
__device__ __forceinline__ uint32_t smem_u32(const void* p) {
    uint32_t a;
    asm("{ .reg .u64 t; cvta.to.shared.u64 t, %1; cvt.u32.u64 %0, t; }" : "=r"(a) : "l"(p));
    return a;
}
__device__ __forceinline__ void cp16(uint32_t dst, const void* src) {
    asm volatile("cp.async.cg.shared.global [%0], [%1], 16;" :: "r"(dst), "l"(src));
}
__device__ __forceinline__ void cp_commit() { asm volatile("cp.async.commit_group;"); }
template <int W> __device__ __forceinline__ void cp_wait() {
    asm volatile("cp.async.wait_group %0;" :: "n"(W));
}
__device__ __forceinline__ void ldm_x4(uint32_t* r, uint32_t addr) {
    asm volatile("ldmatrix.sync.aligned.m8n8.x4.shared.b16 {%0,%1,%2,%3}, [%4];"
                 : "=r"(r[0]), "=r"(r[1]), "=r"(r[2]), "=r"(r[3]) : "r"(addr));
}
__device__ __forceinline__ void mma16816(float* c, const uint32_t* a, uint32_t b0, uint32_t b1) {
    asm volatile(
        "mma.sync.aligned.m16n8k16.row.col.f32.f16.f16.f32 "
        "{%0,%1,%2,%3}, {%4,%5,%6,%7}, {%8,%9}, {%0,%1,%2,%3};"
        : "+f"(c[0]), "+f"(c[1]), "+f"(c[2]), "+f"(c[3])
        : "r"(a[0]), "r"(a[1]), "r"(a[2]), "r"(a[3]), "r"(b0), "r"(b1));
}

struct GArgs {
    const __half* A[2];      // [src], fp16, [M,256]
    const __half* B[2];      // [src], fp16, [*,256] transposed weights
    void* C;
    int M, NC;
};

template <int NSRC, int NT, bool OUTH>
__global__ void __launch_bounds__(256, 2) k_gemm2(GArgs args) {
    constexpr int APL  = 16384;              // 128 rows x 128B per kc chunk
    constexpr int ABUF = NSRC * APL;
    constexpr int BPL  = NT * 128;
    constexpr int BBUF = NSRC * BPL;
    constexpr int BUF  = ABUF + BBUF;
    constexpr int NI   = NT / 16;

    extern __shared__ char sm[];
    const int tid  = threadIdx.x;
    const int lane = tid & 31;
    const int wid  = tid >> 5;
    const int wm   = wid & 3;
    const int wn   = wid >> 2;
    const int m0   = blockIdx.y * 128;
    const int n0   = blockIdx.x * NT;
    const uint32_t sbase = smem_u32(sm);

    const int lr = tid >> 3, lq = tid & 7;

    auto issue_load = [&](int kc, int buf) {
        uint32_t sb = sbase + buf * BUF;
#pragma unroll
        for (int s = 0; s < NSRC; s++) {
            const __half* A = args.A[s];
            uint32_t sa = sb + s * APL;
#pragma unroll
            for (int j = 0; j < 4; j++) {
                int r = lr + j * 32;
                int gr = m0 + r; if (gr > args.M - 1) gr = args.M - 1;
                cp16(sa + r * 128 + ((lq ^ (r & 7)) << 4),
                     A + (size_t)gr * 256 + kc * 64 + lq * 8);
            }
        }
#pragma unroll
        for (int s = 0; s < NSRC; s++) {
            const __half* B = args.B[s];
            uint32_t sbB = sb + ABUF + s * BPL;
#pragma unroll
            for (int j = 0; j < NT / 32; j++) {
                int r = lr + j * 32;
                cp16(sbB + r * 128 + ((lq ^ (r & 7)) << 4),
                     B + (size_t)(n0 + r) * 256 + kc * 64 + lq * 8);
            }
        }
        cp_commit();
    };

    float acc[NSRC][2][NI][4];
#pragma unroll
    for (int s = 0; s < NSRC; s++)
#pragma unroll
        for (int mi = 0; mi < 2; mi++)
#pragma unroll
            for (int ni = 0; ni < NI; ni++)
#pragma unroll
                for (int k = 0; k < 4; k++) acc[s][mi][ni][k] = 0.f;

    auto compute = [&](uint32_t sb) {
#pragma unroll
        for (int ks = 0; ks < 4; ks++) {
#pragma unroll
            for (int s = 0; s < NSRC; s++) {
                uint32_t af[2][4];
#pragma unroll
                for (int mi = 0; mi < 2; mi++) {
                    int row = wm * 32 + mi * 16 + (lane & 15);
                    int c16 = (2 * ks + (lane >> 4)) ^ (row & 7);
                    ldm_x4(af[mi], sb + s * APL + row * 128 + (c16 << 4));
                }
                uint32_t bf[NI][2];
#pragma unroll
                for (int np = 0; np < NT / 32; np++) {
                    int nrow = wn * (NT / 2) + np * 16 + ((lane >> 4) << 3) + (lane & 7);
                    int c16 = (2 * ks + ((lane >> 3) & 1)) ^ (nrow & 7);
                    uint32_t t4[4];
                    ldm_x4(t4, sb + ABUF + s * BPL + nrow * 128 + (c16 << 4));
                    bf[np * 2][0] = t4[0]; bf[np * 2][1] = t4[1];
                    bf[np * 2 + 1][0] = t4[2]; bf[np * 2 + 1][1] = t4[3];
                }
#pragma unroll
                for (int mi = 0; mi < 2; mi++)
#pragma unroll
                    for (int ni = 0; ni < NI; ni++)
                        mma16816(acc[s][mi][ni], af[mi], bf[ni][0], bf[ni][1]);
            }
        }
    };

    issue_load(0, 0);
    for (int kc = 0; kc < 4; kc++) {
        if (kc < 3) { issue_load(kc + 1, (kc + 1) & 1); cp_wait<1>(); }
        else        { cp_wait<0>(); }
        __syncthreads();
        compute(sbase + (kc & 1) * BUF);
        __syncthreads();
    }

#pragma unroll
    for (int mi = 0; mi < 2; mi++) {
#pragma unroll
        for (int half = 0; half < 2; half++) {
            int r = m0 + wm * 32 + mi * 16 + (lane >> 2) + half * 8;
            if (r >= args.M) continue;
            size_t cbase = (size_t)r * args.NC + n0 + wn * (NT / 2) + (lane & 3) * 2;
#pragma unroll
            for (int ni = 0; ni < NI; ni++) {
                float v0, v1;
                if (NSRC == 1) {
                    v0 = acc[0][mi][ni][half * 2];
                    v1 = acc[0][mi][ni][half * 2 + 1];
                } else {
                    v0 = 0.5f * (fmaxf(acc[0][mi][ni][half * 2], 0.f) +
                                 fmaxf(acc[NSRC - 1][mi][ni][half * 2], 0.f));
                    v1 = 0.5f * (fmaxf(acc[0][mi][ni][half * 2 + 1], 0.f) +
                                 fmaxf(acc[NSRC - 1][mi][ni][half * 2 + 1], 0.f));
                }
                if (OUTH) {
                    __half2 hv = __floats2half2_rn(v0, v1);
                    *reinterpret_cast<__half2*>((__half*)args.C + cbase + ni * 8) = hv;
                } else {
                    float* cp = (float*)args.C + cbase + ni * 8;
                    cp[0] = v0; cp[1] = v1;
                }
            }
        }
    }
}

#define SMEM_B1 (2 * (16384 + 128 * 128))              // 65536, double-buffered
#define SMEM_DF (2 * (2 * 16384 + 2 * 64 * 128))       // 98304, double-buffered

// ================= host orchestration =================
extern "C" void kernel_launch(void* const* d_in, const int* in_sizes, int n_in,
                              void* d_out, int out_size) {
    const float* x   = (const float*)d_in[0];
    const float* pe  = (const float*)d_in[1];
    const int*   ei0 = (const int*)d_in[2];
    const float* ea0 = (const float*)d_in[3];
    const int*   ei1 = (const int*)d_in[4];
    const float* ea1 = (const float*)d_in[5];
    const float* nl1 = (const float*)d_in[6];
    const float* nl2 = (const float*)d_in[7];
    const float* lw[8] = { (const float*)d_in[8],  (const float*)d_in[9],
                           (const float*)d_in[10], (const float*)d_in[11],
                           (const float*)d_in[12], (const float*)d_in[13],
                           (const float*)d_in[14], (const float*)d_in[15] };
    float* out = (float*)d_out;

    int N = in_sizes[0] / 128;
    int E = in_sizes[3];

    __half *xc, *xpeh, *a0, *a1, *xmh, *wb, *ws;
    float *dis0, *dis1;
    int *cnt, *off0, *off1, *cur0, *cur1;
    Edge8 *ent0, *ent1;
    cudaGetSymbolAddress((void**)&xc,  g_xcat);
    cudaGetSymbolAddress((void**)&xpeh, g_xpeh);
    cudaGetSymbolAddress((void**)&a0,  g_a0);
    cudaGetSymbolAddress((void**)&a1,  g_a1);
    cudaGetSymbolAddress((void**)&xmh, g_xmh);
    cudaGetSymbolAddress((void**)&wb,  g_wb);
    cudaGetSymbolAddress((void**)&ws,  g_ws);
    cudaGetSymbolAddress((void**)&cnt, g_cnt);
    cudaGetSymbolAddress((void**)&off0, g_off0);
    cudaGetSymbolAddress((void**)&off1, g_off1);
    cudaGetSymbolAddress((void**)&cur0, g_cur0);
    cudaGetSymbolAddress((void**)&cur1, g_cur1);
    cudaGetSymbolAddress((void**)&dis0, g_dis0);
    cudaGetSymbolAddress((void**)&dis1, g_dis1);
    cudaGetSymbolAddress((void**)&ent0, g_ent0);
    cudaGetSymbolAddress((void**)&ent1, g_ent1);
    int* cnt0 = cnt;
    int* cnt1 = cnt + MAXN;

    cudaFuncSetAttribute((const void*)k_gemm2<1, 128, true>,
                         cudaFuncAttributeMaxDynamicSharedMemorySize, SMEM_B1);
    cudaFuncSetAttribute((const void*)k_gemm2<2, 64, true>,
                         cudaFuncAttributeMaxDynamicSharedMemorySize, SMEM_DF);
    cudaFuncSetAttribute((const void*)k_gemm2<2, 64, false>,
                         cudaFuncAttributeMaxDynamicSharedMemorySize, SMEM_DF);

    static cudaStream_t s1 = nullptr;
    static cudaEvent_t ev[2];
    if (s1 == nullptr) {
        cudaStreamCreateWithFlags(&s1, cudaStreamNonBlocking);
        for (int i = 0; i < 2; i++) cudaEventCreateWithFlags(&ev[i], cudaEventDisableTiming);
    }

    int eb = (E + 255) / 256;
    int mtiles = (N + 127) / 128;
    int gw = (N + 7) / 8;
    int nxblk = (N + 3) / 4;

    // ======== fork: preprocessing on s1 ========
    cudaEventRecord(ev[0], 0);
    cudaStreamWaitEvent(s1, ev[0], 0);

    cudaMemsetAsync(cnt, 0, 2 * MAXN * sizeof(int), s1);
    k_count2<<<dim3(eb, 2), 256, 0, s1>>>(ei0 + E, ei1 + E, cnt0, cnt1, E);
    k_scan2<<<2, 1024, 0, s1>>>(cnt0, cnt1, off0, off1, cur0, cur1, dis0, dis1, N);
    k_fill2<<<dim3(eb, 2), 256, 0, s1>>>(ei0, ea0, ei1, ea1, dis0, dis1,
                                         cur0, cur1, ent0, ent1, E);
    cudaEventRecord(ev[1], s1);

    // main: fused feature+wcat prep, stage B GEMM
    k_xcatwt<<<nxblk + 256, 256>>>(x, pe, nl1, nl2, xc, wb, N, nxblk);
    {
        GArgs a = {};
        a.A[0] = xc;
        a.B[0] = wb;
        a.C = xpeh; a.M = N; a.NC = 256;
        k_gemm2<1, 128, true><<<dim3(2, mtiles), 256, SMEM_B1>>>(a);
    }
    k_wtstk4<<<dim3(128, 4), 256>>>(lw[0], lw[1], lw[2], lw[3],
                                    lw[4], lw[5], lw[6], lw[7], ws);
    cudaStreamWaitEvent(0, ev[1], 0);   // join preprocessing

    // ======== stage C: both graphs in one launch ========
    k_gather2<<<dim3(gw, 2), 256>>>(xpeh, 256, 128, off0, off1, ent0, ent1,
                                    dis0, dis1, a0, a1, N);

    // ======== stage D (fused dual-source GEMM, fp16 xm output) ========
    {
        GArgs a = {};
        a.A[0] = a0; a.A[1] = a1;
        a.B[0] = ws + 0 * 32768;
        a.B[1] = ws + 1 * 32768;
        a.C = xmh; a.M = N; a.NC = 128;
        k_gemm2<2, 64, true><<<dim3(2, mtiles), 256, SMEM_DF>>>(a);
    }

    // ======== stage E ========
    k_gather2<<<dim3(gw, 2), 256>>>(xmh, 128, 0, off0, off1, ent0, ent1,
                                    dis0, dis1, a0, a1, N);

    // ======== stage F (fused dual-source GEMM, fp32 out) ========
    {
        GArgs a = {};
        a.A[0] = a0; a.A[1] = a1;
        a.B[0] = ws + 2 * 32768;
        a.B[1] = ws + 3 * 32768;
        a.C = out; a.M = N; a.NC = 128;
        k_gemm2<2, 64, false><<<dim3(2, mtiles), 256, SMEM_DF>>>(a);
    }
}